// round 1
// baseline (speedup 1.0000x reference)
#include <cuda_runtime.h>
#include <math.h>

#define BATCH 2
#define SEQ   2048
#define DM    1024
#define NH    16
#define NKV   4
#define DK    64
#define QKVN  1536          // Q(1024) + K(256) + V(256)
#define ROWS  (BATCH*SEQ)   // 4096
#define GROUPS (NH/NKV)     // 4

// ---------------- scratch (no allocation allowed) ----------------
__device__ float g_qkv[ROWS * QKVN];                 // 25 MB
__device__ float g_q  [BATCH * NH  * SEQ * DK];      // 16.8 MB
__device__ float g_k  [BATCH * NKV * SEQ * DK];      // 4.2 MB
__device__ float g_v  [BATCH * NKV * SEQ * DK];      // 4.2 MB
__device__ float g_attn[ROWS * DM];                  // 16.8 MB

// ---------------- generic NT GEMM: C[M,N] = A[M,K] * B[N,K]^T ----------------
// 64x64 block tile, BK=16, 256 threads, 4x4 microtile with strided mapping
// (rows ty+16i, cols tx+16j) -> conflict-free smem reads with pad-65.
__global__ void gemm_nt(const float* __restrict__ A, const float* __restrict__ B,
                        float* __restrict__ C, int M, int N, int K) {
    __shared__ float As[16 * 65];
    __shared__ float Bs[16 * 65];
    const int tid = threadIdx.x;
    const int tx = tid & 15, ty = tid >> 4;
    const int row0 = blockIdx.y * 64;
    const int col0 = blockIdx.x * 64;

    float acc[4][4] = {};

    for (int k0 = 0; k0 < K; k0 += 16) {
        #pragma unroll
        for (int p = 0; p < 4; p++) {
            int idx = tid + p * 256;
            int r = idx >> 4, c = idx & 15;
            As[c * 65 + r] = A[(size_t)(row0 + r) * K + k0 + c];
            Bs[c * 65 + r] = B[(size_t)(col0 + r) * K + k0 + c];
        }
        __syncthreads();
        #pragma unroll
        for (int kk = 0; kk < 16; kk++) {
            float a[4], b[4];
            #pragma unroll
            for (int i = 0; i < 4; i++) a[i] = As[kk * 65 + ty + 16 * i];
            #pragma unroll
            for (int j = 0; j < 4; j++) b[j] = Bs[kk * 65 + tx + 16 * j];
            #pragma unroll
            for (int i = 0; i < 4; i++)
                #pragma unroll
                for (int j = 0; j < 4; j++)
                    acc[i][j] += a[i] * b[j];
        }
        __syncthreads();
    }
    #pragma unroll
    for (int i = 0; i < 4; i++)
        #pragma unroll
        for (int j = 0; j < 4; j++)
            C[(size_t)(row0 + ty + 16 * i) * N + col0 + tx + 16 * j] = acc[i][j];
}

// ---------------- RMSNorm + RoPE + layout transform ----------------
// grid (ROWS, 6), block (32,4). warp handles one (token, head-slot).
// slots 0..15 = Q heads, 16..19 = K kv-heads, 20..23 = V kv-heads.
__global__ void normrope(const float* __restrict__ qw, const float* __restrict__ kw) {
    const int row  = blockIdx.x;                       // b*SEQ + t
    const int slot = blockIdx.y * 4 + threadIdx.y;     // 0..23
    const int lane = threadIdx.x;                      // 0..31 (pair index)
    const int b = row / SEQ, t = row % SEQ;

    const float* src;
    if (slot < NH)             src = &g_qkv[(size_t)row * QKVN + slot * DK];
    else if (slot < NH + NKV)  src = &g_qkv[(size_t)row * QKVN + DM + (slot - NH) * DK];
    else                       src = &g_qkv[(size_t)row * QKVN + DM + NKV * DK + (slot - NH - NKV) * DK];

    float x1 = src[2 * lane], x2 = src[2 * lane + 1];

    if (slot >= NH + NKV) {   // V: plain copy/transpose
        float* dst = &g_v[(((size_t)b * NKV + (slot - NH - NKV)) * SEQ + t) * DK];
        dst[2 * lane] = x1; dst[2 * lane + 1] = x2;
        return;
    }

    // RMSNorm over DK=64 (32 lanes x 2 elems)
    float ss = x1 * x1 + x2 * x2;
    #pragma unroll
    for (int o = 16; o; o >>= 1) ss += __shfl_xor_sync(0xffffffffu, ss, o);
    const float rnorm = rsqrtf(ss * (1.0f / DK) + 1.1920929e-07f);
    const float* w = (slot < NH) ? qw : kw;
    float y1 = x1 * rnorm * w[2 * lane];
    float y2 = x2 * rnorm * w[2 * lane + 1];

    // RoPE: interleaved pairs, inv_freq = 10000^(-2i/64)
    float inv_freq = __powf(10000.0f, -(float)(2 * lane) / (float)DK);
    float ang = (float)t * inv_freq;
    float s, c;
    sincosf(ang, &s, &c);
    float o1 = y1 * c - y2 * s;
    float o2 = y1 * s + y2 * c;

    float* dst = (slot < NH)
        ? &g_q[(((size_t)b * NH  + slot)        * SEQ + t) * DK]
        : &g_k[(((size_t)b * NKV + (slot - NH)) * SEQ + t) * DK];
    dst[2 * lane] = o1;
    dst[2 * lane + 1] = o2;
}

// ---------------- causal flash attention, fp32 ----------------
// grid (SEQ/64, NH, BATCH), 256 threads, dynamic smem.
__global__ void attn_kernel() {
    extern __shared__ float sm[];
    float* Qs   = sm;                 // 64*65
    float* Ks   = Qs + 64 * 65;
    float* Vs   = Ks + 64 * 65;
    float* Ps   = Vs + 64 * 65;
    float* Mrow = Ps + 64 * 65;       // 64
    float* Lrow = Mrow + 64;          // 64

    const int qb = blockIdx.x;
    const int h  = blockIdx.y;
    const int b  = blockIdx.z;
    const int kvh = h / GROUPS;
    const int tid = threadIdx.x;
    const int tx = tid & 15, ty = tid >> 4;

    const float* Qg = &g_q[(((size_t)b * NH  + h)   * SEQ + qb * 64) * DK];
    const float* Kg = &g_k[(((size_t)b * NKV + kvh) * SEQ) * DK];
    const float* Vg = &g_v[(((size_t)b * NKV + kvh) * SEQ) * DK];

    #pragma unroll
    for (int p = 0; p < 16; p++) {
        int idx = tid + p * 256;
        int r = idx >> 6, c = idx & 63;
        Qs[r * 65 + c] = Qg[r * DK + c];
    }
    if (tid < 64) { Mrow[tid] = -INFINITY; Lrow[tid] = 0.0f; }

    float o[4][4] = {};

    for (int kb = 0; kb <= qb; kb++) {
        __syncthreads();   // protect Ks/Vs rewrite vs previous PV reads; also covers init
        #pragma unroll
        for (int p = 0; p < 16; p++) {
            int idx = tid + p * 256;
            int r = idx >> 6, c = idx & 63;
            Ks[r * 65 + c] = Kg[(size_t)(kb * 64 + r) * DK + c];
            Vs[r * 65 + c] = Vg[(size_t)(kb * 64 + r) * DK + c];
        }
        __syncthreads();

        // S = (Q K^T) * scale
        float s[4][4] = {};
        #pragma unroll
        for (int kk = 0; kk < 64; kk++) {
            float a[4], bb[4];
            #pragma unroll
            for (int i = 0; i < 4; i++) a[i] = Qs[(ty + 16 * i) * 65 + kk];
            #pragma unroll
            for (int j = 0; j < 4; j++) bb[j] = Ks[(tx + 16 * j) * 65 + kk];
            #pragma unroll
            for (int i = 0; i < 4; i++)
                #pragma unroll
                for (int j = 0; j < 4; j++)
                    s[i][j] += a[i] * bb[j];
        }

        const bool diag = (kb == qb);
        #pragma unroll
        for (int i = 0; i < 4; i++) {
            const int qrow = ty + 16 * i;
            float mx = -INFINITY;
            #pragma unroll
            for (int j = 0; j < 4; j++) {
                const int kcol = tx + 16 * j;
                float v = s[i][j] * 0.125f;
                if (diag && kcol > qrow) v = -INFINITY;
                s[i][j] = v;
                mx = fmaxf(mx, v);
            }
            #pragma unroll
            for (int od = 8; od; od >>= 1)
                mx = fmaxf(mx, __shfl_xor_sync(0xffffffffu, mx, od));
            const float mold = Mrow[qrow];
            const float mnew = fmaxf(mold, mx);
            const float f = __expf(mold - mnew);   // exp(-inf)=0 on first tile
            float rs = 0.0f;
            #pragma unroll
            for (int j = 0; j < 4; j++) {
                float p = __expf(s[i][j] - mnew);
                s[i][j] = p;
                rs += p;
            }
            #pragma unroll
            for (int od = 8; od; od >>= 1)
                rs += __shfl_xor_sync(0xffffffffu, rs, od);
            if (tx == 0) { Mrow[qrow] = mnew; Lrow[qrow] = Lrow[qrow] * f + rs; }
            #pragma unroll
            for (int j = 0; j < 4; j++) o[i][j] *= f;
            #pragma unroll
            for (int j = 0; j < 4; j++) Ps[qrow * 65 + tx + 16 * j] = s[i][j];
        }
        __syncthreads();

        // O += P @ V
        #pragma unroll
        for (int kk = 0; kk < 64; kk++) {
            float a[4], bb[4];
            #pragma unroll
            for (int i = 0; i < 4; i++) a[i] = Ps[(ty + 16 * i) * 65 + kk];
            #pragma unroll
            for (int j = 0; j < 4; j++) bb[j] = Vs[kk * 65 + tx + 16 * j];
            #pragma unroll
            for (int i = 0; i < 4; i++)
                #pragma unroll
                for (int j = 0; j < 4; j++)
                    o[i][j] += a[i] * bb[j];
        }
    }
    __syncthreads();

    #pragma unroll
    for (int i = 0; i < 4; i++) {
        const int qrow = ty + 16 * i;
        const float inv_l = 1.0f / Lrow[qrow];
        const int q = qb * 64 + qrow;
        #pragma unroll
        for (int j = 0; j < 4; j++) {
            g_attn[(((size_t)b * SEQ + q) * NH + h) * DK + tx + 16 * j] = o[i][j] * inv_l;
        }
    }
}

// ---------------- launch ----------------
extern "C" void kernel_launch(void* const* d_in, const int* in_sizes, int n_in,
                              void* d_out, int out_size) {
    const float* x    = (const float*)d_in[0];   // [2,2048,1024]
    const float* qkvo = (const float*)d_in[1];   // [2560,1024]
    const float* qw   = (const float*)d_in[2];   // [64]
    const float* kw   = (const float*)d_in[3];   // [64]
    float* out = (float*)d_out;                  // [2,2048,1024]

    void *p_qkv, *p_attn;
    cudaGetSymbolAddress(&p_qkv, g_qkv);
    cudaGetSymbolAddress(&p_attn, g_attn);

    const int ATTN_SMEM = (4 * 64 * 65 + 128) * (int)sizeof(float);  // 67072 B
    cudaFuncSetAttribute(attn_kernel, cudaFuncAttributeMaxDynamicSharedMemorySize, ATTN_SMEM);

    // 1) QKV projection: [4096,1536] = x @ Wqkv^T
    gemm_nt<<<dim3(QKVN / 64, ROWS / 64), 256>>>(x, qkvo, (float*)p_qkv, ROWS, QKVN, DM);

    // 2) RMSNorm + RoPE + layout
    normrope<<<dim3(ROWS, 6), dim3(32, 4)>>>(qw, kw);

    // 3) causal flash attention
    attn_kernel<<<dim3(SEQ / 64, NH, BATCH), 256, ATTN_SMEM>>>();

    // 4) output projection: [4096,1024] = attn @ Wo^T
    gemm_nt<<<dim3(DM / 64, ROWS / 64), 256>>>((const float*)p_attn, qkvo + (size_t)QKVN * DM,
                                               out, ROWS, DM, DM);
}

// round 3
// speedup vs baseline: 1.4658x; 1.4658x over previous
#include <cuda_runtime.h>
#include <cuda_bf16.h>
#include <math.h>
#include <stdint.h>

#define BATCH 2
#define SEQ   2048
#define DM    1024
#define NH    16
#define NKV   4
#define DK    64
#define QKVN  1536
#define ROWS  (BATCH*SEQ)
#define GROUPS (NH/NKV)
#define GK    1024

// ---------------- scratch ----------------
__device__ float g_qkv[ROWS * QKVN];
__device__ float g_q  [BATCH * NH  * SEQ * DK];
__device__ float g_k  [BATCH * NKV * SEQ * DK];
__device__ float g_v  [BATCH * NKV * SEQ * DK];
__device__ float g_attn[ROWS * DM];
// bf16 hi/lo planes (stored as packed pairs in uint32)
__device__ uint32_t g_xhi[ROWS * GK / 2],  g_xlo[ROWS * GK / 2];   // x
__device__ uint32_t g_whi[2560 * GK / 2],  g_wlo[2560 * GK / 2];   // qkvo weights
__device__ uint32_t g_ahi[ROWS * GK / 2],  g_alo[ROWS * GK / 2];   // attn out

// ================= helpers =================
__device__ __forceinline__ uint32_t smem_to_u32(const void* p) {
    uint32_t a;
    asm("{ .reg .u64 t; cvta.to.shared.u64 t, %1; cvt.u32.u64 %0, t; }" : "=r"(a) : "l"(p));
    return a;
}
__device__ __forceinline__ void split2(float2 v, uint32_t& hi, uint32_t& lo) {
    __nv_bfloat16 h0 = __float2bfloat16_rn(v.x);
    __nv_bfloat16 h1 = __float2bfloat16_rn(v.y);
    __nv_bfloat16 l0 = __float2bfloat16_rn(v.x - __bfloat162float(h0));
    __nv_bfloat16 l1 = __float2bfloat16_rn(v.y - __bfloat162float(h1));
    hi = (uint32_t)__bfloat16_as_ushort(h0) | ((uint32_t)__bfloat16_as_ushort(h1) << 16);
    lo = (uint32_t)__bfloat16_as_ushort(l0) | ((uint32_t)__bfloat16_as_ushort(l1) << 16);
}
__device__ __forceinline__ void cp16(uint32_t saddr, const void* gaddr) {
    asm volatile("cp.async.cg.shared.global [%0], [%1], 16;" :: "r"(saddr), "l"(gaddr));
}
#define CP_COMMIT() asm volatile("cp.async.commit_group;")
#define CP_WAIT(N)  asm volatile("cp.async.wait_group %0;" :: "n"(N))

__device__ __forceinline__ void ldsm4(uint32_t* r, uint32_t addr) {
    asm volatile("ldmatrix.sync.aligned.m8n8.x4.shared.b16 {%0,%1,%2,%3}, [%4];"
        : "=r"(r[0]), "=r"(r[1]), "=r"(r[2]), "=r"(r[3]) : "r"(addr));
}
__device__ __forceinline__ void mma16816(float* c, const uint32_t* a, uint32_t b0, uint32_t b1) {
    asm volatile("mma.sync.aligned.m16n8k16.row.col.f32.bf16.bf16.f32 "
        "{%0,%1,%2,%3}, {%4,%5,%6,%7}, {%8,%9}, {%0,%1,%2,%3};"
        : "+f"(c[0]), "+f"(c[1]), "+f"(c[2]), "+f"(c[3])
        : "r"(a[0]), "r"(a[1]), "r"(a[2]), "r"(a[3]), "r"(b0), "r"(b1));
}

// ================= split fp32 -> bf16 hi/lo =================
__global__ void split_bf16(const float* __restrict__ src, uint32_t* __restrict__ hi,
                           uint32_t* __restrict__ lo, int npairs) {
    int i = blockIdx.x * blockDim.x + threadIdx.x;
    if (i < npairs) {
        float2 v = ((const float2*)src)[i];
        uint32_t h, l;
        split2(v, h, l);
        hi[i] = h;
        lo[i] = l;
    }
}

// ================= mma.sync bf16x3 GEMM =================
// C[M,N] = A[M,1024] * B[N,1024]^T with A,B given as hi/lo bf16 planes.
// 128x128 CTA tile, BK=64, 256 threads (8 warps = 4M x 2N), 2-stage cp.async pipeline.
// smem per stage: Ahi/Alo/Bhi/Blo each 128x64 bf16 (16KB) = 64KB; 2 stages = 128KB.
__global__ __launch_bounds__(256, 1) void gemm_bf16x3(
        const __nv_bfloat16* __restrict__ Ahi, const __nv_bfloat16* __restrict__ Alo,
        const __nv_bfloat16* __restrict__ Bhi, const __nv_bfloat16* __restrict__ Blo,
        float* __restrict__ C, int N) {
    extern __shared__ char smc[];
    const uint32_t sb = smem_to_u32(smc);
    const int tid = threadIdx.x;
    const int wid = tid >> 5, lane = tid & 31;
    const int wm = wid & 3, wn = wid >> 2;          // warp tile: 32(M) x 64(N)
    const int row0 = blockIdx.y * 128, col0 = blockIdx.x * 128;

    // stage layout offsets
    auto stA_hi = [&](int s) { return sb + s * 65536u; };
    auto stA_lo = [&](int s) { return sb + s * 65536u + 16384u; };
    auto stB_hi = [&](int s) { return sb + s * 65536u + 32768u; };
    auto stB_lo = [&](int s) { return sb + s * 65536u + 49152u; };

    // issue cp.async loads for k-tile kt into stage s
    auto load_stage = [&](int s, int kt) {
        const int k0 = kt * 64;
        #pragma unroll
        for (int i = 0; i < 4; i++) {
            int idx = tid + i * 256;           // 1024 chunks: 128 rows x 8 x 16B
            int r = idx >> 3, c = idx & 7;
            uint32_t soff = (uint32_t)(r * 128 + ((c ^ (r & 7)) << 4));
            size_t gbyte = ((size_t)(row0 + r) * GK + k0) * 2 + c * 16;
            cp16(stA_hi(s) + soff, (const char*)Ahi + gbyte);
            cp16(stA_lo(s) + soff, (const char*)Alo + gbyte);
        }
        #pragma unroll
        for (int i = 0; i < 4; i++) {
            int idx = tid + i * 256;
            int r = idx >> 3, c = idx & 7;
            uint32_t soff = (uint32_t)(r * 128 + ((c ^ (r & 7)) << 4));
            size_t gbyte = ((size_t)(col0 + r) * GK + k0) * 2 + c * 16;
            cp16(stB_hi(s) + soff, (const char*)Bhi + gbyte);
            cp16(stB_lo(s) + soff, (const char*)Blo + gbyte);
        }
    };

    float acc[2][8][4];
    #pragma unroll
    for (int i = 0; i < 2; i++)
        #pragma unroll
        for (int j = 0; j < 8; j++)
            #pragma unroll
            for (int e = 0; e < 4; e++) acc[i][j][e] = 0.0f;

    load_stage(0, 0);
    CP_COMMIT();

    const int lrow = lane & 15, khalf = lane >> 4;

    for (int kt = 0; kt < 16; kt++) {
        if (kt + 1 < 16) { load_stage((kt + 1) & 1, kt + 1); CP_COMMIT(); }
        if (kt + 1 < 16) CP_WAIT(1); else CP_WAIT(0);
        __syncthreads();

        const int s = kt & 1;
        const uint32_t aHi = stA_hi(s), aLo = stA_lo(s);
        const uint32_t bHi = stB_hi(s), bLo = stB_lo(s);

        #pragma unroll
        for (int ks = 0; ks < 4; ks++) {
            const int c = ks * 2 + khalf;
            uint32_t ah[2][4], al[2][4];
            #pragma unroll
            for (int ma = 0; ma < 2; ma++) {
                int r = wm * 32 + ma * 16 + lrow;
                uint32_t off = (uint32_t)(r * 128 + ((c ^ (r & 7)) << 4));
                ldsm4(ah[ma], aHi + off);
                ldsm4(al[ma], aLo + off);
            }
            uint32_t bh[4][4], bl[4][4];
            #pragma unroll
            for (int nb = 0; nb < 4; nb++) {
                int r = wn * 64 + nb * 16 + lrow;
                uint32_t off = (uint32_t)(r * 128 + ((c ^ (r & 7)) << 4));
                ldsm4(bh[nb], bHi + off);
                ldsm4(bl[nb], bLo + off);
            }
            #pragma unroll
            for (int ma = 0; ma < 2; ma++) {
                #pragma unroll
                for (int nb = 0; nb < 4; nb++) {
                    // n-atom 0 of this 16-col group: regs {r0, r2}; atom 1: {r1, r3}
                    mma16816(acc[ma][nb * 2],     ah[ma], bh[nb][0], bh[nb][2]);
                    mma16816(acc[ma][nb * 2],     ah[ma], bl[nb][0], bl[nb][2]);
                    mma16816(acc[ma][nb * 2],     al[ma], bh[nb][0], bh[nb][2]);
                    mma16816(acc[ma][nb * 2 + 1], ah[ma], bh[nb][1], bh[nb][3]);
                    mma16816(acc[ma][nb * 2 + 1], ah[ma], bl[nb][1], bl[nb][3]);
                    mma16816(acc[ma][nb * 2 + 1], al[ma], bh[nb][1], bh[nb][3]);
                }
            }
        }
        __syncthreads();
    }

    // epilogue
    const int crow = lane >> 2, ccol = (lane & 3) * 2;
    #pragma unroll
    for (int ma = 0; ma < 2; ma++) {
        #pragma unroll
        for (int na = 0; na < 8; na++) {
            int r = row0 + wm * 32 + ma * 16 + crow;
            int cc = col0 + wn * 64 + na * 8 + ccol;
            *(float2*)&C[(size_t)r * N + cc]       = make_float2(acc[ma][na][0], acc[ma][na][1]);
            *(float2*)&C[(size_t)(r + 8) * N + cc] = make_float2(acc[ma][na][2], acc[ma][na][3]);
        }
    }
}

// ================= RMSNorm + RoPE + layout =================
__global__ void normrope(const float* __restrict__ qw, const float* __restrict__ kw) {
    const int row  = blockIdx.x;
    const int slot = blockIdx.y * 4 + threadIdx.y;
    const int lane = threadIdx.x;
    const int b = row / SEQ, t = row % SEQ;

    const float* src;
    if (slot < NH)             src = &g_qkv[(size_t)row * QKVN + slot * DK];
    else if (slot < NH + NKV)  src = &g_qkv[(size_t)row * QKVN + DM + (slot - NH) * DK];
    else                       src = &g_qkv[(size_t)row * QKVN + DM + NKV * DK + (slot - NH - NKV) * DK];

    float x1 = src[2 * lane], x2 = src[2 * lane + 1];

    if (slot >= NH + NKV) {
        float* dst = &g_v[(((size_t)b * NKV + (slot - NH - NKV)) * SEQ + t) * DK];
        dst[2 * lane] = x1; dst[2 * lane + 1] = x2;
        return;
    }

    float ss = x1 * x1 + x2 * x2;
    #pragma unroll
    for (int o = 16; o; o >>= 1) ss += __shfl_xor_sync(0xffffffffu, ss, o);
    const float rnorm = rsqrtf(ss * (1.0f / DK) + 1.1920929e-07f);
    const float* w = (slot < NH) ? qw : kw;
    float y1 = x1 * rnorm * w[2 * lane];
    float y2 = x2 * rnorm * w[2 * lane + 1];

    float inv_freq = __powf(10000.0f, -(float)(2 * lane) / (float)DK);
    float ang = (float)t * inv_freq;
    float s, c;
    sincosf(ang, &s, &c);
    float o1 = y1 * c - y2 * s;
    float o2 = y1 * s + y2 * c;

    float* dst = (slot < NH)
        ? &g_q[(((size_t)b * NH  + slot)        * SEQ + t) * DK]
        : &g_k[(((size_t)b * NKV + (slot - NH)) * SEQ + t) * DK];
    dst[2 * lane] = o1;
    dst[2 * lane + 1] = o2;
}

// ================= causal flash attention (fp32, vectorized LDS) =================
__device__ __forceinline__ int swz4(int c) { return ((c >> 2) & 15) << 2; }

__global__ __launch_bounds__(256) void attn_kernel() {
    extern __shared__ float smf[];
    float* Qt = smf;                    // 64*68, transposed + swizzled
    float* Kt = Qt + 64 * 68;
    float* Vs = Kt + 64 * 68;
    float* Pt = Vs + 64 * 68;
    float* Mrow = Pt + 64 * 68;
    float* Lrow = Mrow + 64;

    const int qb = blockIdx.x;
    const int h  = blockIdx.y;
    const int b  = blockIdx.z;
    const int kvh = h / GROUPS;
    const int tid = threadIdx.x;
    const int tx = tid & 15, ty = tid >> 4;

    const float* Qg = &g_q[(((size_t)b * NH  + h)   * SEQ + qb * 64) * DK];
    const float* Kg = &g_k[(((size_t)b * NKV + kvh) * SEQ) * DK];
    const float* Vg = &g_v[(((size_t)b * NKV + kvh) * SEQ) * DK];

    #pragma unroll
    for (int p = 0; p < 4; p++) {
        int idx = tid + p * 256;
        int r = idx >> 4, c4 = idx & 15;
        float4 q4 = *(const float4*)&Qg[r * DK + c4 * 4];
        const float qv[4] = {q4.x, q4.y, q4.z, q4.w};
        #pragma unroll
        for (int e = 0; e < 4; e++) {
            int c = 4 * c4 + e;
            Qt[c * 68 + (r ^ swz4(c))] = qv[e];
        }
    }
    if (tid < 64) { Mrow[tid] = -INFINITY; Lrow[tid] = 0.0f; }

    float o[4][4] = {};

    for (int kb = 0; kb <= qb; kb++) {
        __syncthreads();
        #pragma unroll
        for (int p = 0; p < 4; p++) {
            int idx = tid + p * 256;
            int r = idx >> 4, c4 = idx & 15;
            float4 k4 = *(const float4*)&Kg[(size_t)(kb * 64 + r) * DK + c4 * 4];
            const float kv[4] = {k4.x, k4.y, k4.z, k4.w};
            #pragma unroll
            for (int e = 0; e < 4; e++) {
                int c = 4 * c4 + e;
                Kt[c * 68 + (r ^ swz4(c))] = kv[e];
            }
            *(float4*)&Vs[r * 68 + c4 * 4] =
                *(const float4*)&Vg[(size_t)(kb * 64 + r) * DK + c4 * 4];
        }
        __syncthreads();

        float s[4][4] = {};
        #pragma unroll
        for (int kk = 0; kk < 64; kk++) {
            const int sw = swz4(kk);
            float4 a = *(const float4*)&Qt[kk * 68 + ((4 * ty) ^ sw)];
            float4 bb = *(const float4*)&Kt[kk * 68 + ((4 * tx) ^ sw)];
            const float av[4] = {a.x, a.y, a.z, a.w};
            const float bv[4] = {bb.x, bb.y, bb.z, bb.w};
            #pragma unroll
            for (int i = 0; i < 4; i++)
                #pragma unroll
                for (int j = 0; j < 4; j++)
                    s[i][j] += av[i] * bv[j];
        }

        const bool diag = (kb == qb);
        #pragma unroll
        for (int i = 0; i < 4; i++) {
            const int qrow = 4 * ty + i;
            float mx = -INFINITY;
            #pragma unroll
            for (int j = 0; j < 4; j++) {
                const int kcol = 4 * tx + j;
                float v = s[i][j] * 0.125f;
                if (diag && kcol > qrow) v = -INFINITY;
                s[i][j] = v;
                mx = fmaxf(mx, v);
            }
            #pragma unroll
            for (int od = 8; od; od >>= 1)
                mx = fmaxf(mx, __shfl_xor_sync(0xffffffffu, mx, od));
            const float mold = Mrow[qrow];
            const float mnew = fmaxf(mold, mx);
            const float f = __expf(mold - mnew);
            float rs = 0.0f;
            #pragma unroll
            for (int j = 0; j < 4; j++) {
                float p = __expf(s[i][j] - mnew);
                s[i][j] = p;
                rs += p;
            }
            #pragma unroll
            for (int od = 8; od; od >>= 1)
                rs += __shfl_xor_sync(0xffffffffu, rs, od);
            if (tx == 0) { Mrow[qrow] = mnew; Lrow[qrow] = Lrow[qrow] * f + rs; }
            #pragma unroll
            for (int j = 0; j < 4; j++) o[i][j] *= f;
        }
        #pragma unroll
        for (int j = 0; j < 4; j++) {
            const int kcol = 4 * tx + j;
            float4 pv = make_float4(s[0][j], s[1][j], s[2][j], s[3][j]);
            *(float4*)&Pt[kcol * 68 + ((4 * ty) ^ swz4(kcol))] = pv;
        }
        __syncthreads();

        #pragma unroll
        for (int kk = 0; kk < 64; kk++) {
            float4 a = *(const float4*)&Pt[kk * 68 + ((4 * ty) ^ swz4(kk))];
            float4 bb = *(const float4*)&Vs[kk * 68 + 4 * tx];
            const float av[4] = {a.x, a.y, a.z, a.w};
            const float bv[4] = {bb.x, bb.y, bb.z, bb.w};
            #pragma unroll
            for (int i = 0; i < 4; i++)
                #pragma unroll
                for (int j = 0; j < 4; j++)
                    o[i][j] += av[i] * bv[j];
        }
    }
    __syncthreads();

    #pragma unroll
    for (int i = 0; i < 4; i++) {
        const int qrow = 4 * ty + i;
        const float inv_l = 1.0f / Lrow[qrow];
        const int q = qb * 64 + qrow;
        float4 ov = make_float4(o[i][0] * inv_l, o[i][1] * inv_l, o[i][2] * inv_l, o[i][3] * inv_l);
        *(float4*)&g_attn[(((size_t)b * SEQ + q) * NH + h) * DK + 4 * tx] = ov;
    }
}

// ================= launch =================
extern "C" void kernel_launch(void* const* d_in, const int* in_sizes, int n_in,
                              void* d_out, int out_size) {
    const float* x    = (const float*)d_in[0];
    const float* qkvo = (const float*)d_in[1];
    const float* qw   = (const float*)d_in[2];
    const float* kw   = (const float*)d_in[3];
    float* out = (float*)d_out;

    void *p_qkv, *p_attn, *p_xhi, *p_xlo, *p_whi, *p_wlo, *p_ahi, *p_alo;
    cudaGetSymbolAddress(&p_qkv, g_qkv);
    cudaGetSymbolAddress(&p_attn, g_attn);
    cudaGetSymbolAddress(&p_xhi, g_xhi); cudaGetSymbolAddress(&p_xlo, g_xlo);
    cudaGetSymbolAddress(&p_whi, g_whi); cudaGetSymbolAddress(&p_wlo, g_wlo);
    cudaGetSymbolAddress(&p_ahi, g_ahi); cudaGetSymbolAddress(&p_alo, g_alo);

    const int GEMM_SMEM = 2 * 65536;                                 // 128 KB
    const int ATTN_SMEM = (4 * 64 * 68 + 128) * (int)sizeof(float);  // 70144 B
    cudaFuncSetAttribute(gemm_bf16x3, cudaFuncAttributeMaxDynamicSharedMemorySize, GEMM_SMEM);
    cudaFuncSetAttribute(attn_kernel, cudaFuncAttributeMaxDynamicSharedMemorySize, ATTN_SMEM);

    // 0) split inputs/weights to bf16 hi/lo planes
    {
        int np = ROWS * GK / 2;
        split_bf16<<<np / 256, 256>>>(x, (uint32_t*)p_xhi, (uint32_t*)p_xlo, np);
        int nw = 2560 * GK / 2;
        split_bf16<<<nw / 256, 256>>>(qkvo, (uint32_t*)p_whi, (uint32_t*)p_wlo, nw);
    }

    // 1) QKV projection: [4096,1536]
    gemm_bf16x3<<<dim3(QKVN / 128, ROWS / 128), 256, GEMM_SMEM>>>(
        (const __nv_bfloat16*)p_xhi, (const __nv_bfloat16*)p_xlo,
        (const __nv_bfloat16*)p_whi, (const __nv_bfloat16*)p_wlo,
        (float*)p_qkv, QKVN);

    // 2) RMSNorm + RoPE + layout
    normrope<<<dim3(ROWS, 6), dim3(32, 4)>>>(qw, kw);

    // 3) causal flash attention
    attn_kernel<<<dim3(SEQ / 64, NH, BATCH), 256, ATTN_SMEM>>>();

    // 4) split attention output, then O projection: [4096,1024]
    {
        int np = ROWS * GK / 2;
        split_bf16<<<np / 256, 256>>>((const float*)p_attn, (uint32_t*)p_ahi, (uint32_t*)p_alo, np);
    }
    gemm_bf16x3<<<dim3(DM / 128, ROWS / 128), 256, GEMM_SMEM>>>(
        (const __nv_bfloat16*)p_ahi, (const __nv_bfloat16*)p_alo,
        (const __nv_bfloat16*)p_whi + (size_t)QKVN * GK,
        (const __nv_bfloat16*)p_wlo + (size_t)QKVN * GK,
        out, DM);
}

// round 4
// speedup vs baseline: 2.4633x; 1.6806x over previous
#include <cuda_runtime.h>
#include <cuda_bf16.h>
#include <math.h>
#include <stdint.h>

#define BATCH 2
#define SEQ   2048
#define DM    1024
#define NH    16
#define NKV   4
#define DK    64
#define QKVN  1536
#define ROWS  (BATCH*SEQ)
#define GROUPS (NH/NKV)
#define GK    1024

// ---------------- scratch ----------------
__device__ float g_qkv[ROWS * QKVN];
// bf16 hi/lo planes (packed bf16x2 in uint32)
__device__ uint32_t g_xhi[ROWS * GK / 2],  g_xlo[ROWS * GK / 2];
__device__ uint32_t g_whi[2560 * GK / 2],  g_wlo[2560 * GK / 2];
__device__ uint32_t g_ahi[ROWS * DM / 2],  g_alo[ROWS * DM / 2];
__device__ uint32_t g_qhi[BATCH * NH  * SEQ * DK / 2], g_qlo[BATCH * NH  * SEQ * DK / 2];
__device__ uint32_t g_khi[BATCH * NKV * SEQ * DK / 2], g_klo[BATCH * NKV * SEQ * DK / 2];
__device__ uint32_t g_vhi[BATCH * NKV * SEQ * DK / 2], g_vlo[BATCH * NKV * SEQ * DK / 2];

// ================= helpers =================
__device__ __forceinline__ uint32_t smem_to_u32(const void* p) {
    uint32_t a;
    asm("{ .reg .u64 t; cvta.to.shared.u64 t, %1; cvt.u32.u64 %0, t; }" : "=r"(a) : "l"(p));
    return a;
}
__device__ __forceinline__ void split2(float2 v, uint32_t& hi, uint32_t& lo) {
    __nv_bfloat16 h0 = __float2bfloat16_rn(v.x);
    __nv_bfloat16 h1 = __float2bfloat16_rn(v.y);
    __nv_bfloat16 l0 = __float2bfloat16_rn(v.x - __bfloat162float(h0));
    __nv_bfloat16 l1 = __float2bfloat16_rn(v.y - __bfloat162float(h1));
    hi = (uint32_t)__bfloat16_as_ushort(h0) | ((uint32_t)__bfloat16_as_ushort(h1) << 16);
    lo = (uint32_t)__bfloat16_as_ushort(l0) | ((uint32_t)__bfloat16_as_ushort(l1) << 16);
}
__device__ __forceinline__ void cp16(uint32_t saddr, const void* gaddr) {
    asm volatile("cp.async.cg.shared.global [%0], [%1], 16;" :: "r"(saddr), "l"(gaddr));
}
#define CP_COMMIT() asm volatile("cp.async.commit_group;")
#define CP_WAIT(N)  asm volatile("cp.async.wait_group %0;" :: "n"(N))

__device__ __forceinline__ void ldsm4(uint32_t* r, uint32_t addr) {
    asm volatile("ldmatrix.sync.aligned.m8n8.x4.shared.b16 {%0,%1,%2,%3}, [%4];"
        : "=r"(r[0]), "=r"(r[1]), "=r"(r[2]), "=r"(r[3]) : "r"(addr));
}
__device__ __forceinline__ void ldsm4t(uint32_t* r, uint32_t addr) {
    asm volatile("ldmatrix.sync.aligned.m8n8.x4.trans.shared.b16 {%0,%1,%2,%3}, [%4];"
        : "=r"(r[0]), "=r"(r[1]), "=r"(r[2]), "=r"(r[3]) : "r"(addr));
}
__device__ __forceinline__ void mma16816(float* c, const uint32_t* a, uint32_t b0, uint32_t b1) {
    asm volatile("mma.sync.aligned.m16n8k16.row.col.f32.bf16.bf16.f32 "
        "{%0,%1,%2,%3}, {%4,%5,%6,%7}, {%8,%9}, {%0,%1,%2,%3};"
        : "+f"(c[0]), "+f"(c[1]), "+f"(c[2]), "+f"(c[3])
        : "r"(a[0]), "r"(a[1]), "r"(a[2]), "r"(a[3]), "r"(b0), "r"(b1));
}

// ================= split fp32 -> bf16 hi/lo =================
__global__ void split_bf16(const float* __restrict__ src, uint32_t* __restrict__ hi,
                           uint32_t* __restrict__ lo, int npairs) {
    int i = blockIdx.x * blockDim.x + threadIdx.x;
    if (i < npairs) {
        float2 v = ((const float2*)src)[i];
        uint32_t h, l;
        split2(v, h, l);
        hi[i] = h;
        lo[i] = l;
    }
}

// ================= mma.sync bf16x3 GEMM (unchanged from R3) =================
__global__ __launch_bounds__(256, 1) void gemm_bf16x3(
        const __nv_bfloat16* __restrict__ Ahi, const __nv_bfloat16* __restrict__ Alo,
        const __nv_bfloat16* __restrict__ Bhi, const __nv_bfloat16* __restrict__ Blo,
        float* __restrict__ C, int N) {
    extern __shared__ char smc[];
    const uint32_t sb = smem_to_u32(smc);
    const int tid = threadIdx.x;
    const int wid = tid >> 5, lane = tid & 31;
    const int wm = wid & 3, wn = wid >> 2;
    const int row0 = blockIdx.y * 128, col0 = blockIdx.x * 128;

    auto stA_hi = [&](int s) { return sb + s * 65536u; };
    auto stA_lo = [&](int s) { return sb + s * 65536u + 16384u; };
    auto stB_hi = [&](int s) { return sb + s * 65536u + 32768u; };
    auto stB_lo = [&](int s) { return sb + s * 65536u + 49152u; };

    auto load_stage = [&](int s, int kt) {
        const int k0 = kt * 64;
        #pragma unroll
        for (int i = 0; i < 4; i++) {
            int idx = tid + i * 256;
            int r = idx >> 3, c = idx & 7;
            uint32_t soff = (uint32_t)(r * 128 + ((c ^ (r & 7)) << 4));
            size_t gbyte = ((size_t)(row0 + r) * GK + k0) * 2 + c * 16;
            cp16(stA_hi(s) + soff, (const char*)Ahi + gbyte);
            cp16(stA_lo(s) + soff, (const char*)Alo + gbyte);
        }
        #pragma unroll
        for (int i = 0; i < 4; i++) {
            int idx = tid + i * 256;
            int r = idx >> 3, c = idx & 7;
            uint32_t soff = (uint32_t)(r * 128 + ((c ^ (r & 7)) << 4));
            size_t gbyte = ((size_t)(col0 + r) * GK + k0) * 2 + c * 16;
            cp16(stB_hi(s) + soff, (const char*)Bhi + gbyte);
            cp16(stB_lo(s) + soff, (const char*)Blo + gbyte);
        }
    };

    float acc[2][8][4];
    #pragma unroll
    for (int i = 0; i < 2; i++)
        #pragma unroll
        for (int j = 0; j < 8; j++)
            #pragma unroll
            for (int e = 0; e < 4; e++) acc[i][j][e] = 0.0f;

    load_stage(0, 0);
    CP_COMMIT();

    const int lrow = lane & 15, khalf = lane >> 4;

    for (int kt = 0; kt < 16; kt++) {
        if (kt + 1 < 16) { load_stage((kt + 1) & 1, kt + 1); CP_COMMIT(); }
        if (kt + 1 < 16) CP_WAIT(1); else CP_WAIT(0);
        __syncthreads();

        const int s = kt & 1;
        const uint32_t aHi = stA_hi(s), aLo = stA_lo(s);
        const uint32_t bHi = stB_hi(s), bLo = stB_lo(s);

        #pragma unroll
        for (int ks = 0; ks < 4; ks++) {
            const int c = ks * 2 + khalf;
            uint32_t ah[2][4], al[2][4];
            #pragma unroll
            for (int ma = 0; ma < 2; ma++) {
                int r = wm * 32 + ma * 16 + lrow;
                uint32_t off = (uint32_t)(r * 128 + ((c ^ (r & 7)) << 4));
                ldsm4(ah[ma], aHi + off);
                ldsm4(al[ma], aLo + off);
            }
            uint32_t bh[4][4], bl[4][4];
            #pragma unroll
            for (int nb = 0; nb < 4; nb++) {
                int r = wn * 64 + nb * 16 + lrow;
                uint32_t off = (uint32_t)(r * 128 + ((c ^ (r & 7)) << 4));
                ldsm4(bh[nb], bHi + off);
                ldsm4(bl[nb], bLo + off);
            }
            #pragma unroll
            for (int ma = 0; ma < 2; ma++) {
                #pragma unroll
                for (int nb = 0; nb < 4; nb++) {
                    mma16816(acc[ma][nb * 2],     ah[ma], bh[nb][0], bh[nb][2]);
                    mma16816(acc[ma][nb * 2],     ah[ma], bl[nb][0], bl[nb][2]);
                    mma16816(acc[ma][nb * 2],     al[ma], bh[nb][0], bh[nb][2]);
                    mma16816(acc[ma][nb * 2 + 1], ah[ma], bh[nb][1], bh[nb][3]);
                    mma16816(acc[ma][nb * 2 + 1], ah[ma], bl[nb][1], bl[nb][3]);
                    mma16816(acc[ma][nb * 2 + 1], al[ma], bh[nb][1], bh[nb][3]);
                }
            }
        }
        __syncthreads();
    }

    const int crow = lane >> 2, ccol = (lane & 3) * 2;
    #pragma unroll
    for (int ma = 0; ma < 2; ma++) {
        #pragma unroll
        for (int na = 0; na < 8; na++) {
            int r = row0 + wm * 32 + ma * 16 + crow;
            int cc = col0 + wn * 64 + na * 8 + ccol;
            *(float2*)&C[(size_t)r * N + cc]       = make_float2(acc[ma][na][0], acc[ma][na][1]);
            *(float2*)&C[(size_t)(r + 8) * N + cc] = make_float2(acc[ma][na][2], acc[ma][na][3]);
        }
    }
}

// ================= RMSNorm + RoPE -> packed bf16 hi/lo planes =================
__global__ void normrope(const float* __restrict__ qw, const float* __restrict__ kw) {
    const int row  = blockIdx.x;
    const int slot = blockIdx.y * 4 + threadIdx.y;
    const int lane = threadIdx.x;
    const int b = row / SEQ, t = row % SEQ;

    const float* src;
    if (slot < NH)             src = &g_qkv[(size_t)row * QKVN + slot * DK];
    else if (slot < NH + NKV)  src = &g_qkv[(size_t)row * QKVN + DM + (slot - NH) * DK];
    else                       src = &g_qkv[(size_t)row * QKVN + DM + NKV * DK + (slot - NH - NKV) * DK];

    float x1 = src[2 * lane], x2 = src[2 * lane + 1];

    if (slot >= NH + NKV) {   // V: split only
        size_t di = (((size_t)b * NKV + (slot - NH - NKV)) * SEQ + t) * 32 + lane;
        uint32_t hi, lo;
        split2(make_float2(x1, x2), hi, lo);
        g_vhi[di] = hi; g_vlo[di] = lo;
        return;
    }

    float ss = x1 * x1 + x2 * x2;
    #pragma unroll
    for (int o = 16; o; o >>= 1) ss += __shfl_xor_sync(0xffffffffu, ss, o);
    const float rnorm = rsqrtf(ss * (1.0f / DK) + 1.1920929e-07f);
    const float* w = (slot < NH) ? qw : kw;
    float y1 = x1 * rnorm * w[2 * lane];
    float y2 = x2 * rnorm * w[2 * lane + 1];

    float inv_freq = __powf(10000.0f, -(float)(2 * lane) / (float)DK);
    float ang = (float)t * inv_freq;
    float s, c;
    sincosf(ang, &s, &c);
    float o1 = y1 * c - y2 * s;
    float o2 = y1 * s + y2 * c;

    uint32_t hi, lo;
    if (slot < NH) {           // Q: fold softmax scale 1/8
        split2(make_float2(o1 * 0.125f, o2 * 0.125f), hi, lo);
        size_t di = (((size_t)b * NH + slot) * SEQ + t) * 32 + lane;
        g_qhi[di] = hi; g_qlo[di] = lo;
    } else {
        split2(make_float2(o1, o2), hi, lo);
        size_t di = (((size_t)b * NKV + (slot - NH)) * SEQ + t) * 32 + lane;
        g_khi[di] = hi; g_klo[di] = lo;
    }
}

// ================= tensor-core causal flash attention =================
// CTA: 128 q-rows x 1 head. 8 warps x 16 rows. K/V tiles of 64 tokens, 2-stage cp.async.
// smem: 2 stages x (Khi|Klo|Vhi|Vlo each 8KB) = 64KB. Q staged once in stage0+1 area.
__global__ __launch_bounds__(256, 1) void attn_mma() {
    extern __shared__ char sma[];
    const uint32_t sb = smem_to_u32(sma);
    const int tid = threadIdx.x;
    const int wid = tid >> 5, lane = tid & 31;
    const int qb = (int)gridDim.x - 1 - (int)blockIdx.x;   // heavy blocks first
    const int h  = blockIdx.y, b = blockIdx.z;
    const int kvh = h / GROUPS;

    auto KHI = [&](int s) { return sb + s * 32768u; };
    auto KLO = [&](int s) { return sb + s * 32768u + 8192u; };
    auto VHI = [&](int s) { return sb + s * 32768u + 16384u; };
    auto VLO = [&](int s) { return sb + s * 32768u + 24576u; };

    const char* qhiB = (const char*)g_qhi + (((size_t)b * NH + h) * SEQ + (size_t)qb * 128) * 128;
    const char* qloB = (const char*)g_qlo + (((size_t)b * NH + h) * SEQ + (size_t)qb * 128) * 128;
    const char* khiB = (const char*)g_khi + ((size_t)b * NKV + kvh) * SEQ * 128;
    const char* kloB = (const char*)g_klo + ((size_t)b * NKV + kvh) * SEQ * 128;
    const char* vhiB = (const char*)g_vhi + ((size_t)b * NKV + kvh) * SEQ * 128;
    const char* vloB = (const char*)g_vlo + ((size_t)b * NKV + kvh) * SEQ * 128;

    // ---- stage Q (128 rows x 128B per plane) into stage0/1 area, load fragments ----
    {
        const uint32_t QH = sb, QL = sb + 16384u;
        #pragma unroll
        for (int i = 0; i < 4; i++) {
            int idx = tid + i * 256;
            int r = idx >> 3, c = idx & 7;
            uint32_t soff = (uint32_t)(r * 128 + ((c ^ (r & 7)) << 4));
            cp16(QH + soff, qhiB + (size_t)r * 128 + c * 16);
            cp16(QL + soff, qloB + (size_t)r * 128 + c * 16);
        }
        CP_COMMIT(); CP_WAIT(0);
        __syncthreads();
    }
    uint32_t qh[4][4], ql[4][4];
    {
        const int lrow = lane & 15, khalf = lane >> 4;
        const int r = wid * 16 + lrow;
        #pragma unroll
        for (int ks = 0; ks < 4; ks++) {
            const int c = ks * 2 + khalf;
            uint32_t off = (uint32_t)(r * 128 + ((c ^ (r & 7)) << 4));
            ldsm4(qh[ks], sb + off);
            ldsm4(ql[ks], sb + 16384u + off);
        }
    }
    __syncthreads();

    auto load_kv = [&](int s, int kb) {
        #pragma unroll
        for (int i = 0; i < 2; i++) {
            int idx = tid + i * 256;
            int r = idx >> 3, c = idx & 7;
            uint32_t soff = (uint32_t)(r * 128 + ((c ^ (r & 7)) << 4));
            size_t gb = ((size_t)kb * 64 + r) * 128 + c * 16;
            cp16(KHI(s) + soff, khiB + gb);
            cp16(KLO(s) + soff, kloB + gb);
            cp16(VHI(s) + soff, vhiB + gb);
            cp16(VLO(s) + soff, vloB + gb);
        }
    };

    const int nkb = 2 * qb + 2;
    float oa[8][4];
    #pragma unroll
    for (int j = 0; j < 8; j++)
        #pragma unroll
        for (int e = 0; e < 4; e++) oa[j][e] = 0.0f;
    float m0 = -1e30f, m1 = -1e30f, l0 = 0.0f, l1 = 0.0f;

    const int gr0 = qb * 128 + wid * 16 + (lane >> 2);
    const int gr1 = gr0 + 8;
    const int lrow = lane & 15, khalf = lane >> 4;
    const int vrow_base = ((lane >> 3) & 1) * 8 + (lane & 7);
    const int vkh = lane >> 4;   // chunk select for trans loads

    load_kv(0, 0);
    CP_COMMIT();

    for (int kb = 0; kb < nkb; kb++) {
        if (kb + 1 < nkb) { load_kv((kb + 1) & 1, kb + 1); CP_COMMIT(); }
        if (kb + 1 < nkb) CP_WAIT(1); else CP_WAIT(0);
        __syncthreads();

        const int s = kb & 1;
        const uint32_t kHi = KHI(s), kLo = KLO(s), vHi = VHI(s), vLo = VLO(s);

        // ---- S = Q K^T (3-way split) ----
        float sc[8][4];
        #pragma unroll
        for (int j = 0; j < 8; j++)
            #pragma unroll
            for (int e = 0; e < 4; e++) sc[j][e] = 0.0f;

        #pragma unroll
        for (int ks = 0; ks < 4; ks++) {
            const int c = ks * 2 + khalf;
            uint32_t kh[4][4], kl[4][4];
            #pragma unroll
            for (int nb = 0; nb < 4; nb++) {
                int r = nb * 16 + lrow;
                uint32_t off = (uint32_t)(r * 128 + ((c ^ (r & 7)) << 4));
                ldsm4(kh[nb], kHi + off);
                ldsm4(kl[nb], kLo + off);
            }
            #pragma unroll
            for (int nb = 0; nb < 4; nb++) {
                mma16816(sc[2 * nb],     qh[ks], kh[nb][0], kh[nb][2]);
                mma16816(sc[2 * nb],     qh[ks], kl[nb][0], kl[nb][2]);
                mma16816(sc[2 * nb],     ql[ks], kh[nb][0], kh[nb][2]);
                mma16816(sc[2 * nb + 1], qh[ks], kh[nb][1], kh[nb][3]);
                mma16816(sc[2 * nb + 1], qh[ks], kl[nb][1], kl[nb][3]);
                mma16816(sc[2 * nb + 1], ql[ks], kh[nb][1], kh[nb][3]);
            }
        }

        // ---- causal mask (only near diagonal) ----
        if (kb * 64 + 63 > qb * 128 + wid * 16) {
            #pragma unroll
            for (int j = 0; j < 8; j++) {
                const int c0 = kb * 64 + 8 * j + (lane & 3) * 2;
                const int c1 = c0 + 1;
                if (c0 > gr0) sc[j][0] = -INFINITY;
                if (c1 > gr0) sc[j][1] = -INFINITY;
                if (c0 > gr1) sc[j][2] = -INFINITY;
                if (c1 > gr1) sc[j][3] = -INFINITY;
            }
        }

        // ---- online softmax (rows owned within quad) ----
        float mx0 = -INFINITY, mx1 = -INFINITY;
        #pragma unroll
        for (int j = 0; j < 8; j++) {
            mx0 = fmaxf(mx0, fmaxf(sc[j][0], sc[j][1]));
            mx1 = fmaxf(mx1, fmaxf(sc[j][2], sc[j][3]));
        }
        mx0 = fmaxf(mx0, __shfl_xor_sync(0xffffffffu, mx0, 1));
        mx0 = fmaxf(mx0, __shfl_xor_sync(0xffffffffu, mx0, 2));
        mx1 = fmaxf(mx1, __shfl_xor_sync(0xffffffffu, mx1, 1));
        mx1 = fmaxf(mx1, __shfl_xor_sync(0xffffffffu, mx1, 2));

        const float mn0 = fmaxf(m0, fmaxf(mx0, -1e30f));
        const float mn1 = fmaxf(m1, fmaxf(mx1, -1e30f));
        const float f0 = __expf(m0 - mn0);
        const float f1 = __expf(m1 - mn1);
        m0 = mn0; m1 = mn1;

        float rs0 = 0.0f, rs1 = 0.0f;
        #pragma unroll
        for (int j = 0; j < 8; j++) {
            sc[j][0] = __expf(sc[j][0] - mn0);
            sc[j][1] = __expf(sc[j][1] - mn0);
            sc[j][2] = __expf(sc[j][2] - mn1);
            sc[j][3] = __expf(sc[j][3] - mn1);
            rs0 += sc[j][0] + sc[j][1];
            rs1 += sc[j][2] + sc[j][3];
        }
        rs0 += __shfl_xor_sync(0xffffffffu, rs0, 1);
        rs0 += __shfl_xor_sync(0xffffffffu, rs0, 2);
        rs1 += __shfl_xor_sync(0xffffffffu, rs1, 1);
        rs1 += __shfl_xor_sync(0xffffffffu, rs1, 2);
        l0 = l0 * f0 + rs0;
        l1 = l1 * f1 + rs1;

        #pragma unroll
        for (int j = 0; j < 8; j++) {
            oa[j][0] *= f0; oa[j][1] *= f0;
            oa[j][2] *= f1; oa[j][3] *= f1;
        }

        // ---- P fragments (accumulator -> A operand), hi/lo split ----
        uint32_t pah[4][4], pal[4][4];
        #pragma unroll
        for (int kk = 0; kk < 4; kk++) {
            split2(make_float2(sc[2 * kk][0],     sc[2 * kk][1]),     pah[kk][0], pal[kk][0]);
            split2(make_float2(sc[2 * kk][2],     sc[2 * kk][3]),     pah[kk][1], pal[kk][1]);
            split2(make_float2(sc[2 * kk + 1][0], sc[2 * kk + 1][1]), pah[kk][2], pal[kk][2]);
            split2(make_float2(sc[2 * kk + 1][2], sc[2 * kk + 1][3]), pah[kk][3], pal[kk][3]);
        }

        // ---- O += P V (3-way split), V via ldmatrix.trans ----
        #pragma unroll
        for (int kk = 0; kk < 4; kk++) {
            const int vr = kk * 16 + vrow_base;
            #pragma unroll
            for (int ng = 0; ng < 4; ng++) {
                const int vc = ng * 2 + vkh;
                uint32_t off = (uint32_t)(vr * 128 + ((vc ^ (vr & 7)) << 4));
                uint32_t vh[4], vl[4];
                ldsm4t(vh, vHi + off);
                ldsm4t(vl, vLo + off);
                mma16816(oa[2 * ng],     pah[kk], vh[0], vh[1]);
                mma16816(oa[2 * ng],     pah[kk], vl[0], vl[1]);
                mma16816(oa[2 * ng],     pal[kk], vh[0], vh[1]);
                mma16816(oa[2 * ng + 1], pah[kk], vh[2], vh[3]);
                mma16816(oa[2 * ng + 1], pah[kk], vl[2], vl[3]);
                mma16816(oa[2 * ng + 1], pal[kk], vh[2], vh[3]);
            }
        }
        __syncthreads();
    }

    // ---- epilogue: normalize, split to hi/lo planes for O-projection ----
    const float inv0 = 1.0f / l0, inv1 = 1.0f / l1;
    const int t0 = qb * 128 + wid * 16 + (lane >> 2);
    const size_t row0 = (size_t)b * SEQ + t0;
    const size_t row1 = row0 + 8;
    #pragma unroll
    for (int j = 0; j < 8; j++) {
        const int cidx = h * 32 + j * 4 + (lane & 3);
        uint32_t hi, lo;
        split2(make_float2(oa[j][0] * inv0, oa[j][1] * inv0), hi, lo);
        g_ahi[row0 * 512 + cidx] = hi;
        g_alo[row0 * 512 + cidx] = lo;
        split2(make_float2(oa[j][2] * inv1, oa[j][3] * inv1), hi, lo);
        g_ahi[row1 * 512 + cidx] = hi;
        g_alo[row1 * 512 + cidx] = lo;
    }
}

// ================= launch =================
extern "C" void kernel_launch(void* const* d_in, const int* in_sizes, int n_in,
                              void* d_out, int out_size) {
    const float* x    = (const float*)d_in[0];
    const float* qkvo = (const float*)d_in[1];
    const float* qw   = (const float*)d_in[2];
    const float* kw   = (const float*)d_in[3];
    float* out = (float*)d_out;

    void *p_qkv, *p_xhi, *p_xlo, *p_whi, *p_wlo, *p_ahi, *p_alo;
    cudaGetSymbolAddress(&p_qkv, g_qkv);
    cudaGetSymbolAddress(&p_xhi, g_xhi); cudaGetSymbolAddress(&p_xlo, g_xlo);
    cudaGetSymbolAddress(&p_whi, g_whi); cudaGetSymbolAddress(&p_wlo, g_wlo);
    cudaGetSymbolAddress(&p_ahi, g_ahi); cudaGetSymbolAddress(&p_alo, g_alo);

    const int GEMM_SMEM = 2 * 65536;   // 128 KB
    const int ATTN_SMEM = 2 * 32768;   // 64 KB
    cudaFuncSetAttribute(gemm_bf16x3, cudaFuncAttributeMaxDynamicSharedMemorySize, GEMM_SMEM);
    cudaFuncSetAttribute(attn_mma, cudaFuncAttributeMaxDynamicSharedMemorySize, ATTN_SMEM);

    // 0) split x and weights to bf16 hi/lo planes
    {
        int np = ROWS * GK / 2;
        split_bf16<<<np / 256, 256>>>(x, (uint32_t*)p_xhi, (uint32_t*)p_xlo, np);
        int nw = 2560 * GK / 2;
        split_bf16<<<nw / 256, 256>>>(qkvo, (uint32_t*)p_whi, (uint32_t*)p_wlo, nw);
    }

    // 1) QKV projection
    gemm_bf16x3<<<dim3(QKVN / 128, ROWS / 128), 256, GEMM_SMEM>>>(
        (const __nv_bfloat16*)p_xhi, (const __nv_bfloat16*)p_xlo,
        (const __nv_bfloat16*)p_whi, (const __nv_bfloat16*)p_wlo,
        (float*)p_qkv, QKVN);

    // 2) RMSNorm + RoPE -> packed bf16 hi/lo Q/K/V planes
    normrope<<<dim3(ROWS, 6), dim3(32, 4)>>>(qw, kw);

    // 3) tensor-core causal flash attention -> g_ahi/g_alo
    attn_mma<<<dim3(SEQ / 128, NH, BATCH), 256, ATTN_SMEM>>>();

    // 4) O projection
    gemm_bf16x3<<<dim3(DM / 128, ROWS / 128), 256, GEMM_SMEM>>>(
        (const __nv_bfloat16*)p_ahi, (const __nv_bfloat16*)p_alo,
        (const __nv_bfloat16*)p_whi + (size_t)QKVN * GK,
        (const __nv_bfloat16*)p_wlo + (size_t)QKVN * GK,
        out, DM);
}

// round 5
// speedup vs baseline: 3.8604x; 1.5671x over previous
#include <cuda_runtime.h>
#include <cuda_bf16.h>
#include <math.h>
#include <stdint.h>

#define BATCH 2
#define SEQ   2048
#define DM    1024
#define NH    16
#define NKV   4
#define DK    64
#define QKVN  1536
#define ROWS  (BATCH*SEQ)
#define GROUPS (NH/NKV)
#define GK    1024

// ---------------- scratch ----------------
__device__ float g_qkv[ROWS * QKVN];
__device__ uint32_t g_xhi[ROWS * GK / 2],  g_xlo[ROWS * GK / 2];
__device__ uint32_t g_whi[2560 * GK / 2],  g_wlo[2560 * GK / 2];
__device__ uint32_t g_ahi[ROWS * DM / 2],  g_alo[ROWS * DM / 2];
__device__ uint32_t g_qhi[BATCH * NH  * SEQ * DK / 2], g_qlo[BATCH * NH  * SEQ * DK / 2];
__device__ uint32_t g_khi[BATCH * NKV * SEQ * DK / 2], g_klo[BATCH * NKV * SEQ * DK / 2];
__device__ uint32_t g_vhi[BATCH * NKV * SEQ * DK / 2], g_vlo[BATCH * NKV * SEQ * DK / 2];

// ================= helpers =================
__device__ __forceinline__ uint32_t smem_to_u32(const void* p) {
    uint32_t a;
    asm("{ .reg .u64 t; cvta.to.shared.u64 t, %1; cvt.u32.u64 %0, t; }" : "=r"(a) : "l"(p));
    return a;
}
__device__ __forceinline__ float ex2(float x) {
    float r; asm("ex2.approx.f32 %0, %1;" : "=f"(r) : "f"(x)); return r;
}
__device__ __forceinline__ void split2(float2 v, uint32_t& hi, uint32_t& lo) {
    __nv_bfloat16 h0 = __float2bfloat16_rn(v.x);
    __nv_bfloat16 h1 = __float2bfloat16_rn(v.y);
    __nv_bfloat16 l0 = __float2bfloat16_rn(v.x - __bfloat162float(h0));
    __nv_bfloat16 l1 = __float2bfloat16_rn(v.y - __bfloat162float(h1));
    hi = (uint32_t)__bfloat16_as_ushort(h0) | ((uint32_t)__bfloat16_as_ushort(h1) << 16);
    lo = (uint32_t)__bfloat16_as_ushort(l0) | ((uint32_t)__bfloat16_as_ushort(l1) << 16);
}
__device__ __forceinline__ void cp16(uint32_t saddr, const void* gaddr) {
    asm volatile("cp.async.cg.shared.global [%0], [%1], 16;" :: "r"(saddr), "l"(gaddr));
}
#define CP_COMMIT() asm volatile("cp.async.commit_group;")
#define CP_WAIT(N)  asm volatile("cp.async.wait_group %0;" :: "n"(N))

__device__ __forceinline__ void ldsm4(uint32_t* r, uint32_t addr) {
    asm volatile("ldmatrix.sync.aligned.m8n8.x4.shared.b16 {%0,%1,%2,%3}, [%4];"
        : "=r"(r[0]), "=r"(r[1]), "=r"(r[2]), "=r"(r[3]) : "r"(addr));
}
__device__ __forceinline__ void ldsm4t(uint32_t* r, uint32_t addr) {
    asm volatile("ldmatrix.sync.aligned.m8n8.x4.trans.shared.b16 {%0,%1,%2,%3}, [%4];"
        : "=r"(r[0]), "=r"(r[1]), "=r"(r[2]), "=r"(r[3]) : "r"(addr));
}
__device__ __forceinline__ void mma16816(float* c, const uint32_t* a, uint32_t b0, uint32_t b1) {
    asm volatile("mma.sync.aligned.m16n8k16.row.col.f32.bf16.bf16.f32 "
        "{%0,%1,%2,%3}, {%4,%5,%6,%7}, {%8,%9}, {%0,%1,%2,%3};"
        : "+f"(c[0]), "+f"(c[1]), "+f"(c[2]), "+f"(c[3])
        : "r"(a[0]), "r"(a[1]), "r"(a[2]), "r"(a[3]), "r"(b0), "r"(b1));
}

// ================= split fp32 -> bf16 hi/lo =================
__global__ void split_bf16(const float* __restrict__ src, uint32_t* __restrict__ hi,
                           uint32_t* __restrict__ lo, int npairs) {
    int i = blockIdx.x * blockDim.x + threadIdx.x;
    if (i < npairs) {
        float2 v = ((const float2*)src)[i];
        uint32_t h, l;
        split2(v, h, l);
        hi[i] = h;
        lo[i] = l;
    }
}

// ================= mma.sync bf16x3 GEMM, 3-stage pipeline =================
__global__ __launch_bounds__(256, 1) void gemm_bf16x3(
        const __nv_bfloat16* __restrict__ Ahi, const __nv_bfloat16* __restrict__ Alo,
        const __nv_bfloat16* __restrict__ Bhi, const __nv_bfloat16* __restrict__ Blo,
        float* __restrict__ C, int N) {
    extern __shared__ char smc[];
    const uint32_t sb = smem_to_u32(smc);
    const int tid = threadIdx.x;
    const int wid = tid >> 5, lane = tid & 31;
    const int wm = wid & 3, wn = wid >> 2;
    const int row0 = blockIdx.y * 128, col0 = blockIdx.x * 128;

    auto stA_hi = [&](int s) { return sb + s * 65536u; };
    auto stA_lo = [&](int s) { return sb + s * 65536u + 16384u; };
    auto stB_hi = [&](int s) { return sb + s * 65536u + 32768u; };
    auto stB_lo = [&](int s) { return sb + s * 65536u + 49152u; };

    auto load_stage = [&](int s, int kt) {
        const int k0 = kt * 64;
        #pragma unroll
        for (int i = 0; i < 4; i++) {
            int idx = tid + i * 256;
            int r = idx >> 3, c = idx & 7;
            uint32_t soff = (uint32_t)(r * 128 + ((c ^ (r & 7)) << 4));
            size_t gbyte = ((size_t)(row0 + r) * GK + k0) * 2 + c * 16;
            cp16(stA_hi(s) + soff, (const char*)Ahi + gbyte);
            cp16(stA_lo(s) + soff, (const char*)Alo + gbyte);
        }
        #pragma unroll
        for (int i = 0; i < 4; i++) {
            int idx = tid + i * 256;
            int r = idx >> 3, c = idx & 7;
            uint32_t soff = (uint32_t)(r * 128 + ((c ^ (r & 7)) << 4));
            size_t gbyte = ((size_t)(col0 + r) * GK + k0) * 2 + c * 16;
            cp16(stB_hi(s) + soff, (const char*)Bhi + gbyte);
            cp16(stB_lo(s) + soff, (const char*)Blo + gbyte);
        }
    };

    float acc[2][8][4];
    #pragma unroll
    for (int i = 0; i < 2; i++)
        #pragma unroll
        for (int j = 0; j < 8; j++)
            #pragma unroll
            for (int e = 0; e < 4; e++) acc[i][j][e] = 0.0f;

    load_stage(0, 0); CP_COMMIT();
    load_stage(1, 1); CP_COMMIT();

    const int lrow = lane & 15, khalf = lane >> 4;

    for (int kt = 0; kt < 16; kt++) {
        if (kt + 2 < 16) { load_stage((kt + 2) % 3, kt + 2); CP_COMMIT(); }
        if (kt < 14) CP_WAIT(2);
        else if (kt == 14) CP_WAIT(1);
        else CP_WAIT(0);
        __syncthreads();

        const int s = kt % 3;
        const uint32_t aHi = stA_hi(s), aLo = stA_lo(s);
        const uint32_t bHi = stB_hi(s), bLo = stB_lo(s);

        #pragma unroll
        for (int ks = 0; ks < 4; ks++) {
            const int c = ks * 2 + khalf;
            uint32_t ah[2][4], al[2][4];
            #pragma unroll
            for (int ma = 0; ma < 2; ma++) {
                int r = wm * 32 + ma * 16 + lrow;
                uint32_t off = (uint32_t)(r * 128 + ((c ^ (r & 7)) << 4));
                ldsm4(ah[ma], aHi + off);
                ldsm4(al[ma], aLo + off);
            }
            uint32_t bh[4][4], bl[4][4];
            #pragma unroll
            for (int nb = 0; nb < 4; nb++) {
                int r = wn * 64 + nb * 16 + lrow;
                uint32_t off = (uint32_t)(r * 128 + ((c ^ (r & 7)) << 4));
                ldsm4(bh[nb], bHi + off);
                ldsm4(bl[nb], bLo + off);
            }
            #pragma unroll
            for (int ma = 0; ma < 2; ma++) {
                #pragma unroll
                for (int nb = 0; nb < 4; nb++) {
                    mma16816(acc[ma][nb * 2],     ah[ma], bh[nb][0], bh[nb][2]);
                    mma16816(acc[ma][nb * 2],     ah[ma], bl[nb][0], bl[nb][2]);
                    mma16816(acc[ma][nb * 2],     al[ma], bh[nb][0], bh[nb][2]);
                    mma16816(acc[ma][nb * 2 + 1], ah[ma], bh[nb][1], bh[nb][3]);
                    mma16816(acc[ma][nb * 2 + 1], ah[ma], bl[nb][1], bl[nb][3]);
                    mma16816(acc[ma][nb * 2 + 1], al[ma], bh[nb][1], bh[nb][3]);
                }
            }
        }
        __syncthreads();
    }

    const int crow = lane >> 2, ccol = (lane & 3) * 2;
    #pragma unroll
    for (int ma = 0; ma < 2; ma++) {
        #pragma unroll
        for (int na = 0; na < 8; na++) {
            int r = row0 + wm * 32 + ma * 16 + crow;
            int cc = col0 + wn * 64 + na * 8 + ccol;
            *(float2*)&C[(size_t)r * N + cc]       = make_float2(acc[ma][na][0], acc[ma][na][1]);
            *(float2*)&C[(size_t)(r + 8) * N + cc] = make_float2(acc[ma][na][2], acc[ma][na][3]);
        }
    }
}

// ================= RMSNorm + RoPE -> packed bf16 hi/lo planes =================
__global__ void normrope(const float* __restrict__ qw, const float* __restrict__ kw) {
    const int row  = blockIdx.x;
    const int slot = blockIdx.y * 4 + threadIdx.y;
    const int lane = threadIdx.x;
    const int b = row / SEQ, t = row % SEQ;

    const float* src;
    if (slot < NH)             src = &g_qkv[(size_t)row * QKVN + slot * DK];
    else if (slot < NH + NKV)  src = &g_qkv[(size_t)row * QKVN + DM + (slot - NH) * DK];
    else                       src = &g_qkv[(size_t)row * QKVN + DM + NKV * DK + (slot - NH - NKV) * DK];

    float x1 = src[2 * lane], x2 = src[2 * lane + 1];

    if (slot >= NH + NKV) {   // V: split only
        size_t di = (((size_t)b * NKV + (slot - NH - NKV)) * SEQ + t) * 32 + lane;
        uint32_t hi, lo;
        split2(make_float2(x1, x2), hi, lo);
        g_vhi[di] = hi; g_vlo[di] = lo;
        return;
    }

    float ss = x1 * x1 + x2 * x2;
    #pragma unroll
    for (int o = 16; o; o >>= 1) ss += __shfl_xor_sync(0xffffffffu, ss, o);
    const float rnorm = rsqrtf(ss * (1.0f / DK) + 1.1920929e-07f);
    const float* w = (slot < NH) ? qw : kw;
    float y1 = x1 * rnorm * w[2 * lane];
    float y2 = x2 * rnorm * w[2 * lane + 1];

    float inv_freq = __powf(10000.0f, -(float)(2 * lane) / (float)DK);
    float ang = (float)t * inv_freq;
    float s, c;
    sincosf(ang, &s, &c);
    float o1 = y1 * c - y2 * s;
    float o2 = y1 * s + y2 * c;

    uint32_t hi, lo;
    if (slot < NH) {           // Q: fold softmax scale 1/8 and log2(e) (for ex2-domain softmax)
        const float qs = 0.125f * 1.4426950408889634f;
        split2(make_float2(o1 * qs, o2 * qs), hi, lo);
        size_t di = (((size_t)b * NH + slot) * SEQ + t) * 32 + lane;
        g_qhi[di] = hi; g_qlo[di] = lo;
    } else {
        split2(make_float2(o1, o2), hi, lo);
        size_t di = (((size_t)b * NKV + (slot - NH)) * SEQ + t) * 32 + lane;
        g_khi[di] = hi; g_klo[di] = lo;
    }
}

// ================= tensor-core causal flash attention =================
// CTA: 128 q-rows x 1 head. 8 warps x 16 rows. KV tiles of 128 tokens, 2-stage cp.async.
// smem: 2 stages x (Khi|Klo|Vhi|Vlo each 16KB) = 128KB. Q staged once in stage0 area.
__global__ __launch_bounds__(256, 1) void attn_mma() {
    extern __shared__ char sma[];
    const uint32_t sb = smem_to_u32(sma);
    const int tid = threadIdx.x;
    const int wid = tid >> 5, lane = tid & 31;
    const int qb = (int)gridDim.x - 1 - (int)blockIdx.x;   // heavy blocks first
    const int h  = blockIdx.y, b = blockIdx.z;
    const int kvh = h / GROUPS;

    auto KHI = [&](int s) { return sb + s * 65536u; };
    auto KLO = [&](int s) { return sb + s * 65536u + 16384u; };
    auto VHI = [&](int s) { return sb + s * 65536u + 32768u; };
    auto VLO = [&](int s) { return sb + s * 65536u + 49152u; };

    const char* qhiB = (const char*)g_qhi + (((size_t)b * NH + h) * SEQ + (size_t)qb * 128) * 128;
    const char* qloB = (const char*)g_qlo + (((size_t)b * NH + h) * SEQ + (size_t)qb * 128) * 128;
    const char* khiB = (const char*)g_khi + ((size_t)b * NKV + kvh) * SEQ * 128;
    const char* kloB = (const char*)g_klo + ((size_t)b * NKV + kvh) * SEQ * 128;
    const char* vhiB = (const char*)g_vhi + ((size_t)b * NKV + kvh) * SEQ * 128;
    const char* vloB = (const char*)g_vlo + ((size_t)b * NKV + kvh) * SEQ * 128;

    // ---- stage Q (128 rows x 128B per plane), load fragments ----
    {
        const uint32_t QH = sb, QL = sb + 16384u;
        #pragma unroll
        for (int i = 0; i < 4; i++) {
            int idx = tid + i * 256;
            int r = idx >> 3, c = idx & 7;
            uint32_t soff = (uint32_t)(r * 128 + ((c ^ (r & 7)) << 4));
            cp16(QH + soff, qhiB + (size_t)r * 128 + c * 16);
            cp16(QL + soff, qloB + (size_t)r * 128 + c * 16);
        }
        CP_COMMIT(); CP_WAIT(0);
        __syncthreads();
    }
    uint32_t qh[4][4], ql[4][4];
    {
        const int lrow = lane & 15, khalf = lane >> 4;
        const int r = wid * 16 + lrow;
        #pragma unroll
        for (int ks = 0; ks < 4; ks++) {
            const int c = ks * 2 + khalf;
            uint32_t off = (uint32_t)(r * 128 + ((c ^ (r & 7)) << 4));
            ldsm4(qh[ks], sb + off);
            ldsm4(ql[ks], sb + 16384u + off);
        }
    }
    __syncthreads();

    auto load_kv = [&](int s, int kb) {
        #pragma unroll
        for (int i = 0; i < 4; i++) {
            int idx = tid + i * 256;
            int r = idx >> 3, c = idx & 7;
            uint32_t soff = (uint32_t)(r * 128 + ((c ^ (r & 7)) << 4));
            size_t gb = ((size_t)kb * 128 + r) * 128 + c * 16;
            cp16(KHI(s) + soff, khiB + gb);
            cp16(KLO(s) + soff, kloB + gb);
            cp16(VHI(s) + soff, vhiB + gb);
            cp16(VLO(s) + soff, vloB + gb);
        }
    };

    const int nkb = qb + 1;     // 128-token KV tiles
    float oa[8][4];
    #pragma unroll
    for (int j = 0; j < 8; j++)
        #pragma unroll
        for (int e = 0; e < 4; e++) oa[j][e] = 0.0f;
    float m0 = -1e30f, m1 = -1e30f, l0 = 0.0f, l1 = 0.0f;

    const int gr0 = qb * 128 + wid * 16 + (lane >> 2);
    const int gr1 = gr0 + 8;
    const int lrow = lane & 15, khalf = lane >> 4;
    const int vrow_base = ((lane >> 3) & 1) * 8 + (lane & 7);
    const int vkh = lane >> 4;

    load_kv(0, 0);
    CP_COMMIT();

    for (int kb = 0; kb < nkb; kb++) {
        if (kb + 1 < nkb) { load_kv((kb + 1) & 1, kb + 1); CP_COMMIT(); }
        if (kb + 1 < nkb) CP_WAIT(1); else CP_WAIT(0);
        __syncthreads();

        const int s = kb & 1;
        const uint32_t kHi = KHI(s), kLo = KLO(s), vHi = VHI(s), vLo = VLO(s);

        // ---- S = Q K^T over 128 key columns (3-way split) ----
        float sc[16][4];
        #pragma unroll
        for (int j = 0; j < 16; j++)
            #pragma unroll
            for (int e = 0; e < 4; e++) sc[j][e] = 0.0f;

        #pragma unroll
        for (int ks = 0; ks < 4; ks++) {
            const int c = ks * 2 + khalf;
            #pragma unroll
            for (int nb = 0; nb < 8; nb++) {
                int r = nb * 16 + lrow;
                uint32_t off = (uint32_t)(r * 128 + ((c ^ (r & 7)) << 4));
                uint32_t kh[4], kl[4];
                ldsm4(kh, kHi + off);
                ldsm4(kl, kLo + off);
                mma16816(sc[2 * nb],     qh[ks], kh[0], kh[2]);
                mma16816(sc[2 * nb],     qh[ks], kl[0], kl[2]);
                mma16816(sc[2 * nb],     ql[ks], kh[0], kh[2]);
                mma16816(sc[2 * nb + 1], qh[ks], kh[1], kh[3]);
                mma16816(sc[2 * nb + 1], qh[ks], kl[1], kl[3]);
                mma16816(sc[2 * nb + 1], ql[ks], kh[1], kh[3]);
            }
        }

        // ---- causal mask (diagonal tile only) ----
        if (kb == qb) {
            #pragma unroll
            for (int j = 0; j < 16; j++) {
                const int c0 = kb * 128 + 8 * j + (lane & 3) * 2;
                const int c1 = c0 + 1;
                if (c0 > gr0) sc[j][0] = -INFINITY;
                if (c1 > gr0) sc[j][1] = -INFINITY;
                if (c0 > gr1) sc[j][2] = -INFINITY;
                if (c1 > gr1) sc[j][3] = -INFINITY;
            }
        }

        // ---- online softmax (log2 domain; rows owned within quad) ----
        float mx0 = -INFINITY, mx1 = -INFINITY;
        #pragma unroll
        for (int j = 0; j < 16; j++) {
            mx0 = fmaxf(mx0, fmaxf(sc[j][0], sc[j][1]));
            mx1 = fmaxf(mx1, fmaxf(sc[j][2], sc[j][3]));
        }
        mx0 = fmaxf(mx0, __shfl_xor_sync(0xffffffffu, mx0, 1));
        mx0 = fmaxf(mx0, __shfl_xor_sync(0xffffffffu, mx0, 2));
        mx1 = fmaxf(mx1, __shfl_xor_sync(0xffffffffu, mx1, 1));
        mx1 = fmaxf(mx1, __shfl_xor_sync(0xffffffffu, mx1, 2));

        const float mn0 = fmaxf(m0, fmaxf(mx0, -1e30f));
        const float mn1 = fmaxf(m1, fmaxf(mx1, -1e30f));
        const float f0 = ex2(m0 - mn0);
        const float f1 = ex2(m1 - mn1);
        m0 = mn0; m1 = mn1;

        float rs0 = 0.0f, rs1 = 0.0f;
        #pragma unroll
        for (int j = 0; j < 16; j++) {
            sc[j][0] = ex2(sc[j][0] - mn0);
            sc[j][1] = ex2(sc[j][1] - mn0);
            sc[j][2] = ex2(sc[j][2] - mn1);
            sc[j][3] = ex2(sc[j][3] - mn1);
            rs0 += sc[j][0] + sc[j][1];
            rs1 += sc[j][2] + sc[j][3];
        }
        rs0 += __shfl_xor_sync(0xffffffffu, rs0, 1);
        rs0 += __shfl_xor_sync(0xffffffffu, rs0, 2);
        rs1 += __shfl_xor_sync(0xffffffffu, rs1, 1);
        rs1 += __shfl_xor_sync(0xffffffffu, rs1, 2);
        l0 = l0 * f0 + rs0;
        l1 = l1 * f1 + rs1;

        #pragma unroll
        for (int j = 0; j < 8; j++) {
            oa[j][0] *= f0; oa[j][1] *= f0;
            oa[j][2] *= f1; oa[j][3] *= f1;
        }

        // ---- P fragments (accumulator -> A operand), hi/lo split ----
        uint32_t pah[8][4], pal[8][4];
        #pragma unroll
        for (int kk = 0; kk < 8; kk++) {
            split2(make_float2(sc[2 * kk][0],     sc[2 * kk][1]),     pah[kk][0], pal[kk][0]);
            split2(make_float2(sc[2 * kk][2],     sc[2 * kk][3]),     pah[kk][1], pal[kk][1]);
            split2(make_float2(sc[2 * kk + 1][0], sc[2 * kk + 1][1]), pah[kk][2], pal[kk][2]);
            split2(make_float2(sc[2 * kk + 1][2], sc[2 * kk + 1][3]), pah[kk][3], pal[kk][3]);
        }

        // ---- O += P V (3-way split), V via ldmatrix.trans ----
        #pragma unroll
        for (int kk = 0; kk < 8; kk++) {
            const int vr = kk * 16 + vrow_base;
            #pragma unroll
            for (int ng = 0; ng < 4; ng++) {
                const int vc = ng * 2 + vkh;
                uint32_t off = (uint32_t)(vr * 128 + ((vc ^ (vr & 7)) << 4));
                uint32_t vh[4], vl[4];
                ldsm4t(vh, vHi + off);
                ldsm4t(vl, vLo + off);
                mma16816(oa[2 * ng],     pah[kk], vh[0], vh[1]);
                mma16816(oa[2 * ng],     pah[kk], vl[0], vl[1]);
                mma16816(oa[2 * ng],     pal[kk], vh[0], vh[1]);
                mma16816(oa[2 * ng + 1], pah[kk], vh[2], vh[3]);
                mma16816(oa[2 * ng + 1], pah[kk], vl[2], vl[3]);
                mma16816(oa[2 * ng + 1], pal[kk], vh[2], vh[3]);
            }
        }
        __syncthreads();
    }

    // ---- epilogue: normalize, split to hi/lo planes for O-projection ----
    const float inv0 = 1.0f / l0, inv1 = 1.0f / l1;
    const int t0 = qb * 128 + wid * 16 + (lane >> 2);
    const size_t row0 = (size_t)b * SEQ + t0;
    const size_t row1 = row0 + 8;
    #pragma unroll
    for (int j = 0; j < 8; j++) {
        const int cidx = h * 32 + j * 4 + (lane & 3);
        uint32_t hi, lo;
        split2(make_float2(oa[j][0] * inv0, oa[j][1] * inv0), hi, lo);
        g_ahi[row0 * 512 + cidx] = hi;
        g_alo[row0 * 512 + cidx] = lo;
        split2(make_float2(oa[j][2] * inv1, oa[j][3] * inv1), hi, lo);
        g_ahi[row1 * 512 + cidx] = hi;
        g_alo[row1 * 512 + cidx] = lo;
    }
}

// ================= launch =================
extern "C" void kernel_launch(void* const* d_in, const int* in_sizes, int n_in,
                              void* d_out, int out_size) {
    const float* x    = (const float*)d_in[0];
    const float* qkvo = (const float*)d_in[1];
    const float* qw   = (const float*)d_in[2];
    const float* kw   = (const float*)d_in[3];
    float* out = (float*)d_out;

    void *p_qkv, *p_xhi, *p_xlo, *p_whi, *p_wlo, *p_ahi, *p_alo;
    cudaGetSymbolAddress(&p_qkv, g_qkv);
    cudaGetSymbolAddress(&p_xhi, g_xhi); cudaGetSymbolAddress(&p_xlo, g_xlo);
    cudaGetSymbolAddress(&p_whi, g_whi); cudaGetSymbolAddress(&p_wlo, g_wlo);
    cudaGetSymbolAddress(&p_ahi, g_ahi); cudaGetSymbolAddress(&p_alo, g_alo);

    const int GEMM_SMEM = 3 * 65536;   // 192 KB
    const int ATTN_SMEM = 2 * 65536;   // 128 KB
    cudaFuncSetAttribute(gemm_bf16x3, cudaFuncAttributeMaxDynamicSharedMemorySize, GEMM_SMEM);
    cudaFuncSetAttribute(attn_mma, cudaFuncAttributeMaxDynamicSharedMemorySize, ATTN_SMEM);

    // 0) split x and weights to bf16 hi/lo planes
    {
        int np = ROWS * GK / 2;
        split_bf16<<<np / 256, 256>>>(x, (uint32_t*)p_xhi, (uint32_t*)p_xlo, np);
        int nw = 2560 * GK / 2;
        split_bf16<<<nw / 256, 256>>>(qkvo, (uint32_t*)p_whi, (uint32_t*)p_wlo, nw);
    }

    // 1) QKV projection
    gemm_bf16x3<<<dim3(QKVN / 128, ROWS / 128), 256, GEMM_SMEM>>>(
        (const __nv_bfloat16*)p_xhi, (const __nv_bfloat16*)p_xlo,
        (const __nv_bfloat16*)p_whi, (const __nv_bfloat16*)p_wlo,
        (float*)p_qkv, QKVN);

    // 2) RMSNorm + RoPE -> packed bf16 hi/lo Q/K/V planes
    normrope<<<dim3(ROWS, 6), dim3(32, 4)>>>(qw, kw);

    // 3) tensor-core causal flash attention -> g_ahi/g_alo
    attn_mma<<<dim3(SEQ / 128, NH, BATCH), 256, ATTN_SMEM>>>();

    // 4) O projection
    gemm_bf16x3<<<dim3(DM / 128, ROWS / 128), 256, GEMM_SMEM>>>(
        (const __nv_bfloat16*)p_ahi, (const __nv_bfloat16*)p_alo,
        (const __nv_bfloat16*)p_whi + (size_t)QKVN * GK,
        (const __nv_bfloat16*)p_wlo + (size_t)QKVN * GK,
        out, DM);
}

// round 6
// speedup vs baseline: 3.8616x; 1.0003x over previous
#include <cuda_runtime.h>
#include <cuda_bf16.h>
#include <math.h>
#include <stdint.h>

#define BATCH 2
#define SEQ   2048
#define DM    1024
#define NH    16
#define NKV   4
#define DK    64
#define QKVN  1536
#define ROWS  (BATCH*SEQ)
#define GROUPS (NH/NKV)
#define GK    1024

// ---------------- scratch ----------------
__device__ float g_qkv[ROWS * QKVN];
__device__ uint32_t g_xhi[ROWS * GK / 2],  g_xlo[ROWS * GK / 2];
__device__ uint32_t g_whi[2560 * GK / 2],  g_wlo[2560 * GK / 2];
__device__ uint32_t g_ahi[ROWS * DM / 2],  g_alo[ROWS * DM / 2];
__device__ uint32_t g_qhi[BATCH * NH  * SEQ * DK / 2], g_qlo[BATCH * NH  * SEQ * DK / 2];
__device__ uint32_t g_khi[BATCH * NKV * SEQ * DK / 2], g_klo[BATCH * NKV * SEQ * DK / 2];
__device__ uint32_t g_vhi[BATCH * NKV * SEQ * DK / 2], g_vlo[BATCH * NKV * SEQ * DK / 2];

// ================= helpers =================
__device__ __forceinline__ uint32_t smem_to_u32(const void* p) {
    uint32_t a;
    asm("{ .reg .u64 t; cvta.to.shared.u64 t, %1; cvt.u32.u64 %0, t; }" : "=r"(a) : "l"(p));
    return a;
}
__device__ __forceinline__ float ex2(float x) {
    float r; asm("ex2.approx.f32 %0, %1;" : "=f"(r) : "f"(x)); return r;
}
__device__ __forceinline__ void split2(float2 v, uint32_t& hi, uint32_t& lo) {
    __nv_bfloat16 h0 = __float2bfloat16_rn(v.x);
    __nv_bfloat16 h1 = __float2bfloat16_rn(v.y);
    __nv_bfloat16 l0 = __float2bfloat16_rn(v.x - __bfloat162float(h0));
    __nv_bfloat16 l1 = __float2bfloat16_rn(v.y - __bfloat162float(h1));
    hi = (uint32_t)__bfloat16_as_ushort(h0) | ((uint32_t)__bfloat16_as_ushort(h1) << 16);
    lo = (uint32_t)__bfloat16_as_ushort(l0) | ((uint32_t)__bfloat16_as_ushort(l1) << 16);
}
__device__ __forceinline__ void cp16(uint32_t saddr, const void* gaddr) {
    asm volatile("cp.async.cg.shared.global [%0], [%1], 16;" :: "r"(saddr), "l"(gaddr));
}
#define CP_COMMIT() asm volatile("cp.async.commit_group;")
#define CP_WAIT(N)  asm volatile("cp.async.wait_group %0;" :: "n"(N))

__device__ __forceinline__ void ldsm4(uint32_t* r, uint32_t addr) {
    asm volatile("ldmatrix.sync.aligned.m8n8.x4.shared.b16 {%0,%1,%2,%3}, [%4];"
        : "=r"(r[0]), "=r"(r[1]), "=r"(r[2]), "=r"(r[3]) : "r"(addr));
}
__device__ __forceinline__ void ldsm4t(uint32_t* r, uint32_t addr) {
    asm volatile("ldmatrix.sync.aligned.m8n8.x4.trans.shared.b16 {%0,%1,%2,%3}, [%4];"
        : "=r"(r[0]), "=r"(r[1]), "=r"(r[2]), "=r"(r[3]) : "r"(addr));
}
__device__ __forceinline__ void mma16816(float* c, const uint32_t* a, uint32_t b0, uint32_t b1) {
    asm volatile("mma.sync.aligned.m16n8k16.row.col.f32.bf16.bf16.f32 "
        "{%0,%1,%2,%3}, {%4,%5,%6,%7}, {%8,%9}, {%0,%1,%2,%3};"
        : "+f"(c[0]), "+f"(c[1]), "+f"(c[2]), "+f"(c[3])
        : "r"(a[0]), "r"(a[1]), "r"(a[2]), "r"(a[3]), "r"(b0), "r"(b1));
}

// ================= split fp32 -> bf16 hi/lo =================
__global__ void split_bf16(const float* __restrict__ src, uint32_t* __restrict__ hi,
                           uint32_t* __restrict__ lo, int npairs) {
    int i = blockIdx.x * blockDim.x + threadIdx.x;
    if (i < npairs) {
        float2 v = ((const float2*)src)[i];
        uint32_t h, l;
        split2(v, h, l);
        hi[i] = h;
        lo[i] = l;
    }
}

// ================= mma.sync bf16x3 GEMM, 3-stage pipeline, single sync/iter =================
__global__ __launch_bounds__(256, 1) void gemm_bf16x3(
        const __nv_bfloat16* __restrict__ Ahi, const __nv_bfloat16* __restrict__ Alo,
        const __nv_bfloat16* __restrict__ Bhi, const __nv_bfloat16* __restrict__ Blo,
        float* __restrict__ C, int N) {
    extern __shared__ char smc[];
    const uint32_t sb = smem_to_u32(smc);
    const int tid = threadIdx.x;
    const int wid = tid >> 5, lane = tid & 31;
    const int wm = wid & 3, wn = wid >> 2;
    const int row0 = blockIdx.y * 128, col0 = blockIdx.x * 128;

    auto stA_hi = [&](int s) { return sb + s * 65536u; };
    auto stA_lo = [&](int s) { return sb + s * 65536u + 16384u; };
    auto stB_hi = [&](int s) { return sb + s * 65536u + 32768u; };
    auto stB_lo = [&](int s) { return sb + s * 65536u + 49152u; };

    auto load_stage = [&](int s, int kt) {
        const int k0 = kt * 64;
        #pragma unroll
        for (int i = 0; i < 4; i++) {
            int idx = tid + i * 256;
            int r = idx >> 3, c = idx & 7;
            uint32_t soff = (uint32_t)(r * 128 + ((c ^ (r & 7)) << 4));
            size_t gbyte = ((size_t)(row0 + r) * GK + k0) * 2 + c * 16;
            cp16(stA_hi(s) + soff, (const char*)Ahi + gbyte);
            cp16(stA_lo(s) + soff, (const char*)Alo + gbyte);
        }
        #pragma unroll
        for (int i = 0; i < 4; i++) {
            int idx = tid + i * 256;
            int r = idx >> 3, c = idx & 7;
            uint32_t soff = (uint32_t)(r * 128 + ((c ^ (r & 7)) << 4));
            size_t gbyte = ((size_t)(col0 + r) * GK + k0) * 2 + c * 16;
            cp16(stB_hi(s) + soff, (const char*)Bhi + gbyte);
            cp16(stB_lo(s) + soff, (const char*)Blo + gbyte);
        }
    };

    float acc[2][8][4];
    #pragma unroll
    for (int i = 0; i < 2; i++)
        #pragma unroll
        for (int j = 0; j < 8; j++)
            #pragma unroll
            for (int e = 0; e < 4; e++) acc[i][j][e] = 0.0f;

    load_stage(0, 0); CP_COMMIT();
    load_stage(1, 1); CP_COMMIT();

    const int lrow = lane & 15, khalf = lane >> 4;

    for (int kt = 0; kt < 16; kt++) {
        if (kt < 15) CP_WAIT(1); else CP_WAIT(0);
        __syncthreads();
        if (kt + 2 < 16) { load_stage((kt + 2) % 3, kt + 2); CP_COMMIT(); }

        const int s = kt % 3;
        const uint32_t aHi = stA_hi(s), aLo = stA_lo(s);
        const uint32_t bHi = stB_hi(s), bLo = stB_lo(s);

        #pragma unroll
        for (int ks = 0; ks < 4; ks++) {
            const int c = ks * 2 + khalf;
            uint32_t ah[2][4], al[2][4];
            #pragma unroll
            for (int ma = 0; ma < 2; ma++) {
                int r = wm * 32 + ma * 16 + lrow;
                uint32_t off = (uint32_t)(r * 128 + ((c ^ (r & 7)) << 4));
                ldsm4(ah[ma], aHi + off);
                ldsm4(al[ma], aLo + off);
            }
            uint32_t bh[4][4], bl[4][4];
            #pragma unroll
            for (int nb = 0; nb < 4; nb++) {
                int r = wn * 64 + nb * 16 + lrow;
                uint32_t off = (uint32_t)(r * 128 + ((c ^ (r & 7)) << 4));
                ldsm4(bh[nb], bHi + off);
                ldsm4(bl[nb], bLo + off);
            }
            #pragma unroll
            for (int ma = 0; ma < 2; ma++) {
                #pragma unroll
                for (int nb = 0; nb < 4; nb++) {
                    mma16816(acc[ma][nb * 2],     ah[ma], bh[nb][0], bh[nb][2]);
                    mma16816(acc[ma][nb * 2],     ah[ma], bl[nb][0], bl[nb][2]);
                    mma16816(acc[ma][nb * 2],     al[ma], bh[nb][0], bh[nb][2]);
                    mma16816(acc[ma][nb * 2 + 1], ah[ma], bh[nb][1], bh[nb][3]);
                    mma16816(acc[ma][nb * 2 + 1], ah[ma], bl[nb][1], bl[nb][3]);
                    mma16816(acc[ma][nb * 2 + 1], al[ma], bh[nb][1], bh[nb][3]);
                }
            }
        }
    }

    const int crow = lane >> 2, ccol = (lane & 3) * 2;
    #pragma unroll
    for (int ma = 0; ma < 2; ma++) {
        #pragma unroll
        for (int na = 0; na < 8; na++) {
            int r = row0 + wm * 32 + ma * 16 + crow;
            int cc = col0 + wn * 64 + na * 8 + ccol;
            *(float2*)&C[(size_t)r * N + cc]       = make_float2(acc[ma][na][0], acc[ma][na][1]);
            *(float2*)&C[(size_t)(r + 8) * N + cc] = make_float2(acc[ma][na][2], acc[ma][na][3]);
        }
    }
}

// ================= RMSNorm + RoPE -> packed bf16 hi/lo planes =================
__global__ void normrope(const float* __restrict__ qw, const float* __restrict__ kw) {
    const int row  = blockIdx.x;
    const int slot = blockIdx.y * 4 + threadIdx.y;
    const int lane = threadIdx.x;
    const int b = row / SEQ, t = row % SEQ;

    const float* src;
    if (slot < NH)             src = &g_qkv[(size_t)row * QKVN + slot * DK];
    else if (slot < NH + NKV)  src = &g_qkv[(size_t)row * QKVN + DM + (slot - NH) * DK];
    else                       src = &g_qkv[(size_t)row * QKVN + DM + NKV * DK + (slot - NH - NKV) * DK];

    float x1 = src[2 * lane], x2 = src[2 * lane + 1];

    if (slot >= NH + NKV) {   // V: split only
        size_t di = (((size_t)b * NKV + (slot - NH - NKV)) * SEQ + t) * 32 + lane;
        uint32_t hi, lo;
        split2(make_float2(x1, x2), hi, lo);
        g_vhi[di] = hi; g_vlo[di] = lo;
        return;
    }

    float ss = x1 * x1 + x2 * x2;
    #pragma unroll
    for (int o = 16; o; o >>= 1) ss += __shfl_xor_sync(0xffffffffu, ss, o);
    const float rnorm = rsqrtf(ss * (1.0f / DK) + 1.1920929e-07f);
    const float* w = (slot < NH) ? qw : kw;
    float y1 = x1 * rnorm * w[2 * lane];
    float y2 = x2 * rnorm * w[2 * lane + 1];

    float inv_freq = __powf(10000.0f, -(float)(2 * lane) / (float)DK);
    float ang = (float)t * inv_freq;
    float s, c;
    sincosf(ang, &s, &c);
    float o1 = y1 * c - y2 * s;
    float o2 = y1 * s + y2 * c;

    uint32_t hi, lo;
    if (slot < NH) {           // Q: fold softmax scale 1/8 and log2(e)
        const float qs = 0.125f * 1.4426950408889634f;
        split2(make_float2(o1 * qs, o2 * qs), hi, lo);
        size_t di = (((size_t)b * NH + slot) * SEQ + t) * 32 + lane;
        g_qhi[di] = hi; g_qlo[di] = lo;
    } else {
        split2(make_float2(o1, o2), hi, lo);
        size_t di = (((size_t)b * NKV + (slot - NH)) * SEQ + t) * 32 + lane;
        g_khi[di] = hi; g_klo[di] = lo;
    }
}

// ================= tensor-core causal flash attention =================
// Fixed-base softmax: |log2-scores| <= 11.6 (RMSNorm bounds), so no running max
// is needed; exp2 sums/outputs stay well inside fp32 range. l reduced once at end.
__global__ __launch_bounds__(256, 1) void attn_mma() {
    extern __shared__ char sma[];
    const uint32_t sb = smem_to_u32(sma);
    const int tid = threadIdx.x;
    const int wid = tid >> 5, lane = tid & 31;
    const int qb = (int)gridDim.x - 1 - (int)blockIdx.x;   // heavy blocks first
    const int h  = blockIdx.y, b = blockIdx.z;
    const int kvh = h / GROUPS;

    auto KHI = [&](int s) { return sb + s * 65536u; };
    auto KLO = [&](int s) { return sb + s * 65536u + 16384u; };
    auto VHI = [&](int s) { return sb + s * 65536u + 32768u; };
    auto VLO = [&](int s) { return sb + s * 65536u + 49152u; };

    const char* qhiB = (const char*)g_qhi + (((size_t)b * NH + h) * SEQ + (size_t)qb * 128) * 128;
    const char* qloB = (const char*)g_qlo + (((size_t)b * NH + h) * SEQ + (size_t)qb * 128) * 128;
    const char* khiB = (const char*)g_khi + ((size_t)b * NKV + kvh) * SEQ * 128;
    const char* kloB = (const char*)g_klo + ((size_t)b * NKV + kvh) * SEQ * 128;
    const char* vhiB = (const char*)g_vhi + ((size_t)b * NKV + kvh) * SEQ * 128;
    const char* vloB = (const char*)g_vlo + ((size_t)b * NKV + kvh) * SEQ * 128;

    // ---- stage Q (128 rows x 128B per plane), load fragments ----
    {
        const uint32_t QH = sb, QL = sb + 16384u;
        #pragma unroll
        for (int i = 0; i < 4; i++) {
            int idx = tid + i * 256;
            int r = idx >> 3, c = idx & 7;
            uint32_t soff = (uint32_t)(r * 128 + ((c ^ (r & 7)) << 4));
            cp16(QH + soff, qhiB + (size_t)r * 128 + c * 16);
            cp16(QL + soff, qloB + (size_t)r * 128 + c * 16);
        }
        CP_COMMIT(); CP_WAIT(0);
        __syncthreads();
    }
    uint32_t qh[4][4], ql[4][4];
    {
        const int lrow = lane & 15, khalf = lane >> 4;
        const int r = wid * 16 + lrow;
        #pragma unroll
        for (int ks = 0; ks < 4; ks++) {
            const int c = ks * 2 + khalf;
            uint32_t off = (uint32_t)(r * 128 + ((c ^ (r & 7)) << 4));
            ldsm4(qh[ks], sb + off);
            ldsm4(ql[ks], sb + 16384u + off);
        }
    }
    __syncthreads();

    auto load_kv = [&](int s, int kb) {
        #pragma unroll
        for (int i = 0; i < 4; i++) {
            int idx = tid + i * 256;
            int r = idx >> 3, c = idx & 7;
            uint32_t soff = (uint32_t)(r * 128 + ((c ^ (r & 7)) << 4));
            size_t gb = ((size_t)kb * 128 + r) * 128 + c * 16;
            cp16(KHI(s) + soff, khiB + gb);
            cp16(KLO(s) + soff, kloB + gb);
            cp16(VHI(s) + soff, vhiB + gb);
            cp16(VLO(s) + soff, vloB + gb);
        }
    };

    const int nkb = qb + 1;
    float oa[8][4];
    #pragma unroll
    for (int j = 0; j < 8; j++)
        #pragma unroll
        for (int e = 0; e < 4; e++) oa[j][e] = 0.0f;
    float l0 = 0.0f, l1 = 0.0f;   // per-thread partial row sums

    const int gr0 = qb * 128 + wid * 16 + (lane >> 2);
    const int gr1 = gr0 + 8;
    const int lrow = lane & 15, khalf = lane >> 4;
    const int vrow_base = ((lane >> 3) & 1) * 8 + (lane & 7);
    const int vkh = lane >> 4;

    load_kv(0, 0);
    CP_COMMIT();

    for (int kb = 0; kb < nkb; kb++) {
        CP_WAIT(0);
        __syncthreads();
        if (kb + 1 < nkb) { load_kv((kb + 1) & 1, kb + 1); CP_COMMIT(); }

        const int s = kb & 1;
        const uint32_t kHi = KHI(s), kLo = KLO(s), vHi = VHI(s), vLo = VLO(s);

        // ---- S = Q K^T over 128 key columns (3-way split) ----
        float sc[16][4];
        #pragma unroll
        for (int j = 0; j < 16; j++)
            #pragma unroll
            for (int e = 0; e < 4; e++) sc[j][e] = 0.0f;

        #pragma unroll
        for (int ks = 0; ks < 4; ks++) {
            const int c = ks * 2 + khalf;
            #pragma unroll
            for (int nb = 0; nb < 8; nb++) {
                int r = nb * 16 + lrow;
                uint32_t off = (uint32_t)(r * 128 + ((c ^ (r & 7)) << 4));
                uint32_t kh[4], kl[4];
                ldsm4(kh, kHi + off);
                ldsm4(kl, kLo + off);
                mma16816(sc[2 * nb],     qh[ks], kh[0], kh[2]);
                mma16816(sc[2 * nb],     qh[ks], kl[0], kl[2]);
                mma16816(sc[2 * nb],     ql[ks], kh[0], kh[2]);
                mma16816(sc[2 * nb + 1], qh[ks], kh[1], kh[3]);
                mma16816(sc[2 * nb + 1], qh[ks], kl[1], kl[3]);
                mma16816(sc[2 * nb + 1], ql[ks], kh[1], kh[3]);
            }
        }

        // ---- causal mask (diagonal tile only) ----
        if (kb == qb) {
            #pragma unroll
            for (int j = 0; j < 16; j++) {
                const int c0 = kb * 128 + 8 * j + (lane & 3) * 2;
                const int c1 = c0 + 1;
                if (c0 > gr0) sc[j][0] = -INFINITY;
                if (c1 > gr0) sc[j][1] = -INFINITY;
                if (c0 > gr1) sc[j][2] = -INFINITY;
                if (c1 > gr1) sc[j][3] = -INFINITY;
            }
        }

        // ---- fixed-base softmax: P = exp2(S), accumulate partial sums ----
        #pragma unroll
        for (int j = 0; j < 16; j++) {
            sc[j][0] = ex2(sc[j][0]);
            sc[j][1] = ex2(sc[j][1]);
            sc[j][2] = ex2(sc[j][2]);
            sc[j][3] = ex2(sc[j][3]);
            l0 += sc[j][0] + sc[j][1];
            l1 += sc[j][2] + sc[j][3];
        }

        // ---- P fragments (accumulator -> A operand), hi/lo split ----
        uint32_t pah[8][4], pal[8][4];
        #pragma unroll
        for (int kk = 0; kk < 8; kk++) {
            split2(make_float2(sc[2 * kk][0],     sc[2 * kk][1]),     pah[kk][0], pal[kk][0]);
            split2(make_float2(sc[2 * kk][2],     sc[2 * kk][3]),     pah[kk][1], pal[kk][1]);
            split2(make_float2(sc[2 * kk + 1][0], sc[2 * kk + 1][1]), pah[kk][2], pal[kk][2]);
            split2(make_float2(sc[2 * kk + 1][2], sc[2 * kk + 1][3]), pah[kk][3], pal[kk][3]);
        }

        // ---- O += P V (3-way split), V via ldmatrix.trans ----
        #pragma unroll
        for (int kk = 0; kk < 8; kk++) {
            const int vr = kk * 16 + vrow_base;
            #pragma unroll
            for (int ng = 0; ng < 4; ng++) {
                const int vc = ng * 2 + vkh;
                uint32_t off = (uint32_t)(vr * 128 + ((vc ^ (vr & 7)) << 4));
                uint32_t vh[4], vl[4];
                ldsm4t(vh, vHi + off);
                ldsm4t(vl, vLo + off);
                mma16816(oa[2 * ng],     pah[kk], vh[0], vh[1]);
                mma16816(oa[2 * ng],     pah[kk], vl[0], vl[1]);
                mma16816(oa[2 * ng],     pal[kk], vh[0], vh[1]);
                mma16816(oa[2 * ng + 1], pah[kk], vh[2], vh[3]);
                mma16816(oa[2 * ng + 1], pah[kk], vl[2], vl[3]);
                mma16816(oa[2 * ng + 1], pal[kk], vh[2], vh[3]);
            }
        }
    }

    // ---- reduce l within quad (rows owned by 4 lanes), normalize, store planes ----
    l0 += __shfl_xor_sync(0xffffffffu, l0, 1);
    l0 += __shfl_xor_sync(0xffffffffu, l0, 2);
    l1 += __shfl_xor_sync(0xffffffffu, l1, 1);
    l1 += __shfl_xor_sync(0xffffffffu, l1, 2);
    const float inv0 = 1.0f / l0, inv1 = 1.0f / l1;
    const int t0 = qb * 128 + wid * 16 + (lane >> 2);
    const size_t row0 = (size_t)b * SEQ + t0;
    const size_t row1 = row0 + 8;
    #pragma unroll
    for (int j = 0; j < 8; j++) {
        const int cidx = h * 32 + j * 4 + (lane & 3);
        uint32_t hi, lo;
        split2(make_float2(oa[j][0] * inv0, oa[j][1] * inv0), hi, lo);
        g_ahi[row0 * 512 + cidx] = hi;
        g_alo[row0 * 512 + cidx] = lo;
        split2(make_float2(oa[j][2] * inv1, oa[j][3] * inv1), hi, lo);
        g_ahi[row1 * 512 + cidx] = hi;
        g_alo[row1 * 512 + cidx] = lo;
    }
}

// ================= launch =================
extern "C" void kernel_launch(void* const* d_in, const int* in_sizes, int n_in,
                              void* d_out, int out_size) {
    const float* x    = (const float*)d_in[0];
    const float* qkvo = (const float*)d_in[1];
    const float* qw   = (const float*)d_in[2];
    const float* kw   = (const float*)d_in[3];
    float* out = (float*)d_out;

    void *p_qkv, *p_xhi, *p_xlo, *p_whi, *p_wlo, *p_ahi, *p_alo;
    cudaGetSymbolAddress(&p_qkv, g_qkv);
    cudaGetSymbolAddress(&p_xhi, g_xhi); cudaGetSymbolAddress(&p_xlo, g_xlo);
    cudaGetSymbolAddress(&p_whi, g_whi); cudaGetSymbolAddress(&p_wlo, g_wlo);
    cudaGetSymbolAddress(&p_ahi, g_ahi); cudaGetSymbolAddress(&p_alo, g_alo);

    const int GEMM_SMEM = 3 * 65536;   // 192 KB
    const int ATTN_SMEM = 2 * 65536;   // 128 KB
    cudaFuncSetAttribute(gemm_bf16x3, cudaFuncAttributeMaxDynamicSharedMemorySize, GEMM_SMEM);
    cudaFuncSetAttribute(attn_mma, cudaFuncAttributeMaxDynamicSharedMemorySize, ATTN_SMEM);

    // 0) split x and weights to bf16 hi/lo planes
    {
        int np = ROWS * GK / 2;
        split_bf16<<<np / 256, 256>>>(x, (uint32_t*)p_xhi, (uint32_t*)p_xlo, np);
        int nw = 2560 * GK / 2;
        split_bf16<<<nw / 256, 256>>>(qkvo, (uint32_t*)p_whi, (uint32_t*)p_wlo, nw);
    }

    // 1) QKV projection
    gemm_bf16x3<<<dim3(QKVN / 128, ROWS / 128), 256, GEMM_SMEM>>>(
        (const __nv_bfloat16*)p_xhi, (const __nv_bfloat16*)p_xlo,
        (const __nv_bfloat16*)p_whi, (const __nv_bfloat16*)p_wlo,
        (float*)p_qkv, QKVN);

    // 2) RMSNorm + RoPE -> packed bf16 hi/lo Q/K/V planes
    normrope<<<dim3(ROWS, 6), dim3(32, 4)>>>(qw, kw);

    // 3) tensor-core causal flash attention -> g_ahi/g_alo
    attn_mma<<<dim3(SEQ / 128, NH, BATCH), 256, ATTN_SMEM>>>();

    // 4) O projection
    gemm_bf16x3<<<dim3(DM / 128, ROWS / 128), 256, GEMM_SMEM>>>(
        (const __nv_bfloat16*)p_ahi, (const __nv_bfloat16*)p_alo,
        (const __nv_bfloat16*)p_whi + (size_t)QKVN * GK,
        (const __nv_bfloat16*)p_wlo + (size_t)QKVN * GK,
        out, DM);
}

// round 7
// speedup vs baseline: 4.4171x; 1.1438x over previous
#include <cuda_runtime.h>
#include <cuda_bf16.h>
#include <cuda_fp16.h>
#include <math.h>
#include <stdint.h>

#define BATCH 2
#define SEQ   2048
#define DM    1024
#define NH    16
#define NKV   4
#define DK    64
#define QKVN  1536
#define ROWS  (BATCH*SEQ)
#define GROUPS (NH/NKV)
#define GK    1024

// ---------------- scratch ----------------
__device__ float g_qkv[ROWS * QKVN];
__device__ uint32_t g_xhi[ROWS * GK / 2],  g_xlo[ROWS * GK / 2];
__device__ uint32_t g_whi[2560 * GK / 2],  g_wlo[2560 * GK / 2];
__device__ uint32_t g_ahi[ROWS * DM / 2],  g_alo[ROWS * DM / 2];
__device__ uint32_t g_qhi[BATCH * NH  * SEQ * DK / 2], g_qlo[BATCH * NH  * SEQ * DK / 2];
__device__ uint32_t g_khi[BATCH * NKV * SEQ * DK / 2], g_klo[BATCH * NKV * SEQ * DK / 2];
__device__ uint32_t g_vh [BATCH * NKV * SEQ * DK / 2];              // fp16 single plane

// ================= helpers =================
__device__ __forceinline__ uint32_t smem_to_u32(const void* p) {
    uint32_t a;
    asm("{ .reg .u64 t; cvta.to.shared.u64 t, %1; cvt.u32.u64 %0, t; }" : "=r"(a) : "l"(p));
    return a;
}
__device__ __forceinline__ float ex2(float x) {
    float r; asm("ex2.approx.f32 %0, %1;" : "=f"(r) : "f"(x)); return r;
}
__device__ __forceinline__ void split2(float2 v, uint32_t& hi, uint32_t& lo) {
    __nv_bfloat16 h0 = __float2bfloat16_rn(v.x);
    __nv_bfloat16 h1 = __float2bfloat16_rn(v.y);
    __nv_bfloat16 l0 = __float2bfloat16_rn(v.x - __bfloat162float(h0));
    __nv_bfloat16 l1 = __float2bfloat16_rn(v.y - __bfloat162float(h1));
    hi = (uint32_t)__bfloat16_as_ushort(h0) | ((uint32_t)__bfloat16_as_ushort(h1) << 16);
    lo = (uint32_t)__bfloat16_as_ushort(l0) | ((uint32_t)__bfloat16_as_ushort(l1) << 16);
}
// pack two floats into f16x2: first arg -> low half
__device__ __forceinline__ uint32_t pack_h2(float lo, float hi) {
    uint32_t r;
    asm("cvt.rn.f16x2.f32 %0, %1, %2;" : "=r"(r) : "f"(hi), "f"(lo));
    return r;
}
__device__ __forceinline__ void cp16(uint32_t saddr, const void* gaddr) {
    asm volatile("cp.async.cg.shared.global [%0], [%1], 16;" :: "r"(saddr), "l"(gaddr));
}
#define CP_COMMIT() asm volatile("cp.async.commit_group;")
#define CP_WAIT(N)  asm volatile("cp.async.wait_group %0;" :: "n"(N))

__device__ __forceinline__ void ldsm4(uint32_t* r, uint32_t addr) {
    asm volatile("ldmatrix.sync.aligned.m8n8.x4.shared.b16 {%0,%1,%2,%3}, [%4];"
        : "=r"(r[0]), "=r"(r[1]), "=r"(r[2]), "=r"(r[3]) : "r"(addr));
}
__device__ __forceinline__ void ldsm4t(uint32_t* r, uint32_t addr) {
    asm volatile("ldmatrix.sync.aligned.m8n8.x4.trans.shared.b16 {%0,%1,%2,%3}, [%4];"
        : "=r"(r[0]), "=r"(r[1]), "=r"(r[2]), "=r"(r[3]) : "r"(addr));
}
__device__ __forceinline__ void mma16816(float* c, const uint32_t* a, uint32_t b0, uint32_t b1) {
    asm volatile("mma.sync.aligned.m16n8k16.row.col.f32.bf16.bf16.f32 "
        "{%0,%1,%2,%3}, {%4,%5,%6,%7}, {%8,%9}, {%0,%1,%2,%3};"
        : "+f"(c[0]), "+f"(c[1]), "+f"(c[2]), "+f"(c[3])
        : "r"(a[0]), "r"(a[1]), "r"(a[2]), "r"(a[3]), "r"(b0), "r"(b1));
}
__device__ __forceinline__ void mma16816h(float* c, const uint32_t* a, uint32_t b0, uint32_t b1) {
    asm volatile("mma.sync.aligned.m16n8k16.row.col.f32.f16.f16.f32 "
        "{%0,%1,%2,%3}, {%4,%5,%6,%7}, {%8,%9}, {%0,%1,%2,%3};"
        : "+f"(c[0]), "+f"(c[1]), "+f"(c[2]), "+f"(c[3])
        : "r"(a[0]), "r"(a[1]), "r"(a[2]), "r"(a[3]), "r"(b0), "r"(b1));
}

// ================= split fp32 -> bf16 hi/lo =================
__global__ void split_bf16(const float* __restrict__ src, uint32_t* __restrict__ hi,
                           uint32_t* __restrict__ lo, int npairs) {
    int i = blockIdx.x * blockDim.x + threadIdx.x;
    if (i < npairs) {
        float2 v = ((const float2*)src)[i];
        uint32_t h, l;
        split2(v, h, l);
        hi[i] = h;
        lo[i] = l;
    }
}

// ================= mma.sync bf16x3 GEMM, 3-stage pipeline =================
__global__ __launch_bounds__(256, 1) void gemm_bf16x3(
        const __nv_bfloat16* __restrict__ Ahi, const __nv_bfloat16* __restrict__ Alo,
        const __nv_bfloat16* __restrict__ Bhi, const __nv_bfloat16* __restrict__ Blo,
        float* __restrict__ C, int N) {
    extern __shared__ char smc[];
    const uint32_t sb = smem_to_u32(smc);
    const int tid = threadIdx.x;
    const int wid = tid >> 5, lane = tid & 31;
    const int wm = wid & 3, wn = wid >> 2;
    const int row0 = blockIdx.y * 128, col0 = blockIdx.x * 128;

    auto stA_hi = [&](int s) { return sb + s * 65536u; };
    auto stA_lo = [&](int s) { return sb + s * 65536u + 16384u; };
    auto stB_hi = [&](int s) { return sb + s * 65536u + 32768u; };
    auto stB_lo = [&](int s) { return sb + s * 65536u + 49152u; };

    auto load_stage = [&](int s, int kt) {
        const int k0 = kt * 64;
        #pragma unroll
        for (int i = 0; i < 4; i++) {
            int idx = tid + i * 256;
            int r = idx >> 3, c = idx & 7;
            uint32_t soff = (uint32_t)(r * 128 + ((c ^ (r & 7)) << 4));
            size_t gbyte = ((size_t)(row0 + r) * GK + k0) * 2 + c * 16;
            cp16(stA_hi(s) + soff, (const char*)Ahi + gbyte);
            cp16(stA_lo(s) + soff, (const char*)Alo + gbyte);
        }
        #pragma unroll
        for (int i = 0; i < 4; i++) {
            int idx = tid + i * 256;
            int r = idx >> 3, c = idx & 7;
            uint32_t soff = (uint32_t)(r * 128 + ((c ^ (r & 7)) << 4));
            size_t gbyte = ((size_t)(col0 + r) * GK + k0) * 2 + c * 16;
            cp16(stB_hi(s) + soff, (const char*)Bhi + gbyte);
            cp16(stB_lo(s) + soff, (const char*)Blo + gbyte);
        }
    };

    float acc[2][8][4];
    #pragma unroll
    for (int i = 0; i < 2; i++)
        #pragma unroll
        for (int j = 0; j < 8; j++)
            #pragma unroll
            for (int e = 0; e < 4; e++) acc[i][j][e] = 0.0f;

    load_stage(0, 0); CP_COMMIT();
    load_stage(1, 1); CP_COMMIT();

    const int lrow = lane & 15, khalf = lane >> 4;

    for (int kt = 0; kt < 16; kt++) {
        if (kt < 15) CP_WAIT(1); else CP_WAIT(0);
        __syncthreads();
        if (kt + 2 < 16) { load_stage((kt + 2) % 3, kt + 2); CP_COMMIT(); }

        const int s = kt % 3;
        const uint32_t aHi = stA_hi(s), aLo = stA_lo(s);
        const uint32_t bHi = stB_hi(s), bLo = stB_lo(s);

        #pragma unroll
        for (int ks = 0; ks < 4; ks++) {
            const int c = ks * 2 + khalf;
            uint32_t ah[2][4], al[2][4];
            #pragma unroll
            for (int ma = 0; ma < 2; ma++) {
                int r = wm * 32 + ma * 16 + lrow;
                uint32_t off = (uint32_t)(r * 128 + ((c ^ (r & 7)) << 4));
                ldsm4(ah[ma], aHi + off);
                ldsm4(al[ma], aLo + off);
            }
            uint32_t bh[4][4], bl[4][4];
            #pragma unroll
            for (int nb = 0; nb < 4; nb++) {
                int r = wn * 64 + nb * 16 + lrow;
                uint32_t off = (uint32_t)(r * 128 + ((c ^ (r & 7)) << 4));
                ldsm4(bh[nb], bHi + off);
                ldsm4(bl[nb], bLo + off);
            }
            #pragma unroll
            for (int ma = 0; ma < 2; ma++) {
                #pragma unroll
                for (int nb = 0; nb < 4; nb++) {
                    mma16816(acc[ma][nb * 2],     ah[ma], bh[nb][0], bh[nb][2]);
                    mma16816(acc[ma][nb * 2],     ah[ma], bl[nb][0], bl[nb][2]);
                    mma16816(acc[ma][nb * 2],     al[ma], bh[nb][0], bh[nb][2]);
                    mma16816(acc[ma][nb * 2 + 1], ah[ma], bh[nb][1], bh[nb][3]);
                    mma16816(acc[ma][nb * 2 + 1], ah[ma], bl[nb][1], bl[nb][3]);
                    mma16816(acc[ma][nb * 2 + 1], al[ma], bh[nb][1], bh[nb][3]);
                }
            }
        }
    }

    const int crow = lane >> 2, ccol = (lane & 3) * 2;
    #pragma unroll
    for (int ma = 0; ma < 2; ma++) {
        #pragma unroll
        for (int na = 0; na < 8; na++) {
            int r = row0 + wm * 32 + ma * 16 + crow;
            int cc = col0 + wn * 64 + na * 8 + ccol;
            *(float2*)&C[(size_t)r * N + cc]       = make_float2(acc[ma][na][0], acc[ma][na][1]);
            *(float2*)&C[(size_t)(r + 8) * N + cc] = make_float2(acc[ma][na][2], acc[ma][na][3]);
        }
    }
}

// ================= RMSNorm + RoPE -> bf16 hi/lo (Q,K) and fp16 (V) planes =================
__global__ void normrope(const float* __restrict__ qw, const float* __restrict__ kw) {
    const int row  = blockIdx.x;
    const int slot = blockIdx.y * 4 + threadIdx.y;
    const int lane = threadIdx.x;
    const int b = row / SEQ, t = row % SEQ;

    const float* src;
    if (slot < NH)             src = &g_qkv[(size_t)row * QKVN + slot * DK];
    else if (slot < NH + NKV)  src = &g_qkv[(size_t)row * QKVN + DM + (slot - NH) * DK];
    else                       src = &g_qkv[(size_t)row * QKVN + DM + NKV * DK + (slot - NH - NKV) * DK];

    float x1 = src[2 * lane], x2 = src[2 * lane + 1];

    if (slot >= NH + NKV) {   // V: fp16 single plane
        size_t di = (((size_t)b * NKV + (slot - NH - NKV)) * SEQ + t) * 32 + lane;
        g_vh[di] = pack_h2(x1, x2);
        return;
    }

    float ss = x1 * x1 + x2 * x2;
    #pragma unroll
    for (int o = 16; o; o >>= 1) ss += __shfl_xor_sync(0xffffffffu, ss, o);
    const float rnorm = rsqrtf(ss * (1.0f / DK) + 1.1920929e-07f);
    const float* w = (slot < NH) ? qw : kw;
    float y1 = x1 * rnorm * w[2 * lane];
    float y2 = x2 * rnorm * w[2 * lane + 1];

    float inv_freq = __powf(10000.0f, -(float)(2 * lane) / (float)DK);
    float ang = (float)t * inv_freq;
    float s, c;
    sincosf(ang, &s, &c);
    float o1 = y1 * c - y2 * s;
    float o2 = y1 * s + y2 * c;

    uint32_t hi, lo;
    if (slot < NH) {           // Q: fold softmax scale 1/8 and log2(e)
        const float qs = 0.125f * 1.4426950408889634f;
        split2(make_float2(o1 * qs, o2 * qs), hi, lo);
        size_t di = (((size_t)b * NH + slot) * SEQ + t) * 32 + lane;
        g_qhi[di] = hi; g_qlo[di] = lo;
    } else {
        split2(make_float2(o1, o2), hi, lo);
        size_t di = (((size_t)b * NKV + (slot - NH)) * SEQ + t) * 32 + lane;
        g_khi[di] = hi; g_klo[di] = lo;
    }
}

// ================= tensor-core causal flash attention =================
// QK: 3x bf16 split (exact exponents). PV: fp16-single P and V (1 MMA chain).
// Fixed-base softmax (no running max; RMSNorm bounds |log2 scores| <= 11.6).
__global__ __launch_bounds__(256, 1) void attn_mma() {
    extern __shared__ char sma[];
    const uint32_t sb = smem_to_u32(sma);
    const int tid = threadIdx.x;
    const int wid = tid >> 5, lane = tid & 31;
    const int qb = (int)gridDim.x - 1 - (int)blockIdx.x;   // heavy blocks first
    const int h  = blockIdx.y, b = blockIdx.z;
    const int kvh = h / GROUPS;

    auto KHI = [&](int s) { return sb + s * 49152u; };
    auto KLO = [&](int s) { return sb + s * 49152u + 16384u; };
    auto VH  = [&](int s) { return sb + s * 49152u + 32768u; };

    const char* qhiB = (const char*)g_qhi + (((size_t)b * NH + h) * SEQ + (size_t)qb * 128) * 128;
    const char* qloB = (const char*)g_qlo + (((size_t)b * NH + h) * SEQ + (size_t)qb * 128) * 128;
    const char* khiB = (const char*)g_khi + ((size_t)b * NKV + kvh) * SEQ * 128;
    const char* kloB = (const char*)g_klo + ((size_t)b * NKV + kvh) * SEQ * 128;
    const char* vhB  = (const char*)g_vh  + ((size_t)b * NKV + kvh) * SEQ * 128;

    // ---- stage Q (128 rows x 128B per plane) into stage0 area, load fragments ----
    {
        const uint32_t QH = sb, QL = sb + 16384u;
        #pragma unroll
        for (int i = 0; i < 4; i++) {
            int idx = tid + i * 256;
            int r = idx >> 3, c = idx & 7;
            uint32_t soff = (uint32_t)(r * 128 + ((c ^ (r & 7)) << 4));
            cp16(QH + soff, qhiB + (size_t)r * 128 + c * 16);
            cp16(QL + soff, qloB + (size_t)r * 128 + c * 16);
        }
        CP_COMMIT(); CP_WAIT(0);
        __syncthreads();
    }
    uint32_t qh[4][4], ql[4][4];
    {
        const int lrow = lane & 15, khalf = lane >> 4;
        const int r = wid * 16 + lrow;
        #pragma unroll
        for (int ks = 0; ks < 4; ks++) {
            const int c = ks * 2 + khalf;
            uint32_t off = (uint32_t)(r * 128 + ((c ^ (r & 7)) << 4));
            ldsm4(qh[ks], sb + off);
            ldsm4(ql[ks], sb + 16384u + off);
        }
    }
    __syncthreads();

    auto load_kv = [&](int s, int kb) {
        #pragma unroll
        for (int i = 0; i < 4; i++) {
            int idx = tid + i * 256;
            int r = idx >> 3, c = idx & 7;
            uint32_t soff = (uint32_t)(r * 128 + ((c ^ (r & 7)) << 4));
            size_t gb = ((size_t)kb * 128 + r) * 128 + c * 16;
            cp16(KHI(s) + soff, khiB + gb);
            cp16(KLO(s) + soff, kloB + gb);
            cp16(VH(s)  + soff, vhB  + gb);
        }
    };

    const int nkb = qb + 1;
    float oa[8][4];
    #pragma unroll
    for (int j = 0; j < 8; j++)
        #pragma unroll
        for (int e = 0; e < 4; e++) oa[j][e] = 0.0f;
    float l0 = 0.0f, l1 = 0.0f;

    const int gr0 = qb * 128 + wid * 16 + (lane >> 2);
    const int gr1 = gr0 + 8;
    const int lrow = lane & 15, khalf = lane >> 4;
    const int vrow_base = ((lane >> 3) & 1) * 8 + (lane & 7);
    const int vkh = lane >> 4;

    load_kv(0, 0);
    CP_COMMIT();

    for (int kb = 0; kb < nkb; kb++) {
        CP_WAIT(0);
        __syncthreads();
        if (kb + 1 < nkb) { load_kv((kb + 1) & 1, kb + 1); CP_COMMIT(); }

        const int s = kb & 1;
        const uint32_t kHi = KHI(s), kLo = KLO(s), vH = VH(s);

        // ---- S = Q K^T over 128 key columns (3-way bf16 split) ----
        float sc[16][4];
        #pragma unroll
        for (int j = 0; j < 16; j++)
            #pragma unroll
            for (int e = 0; e < 4; e++) sc[j][e] = 0.0f;

        #pragma unroll
        for (int ks = 0; ks < 4; ks++) {
            const int c = ks * 2 + khalf;
            #pragma unroll
            for (int nb = 0; nb < 8; nb++) {
                int r = nb * 16 + lrow;
                uint32_t off = (uint32_t)(r * 128 + ((c ^ (r & 7)) << 4));
                uint32_t kh[4], kl[4];
                ldsm4(kh, kHi + off);
                ldsm4(kl, kLo + off);
                mma16816(sc[2 * nb],     qh[ks], kh[0], kh[2]);
                mma16816(sc[2 * nb],     qh[ks], kl[0], kl[2]);
                mma16816(sc[2 * nb],     ql[ks], kh[0], kh[2]);
                mma16816(sc[2 * nb + 1], qh[ks], kh[1], kh[3]);
                mma16816(sc[2 * nb + 1], qh[ks], kl[1], kl[3]);
                mma16816(sc[2 * nb + 1], ql[ks], kh[1], kh[3]);
            }
        }

        // ---- causal mask (diagonal tile only) ----
        if (kb == qb) {
            #pragma unroll
            for (int j = 0; j < 16; j++) {
                const int c0 = kb * 128 + 8 * j + (lane & 3) * 2;
                const int c1 = c0 + 1;
                if (c0 > gr0) sc[j][0] = -INFINITY;
                if (c1 > gr0) sc[j][1] = -INFINITY;
                if (c0 > gr1) sc[j][2] = -INFINITY;
                if (c1 > gr1) sc[j][3] = -INFINITY;
            }
        }

        // ---- fixed-base softmax: P = exp2(S), accumulate partial sums ----
        #pragma unroll
        for (int j = 0; j < 16; j++) {
            sc[j][0] = ex2(sc[j][0]);
            sc[j][1] = ex2(sc[j][1]);
            sc[j][2] = ex2(sc[j][2]);
            sc[j][3] = ex2(sc[j][3]);
            l0 += sc[j][0] + sc[j][1];
            l1 += sc[j][2] + sc[j][3];
        }

        // ---- P fragments as fp16 (single instruction per pair) ----
        uint32_t pa[8][4];
        #pragma unroll
        for (int kk = 0; kk < 8; kk++) {
            pa[kk][0] = pack_h2(sc[2 * kk][0],     sc[2 * kk][1]);
            pa[kk][1] = pack_h2(sc[2 * kk][2],     sc[2 * kk][3]);
            pa[kk][2] = pack_h2(sc[2 * kk + 1][0], sc[2 * kk + 1][1]);
            pa[kk][3] = pack_h2(sc[2 * kk + 1][2], sc[2 * kk + 1][3]);
        }

        // ---- O += P V (fp16 single chain), V via ldmatrix.trans ----
        #pragma unroll
        for (int kk = 0; kk < 8; kk++) {
            const int vr = kk * 16 + vrow_base;
            #pragma unroll
            for (int ng = 0; ng < 4; ng++) {
                const int vc = ng * 2 + vkh;
                uint32_t off = (uint32_t)(vr * 128 + ((vc ^ (vr & 7)) << 4));
                uint32_t vh[4];
                ldsm4t(vh, vH + off);
                mma16816h(oa[2 * ng],     pa[kk], vh[0], vh[1]);
                mma16816h(oa[2 * ng + 1], pa[kk], vh[2], vh[3]);
            }
        }
    }

    // ---- reduce l within quad, normalize, store hi/lo planes ----
    l0 += __shfl_xor_sync(0xffffffffu, l0, 1);
    l0 += __shfl_xor_sync(0xffffffffu, l0, 2);
    l1 += __shfl_xor_sync(0xffffffffu, l1, 1);
    l1 += __shfl_xor_sync(0xffffffffu, l1, 2);
    const float inv0 = 1.0f / l0, inv1 = 1.0f / l1;
    const int t0 = qb * 128 + wid * 16 + (lane >> 2);
    const size_t row0 = (size_t)b * SEQ + t0;
    const size_t row1 = row0 + 8;
    #pragma unroll
    for (int j = 0; j < 8; j++) {
        const int cidx = h * 32 + j * 4 + (lane & 3);
        uint32_t hi, lo;
        split2(make_float2(oa[j][0] * inv0, oa[j][1] * inv0), hi, lo);
        g_ahi[row0 * 512 + cidx] = hi;
        g_alo[row0 * 512 + cidx] = lo;
        split2(make_float2(oa[j][2] * inv1, oa[j][3] * inv1), hi, lo);
        g_ahi[row1 * 512 + cidx] = hi;
        g_alo[row1 * 512 + cidx] = lo;
    }
}

// ================= launch =================
extern "C" void kernel_launch(void* const* d_in, const int* in_sizes, int n_in,
                              void* d_out, int out_size) {
    const float* x    = (const float*)d_in[0];
    const float* qkvo = (const float*)d_in[1];
    const float* qw   = (const float*)d_in[2];
    const float* kw   = (const float*)d_in[3];
    float* out = (float*)d_out;

    void *p_qkv, *p_xhi, *p_xlo, *p_whi, *p_wlo, *p_ahi, *p_alo;
    cudaGetSymbolAddress(&p_qkv, g_qkv);
    cudaGetSymbolAddress(&p_xhi, g_xhi); cudaGetSymbolAddress(&p_xlo, g_xlo);
    cudaGetSymbolAddress(&p_whi, g_whi); cudaGetSymbolAddress(&p_wlo, g_wlo);
    cudaGetSymbolAddress(&p_ahi, g_ahi); cudaGetSymbolAddress(&p_alo, g_alo);

    const int GEMM_SMEM = 3 * 65536;   // 192 KB
    const int ATTN_SMEM = 2 * 49152;   // 96 KB
    cudaFuncSetAttribute(gemm_bf16x3, cudaFuncAttributeMaxDynamicSharedMemorySize, GEMM_SMEM);
    cudaFuncSetAttribute(attn_mma, cudaFuncAttributeMaxDynamicSharedMemorySize, ATTN_SMEM);

    // 0) split x and weights to bf16 hi/lo planes
    {
        int np = ROWS * GK / 2;
        split_bf16<<<np / 256, 256>>>(x, (uint32_t*)p_xhi, (uint32_t*)p_xlo, np);
        int nw = 2560 * GK / 2;
        split_bf16<<<nw / 256, 256>>>(qkvo, (uint32_t*)p_whi, (uint32_t*)p_wlo, nw);
    }

    // 1) QKV projection
    gemm_bf16x3<<<dim3(QKVN / 128, ROWS / 128), 256, GEMM_SMEM>>>(
        (const __nv_bfloat16*)p_xhi, (const __nv_bfloat16*)p_xlo,
        (const __nv_bfloat16*)p_whi, (const __nv_bfloat16*)p_wlo,
        (float*)p_qkv, QKVN);

    // 2) RMSNorm + RoPE -> Q/K bf16 hi/lo planes, V fp16 plane
    normrope<<<dim3(ROWS, 6), dim3(32, 4)>>>(qw, kw);

    // 3) tensor-core causal flash attention -> g_ahi/g_alo
    attn_mma<<<dim3(SEQ / 128, NH, BATCH), 256, ATTN_SMEM>>>();

    // 4) O projection
    gemm_bf16x3<<<dim3(DM / 128, ROWS / 128), 256, GEMM_SMEM>>>(
        (const __nv_bfloat16*)p_ahi, (const __nv_bfloat16*)p_alo,
        (const __nv_bfloat16*)p_whi + (size_t)QKVN * GK,
        (const __nv_bfloat16*)p_wlo + (size_t)QKVN * GK,
        out, DM);
}

// round 8
// speedup vs baseline: 5.8570x; 1.3260x over previous
#include <cuda_runtime.h>
#include <cuda_fp16.h>
#include <math.h>
#include <stdint.h>

#define BATCH 2
#define SEQ   2048
#define DM    1024
#define NH    16
#define NKV   4
#define DK    64
#define QKVN  1536
#define ROWS  (BATCH*SEQ)
#define GROUPS (NH/NKV)
#define GK    1024

// ---------------- scratch (fp16 packed pairs in uint32) ----------------
__device__ float g_qkv[ROWS * QKVN];
__device__ uint32_t g_xhi[ROWS * GK / 2],  g_xlo[ROWS * GK / 2];    // x hi/lo fp16
__device__ uint32_t g_wh [2560 * GK / 2];                            // weights single fp16
__device__ uint32_t g_ahi[ROWS * DM / 2],  g_alo[ROWS * DM / 2];    // attn out hi/lo fp16
__device__ uint32_t g_qhi[BATCH * NH  * SEQ * DK / 2], g_qlo[BATCH * NH  * SEQ * DK / 2];
__device__ uint32_t g_kh [BATCH * NKV * SEQ * DK / 2];               // K single fp16
__device__ uint32_t g_vh [BATCH * NKV * SEQ * DK / 2];               // V single fp16

// ================= helpers =================
__device__ __forceinline__ uint32_t smem_to_u32(const void* p) {
    uint32_t a;
    asm("{ .reg .u64 t; cvta.to.shared.u64 t, %1; cvt.u32.u64 %0, t; }" : "=r"(a) : "l"(p));
    return a;
}
__device__ __forceinline__ float ex2(float x) {
    float r; asm("ex2.approx.f32 %0, %1;" : "=f"(r) : "f"(x)); return r;
}
// pack two floats to f16x2 (first arg -> low half)
__device__ __forceinline__ uint32_t pack_h2(float lo, float hi) {
    uint32_t r;
    asm("cvt.rn.f16x2.f32 %0, %1, %2;" : "=r"(r) : "f"(hi), "f"(lo));
    return r;
}
__device__ __forceinline__ void splitH2(float2 v, uint32_t& hi, uint32_t& lo) {
    __half h0 = __float2half_rn(v.x);
    __half h1 = __float2half_rn(v.y);
    float r0 = v.x - __half2float(h0);
    float r1 = v.y - __half2float(h1);
    hi = (uint32_t)__half_as_ushort(h0) | ((uint32_t)__half_as_ushort(h1) << 16);
    lo = pack_h2(r0, r1);
}
__device__ __forceinline__ void cp16(uint32_t saddr, const void* gaddr) {
    asm volatile("cp.async.cg.shared.global [%0], [%1], 16;" :: "r"(saddr), "l"(gaddr));
}
#define CP_COMMIT() asm volatile("cp.async.commit_group;")
#define CP_WAIT(N)  asm volatile("cp.async.wait_group %0;" :: "n"(N))

__device__ __forceinline__ void ldsm4(uint32_t* r, uint32_t addr) {
    asm volatile("ldmatrix.sync.aligned.m8n8.x4.shared.b16 {%0,%1,%2,%3}, [%4];"
        : "=r"(r[0]), "=r"(r[1]), "=r"(r[2]), "=r"(r[3]) : "r"(addr));
}
__device__ __forceinline__ void ldsm4t(uint32_t* r, uint32_t addr) {
    asm volatile("ldmatrix.sync.aligned.m8n8.x4.trans.shared.b16 {%0,%1,%2,%3}, [%4];"
        : "=r"(r[0]), "=r"(r[1]), "=r"(r[2]), "=r"(r[3]) : "r"(addr));
}
__device__ __forceinline__ void mma16816h(float* c, const uint32_t* a, uint32_t b0, uint32_t b1) {
    asm volatile("mma.sync.aligned.m16n8k16.row.col.f32.f16.f16.f32 "
        "{%0,%1,%2,%3}, {%4,%5,%6,%7}, {%8,%9}, {%0,%1,%2,%3};"
        : "+f"(c[0]), "+f"(c[1]), "+f"(c[2]), "+f"(c[3])
        : "r"(a[0]), "r"(a[1]), "r"(a[2]), "r"(a[3]), "r"(b0), "r"(b1));
}

// ================= split / pack kernels =================
__global__ void split_f16(const float* __restrict__ src, uint32_t* __restrict__ hi,
                          uint32_t* __restrict__ lo, int npairs) {
    int i = blockIdx.x * blockDim.x + threadIdx.x;
    if (i < npairs) {
        float2 v = ((const float2*)src)[i];
        uint32_t h, l;
        splitH2(v, h, l);
        hi[i] = h;
        lo[i] = l;
    }
}
__global__ void pack_f16(const float* __restrict__ src, uint32_t* __restrict__ dst, int npairs) {
    int i = blockIdx.x * blockDim.x + threadIdx.x;
    if (i < npairs) {
        float2 v = ((const float2*)src)[i];
        dst[i] = pack_h2(v.x, v.y);
    }
}

// ================= fp16x2 GEMM: C = A(hi+lo) * Bh^T, 3-stage pipeline =================
// 128x128 CTA tile, BK=64, 256 threads; stage = Ahi|Alo|Bh (48KB), 3 stages.
__global__ __launch_bounds__(256, 1) void gemm_f16x2(
        const __half* __restrict__ Ahi, const __half* __restrict__ Alo,
        const __half* __restrict__ Bh, float* __restrict__ C, int N) {
    extern __shared__ char smc[];
    const uint32_t sb = smem_to_u32(smc);
    const int tid = threadIdx.x;
    const int wid = tid >> 5, lane = tid & 31;
    const int wm = wid & 3, wn = wid >> 2;
    const int row0 = blockIdx.y * 128, col0 = blockIdx.x * 128;

    auto stA_hi = [&](int s) { return sb + s * 49152u; };
    auto stA_lo = [&](int s) { return sb + s * 49152u + 16384u; };
    auto stB    = [&](int s) { return sb + s * 49152u + 32768u; };

    auto load_stage = [&](int s, int kt) {
        const int k0 = kt * 64;
        #pragma unroll
        for (int i = 0; i < 4; i++) {
            int idx = tid + i * 256;
            int r = idx >> 3, c = idx & 7;
            uint32_t soff = (uint32_t)(r * 128 + ((c ^ (r & 7)) << 4));
            size_t gbyteA = ((size_t)(row0 + r) * GK + k0) * 2 + c * 16;
            size_t gbyteB = ((size_t)(col0 + r) * GK + k0) * 2 + c * 16;
            cp16(stA_hi(s) + soff, (const char*)Ahi + gbyteA);
            cp16(stA_lo(s) + soff, (const char*)Alo + gbyteA);
            cp16(stB(s)    + soff, (const char*)Bh  + gbyteB);
        }
    };

    float acc[2][8][4];
    #pragma unroll
    for (int i = 0; i < 2; i++)
        #pragma unroll
        for (int j = 0; j < 8; j++)
            #pragma unroll
            for (int e = 0; e < 4; e++) acc[i][j][e] = 0.0f;

    load_stage(0, 0); CP_COMMIT();
    load_stage(1, 1); CP_COMMIT();

    const int lrow = lane & 15, khalf = lane >> 4;

    for (int kt = 0; kt < 16; kt++) {
        if (kt < 15) CP_WAIT(1); else CP_WAIT(0);
        __syncthreads();
        if (kt + 2 < 16) { load_stage((kt + 2) % 3, kt + 2); CP_COMMIT(); }

        const int s = kt % 3;
        const uint32_t aHi = stA_hi(s), aLo = stA_lo(s), bH = stB(s);

        #pragma unroll
        for (int ks = 0; ks < 4; ks++) {
            const int c = ks * 2 + khalf;
            uint32_t ah[2][4], al[2][4];
            #pragma unroll
            for (int ma = 0; ma < 2; ma++) {
                int r = wm * 32 + ma * 16 + lrow;
                uint32_t off = (uint32_t)(r * 128 + ((c ^ (r & 7)) << 4));
                ldsm4(ah[ma], aHi + off);
                ldsm4(al[ma], aLo + off);
            }
            uint32_t bh[4][4];
            #pragma unroll
            for (int nb = 0; nb < 4; nb++) {
                int r = wn * 64 + nb * 16 + lrow;
                uint32_t off = (uint32_t)(r * 128 + ((c ^ (r & 7)) << 4));
                ldsm4(bh[nb], bH + off);
            }
            #pragma unroll
            for (int ma = 0; ma < 2; ma++) {
                #pragma unroll
                for (int nb = 0; nb < 4; nb++) {
                    mma16816h(acc[ma][nb * 2],     ah[ma], bh[nb][0], bh[nb][2]);
                    mma16816h(acc[ma][nb * 2],     al[ma], bh[nb][0], bh[nb][2]);
                    mma16816h(acc[ma][nb * 2 + 1], ah[ma], bh[nb][1], bh[nb][3]);
                    mma16816h(acc[ma][nb * 2 + 1], al[ma], bh[nb][1], bh[nb][3]);
                }
            }
        }
    }

    const int crow = lane >> 2, ccol = (lane & 3) * 2;
    #pragma unroll
    for (int ma = 0; ma < 2; ma++) {
        #pragma unroll
        for (int na = 0; na < 8; na++) {
            int r = row0 + wm * 32 + ma * 16 + crow;
            int cc = col0 + wn * 64 + na * 8 + ccol;
            *(float2*)&C[(size_t)r * N + cc]       = make_float2(acc[ma][na][0], acc[ma][na][1]);
            *(float2*)&C[(size_t)(r + 8) * N + cc] = make_float2(acc[ma][na][2], acc[ma][na][3]);
        }
    }
}

// ================= RMSNorm + RoPE -> Q fp16 hi/lo; K,V fp16 single =================
__global__ void normrope(const float* __restrict__ qw, const float* __restrict__ kw) {
    const int row  = blockIdx.x;
    const int slot = blockIdx.y * 4 + threadIdx.y;
    const int lane = threadIdx.x;
    const int b = row / SEQ, t = row % SEQ;

    const float* src;
    if (slot < NH)             src = &g_qkv[(size_t)row * QKVN + slot * DK];
    else if (slot < NH + NKV)  src = &g_qkv[(size_t)row * QKVN + DM + (slot - NH) * DK];
    else                       src = &g_qkv[(size_t)row * QKVN + DM + NKV * DK + (slot - NH - NKV) * DK];

    float x1 = src[2 * lane], x2 = src[2 * lane + 1];

    if (slot >= NH + NKV) {   // V: fp16 single
        size_t di = (((size_t)b * NKV + (slot - NH - NKV)) * SEQ + t) * 32 + lane;
        g_vh[di] = pack_h2(x1, x2);
        return;
    }

    float ss = x1 * x1 + x2 * x2;
    #pragma unroll
    for (int o = 16; o; o >>= 1) ss += __shfl_xor_sync(0xffffffffu, ss, o);
    const float rnorm = rsqrtf(ss * (1.0f / DK) + 1.1920929e-07f);
    const float* w = (slot < NH) ? qw : kw;
    float y1 = x1 * rnorm * w[2 * lane];
    float y2 = x2 * rnorm * w[2 * lane + 1];

    float inv_freq = __powf(10000.0f, -(float)(2 * lane) / (float)DK);
    float ang = (float)t * inv_freq;
    float s, c;
    sincosf(ang, &s, &c);
    float o1 = y1 * c - y2 * s;
    float o2 = y1 * s + y2 * c;

    if (slot < NH) {           // Q: fold 1/8 and log2(e); fp16 hi/lo
        const float qs = 0.125f * 1.4426950408889634f;
        uint32_t hi, lo;
        splitH2(make_float2(o1 * qs, o2 * qs), hi, lo);
        size_t di = (((size_t)b * NH + slot) * SEQ + t) * 32 + lane;
        g_qhi[di] = hi; g_qlo[di] = lo;
    } else {                   // K: fp16 single
        size_t di = (((size_t)b * NKV + (slot - NH)) * SEQ + t) * 32 + lane;
        g_kh[di] = pack_h2(o1, o2);
    }
}

// ================= tensor-core causal flash attention =================
// QK: Q fp16 hi/lo x K fp16 single (2 chains). PV: fp16 single (1 chain).
// Fixed-base exp2 softmax (RMSNorm bounds |log2 scores| <= 11.6).
__global__ __launch_bounds__(256, 1) void attn_mma() {
    extern __shared__ char sma[];
    const uint32_t sb = smem_to_u32(sma);
    const int tid = threadIdx.x;
    const int wid = tid >> 5, lane = tid & 31;
    const int qb = (int)gridDim.x - 1 - (int)blockIdx.x;   // heavy blocks first
    const int h  = blockIdx.y, b = blockIdx.z;
    const int kvh = h / GROUPS;

    auto KH = [&](int s) { return sb + s * 32768u; };
    auto VH = [&](int s) { return sb + s * 32768u + 16384u; };

    const char* qhiB = (const char*)g_qhi + (((size_t)b * NH + h) * SEQ + (size_t)qb * 128) * 128;
    const char* qloB = (const char*)g_qlo + (((size_t)b * NH + h) * SEQ + (size_t)qb * 128) * 128;
    const char* khB  = (const char*)g_kh  + ((size_t)b * NKV + kvh) * SEQ * 128;
    const char* vhB  = (const char*)g_vh  + ((size_t)b * NKV + kvh) * SEQ * 128;

    // ---- stage Q (hi+lo, 32KB) into stage area, load fragments ----
    {
        const uint32_t QH = sb, QL = sb + 16384u;
        #pragma unroll
        for (int i = 0; i < 4; i++) {
            int idx = tid + i * 256;
            int r = idx >> 3, c = idx & 7;
            uint32_t soff = (uint32_t)(r * 128 + ((c ^ (r & 7)) << 4));
            cp16(QH + soff, qhiB + (size_t)r * 128 + c * 16);
            cp16(QL + soff, qloB + (size_t)r * 128 + c * 16);
        }
        CP_COMMIT(); CP_WAIT(0);
        __syncthreads();
    }
    uint32_t qh[4][4], ql[4][4];
    {
        const int lrow = lane & 15, khalf = lane >> 4;
        const int r = wid * 16 + lrow;
        #pragma unroll
        for (int ks = 0; ks < 4; ks++) {
            const int c = ks * 2 + khalf;
            uint32_t off = (uint32_t)(r * 128 + ((c ^ (r & 7)) << 4));
            ldsm4(qh[ks], sb + off);
            ldsm4(ql[ks], sb + 16384u + off);
        }
    }
    __syncthreads();

    auto load_kv = [&](int s, int kb) {
        #pragma unroll
        for (int i = 0; i < 4; i++) {
            int idx = tid + i * 256;
            int r = idx >> 3, c = idx & 7;
            uint32_t soff = (uint32_t)(r * 128 + ((c ^ (r & 7)) << 4));
            size_t gb = ((size_t)kb * 128 + r) * 128 + c * 16;
            cp16(KH(s) + soff, khB + gb);
            cp16(VH(s) + soff, vhB + gb);
        }
    };

    const int nkb = qb + 1;
    float oa[8][4];
    #pragma unroll
    for (int j = 0; j < 8; j++)
        #pragma unroll
        for (int e = 0; e < 4; e++) oa[j][e] = 0.0f;
    float l0 = 0.0f, l1 = 0.0f;

    const int gr0 = qb * 128 + wid * 16 + (lane >> 2);
    const int gr1 = gr0 + 8;
    const int lrow = lane & 15, khalf = lane >> 4;
    const int vrow_base = ((lane >> 3) & 1) * 8 + (lane & 7);
    const int vkh = lane >> 4;

    load_kv(0, 0);
    CP_COMMIT();

    for (int kb = 0; kb < nkb; kb++) {
        CP_WAIT(0);
        __syncthreads();
        if (kb + 1 < nkb) { load_kv((kb + 1) & 1, kb + 1); CP_COMMIT(); }

        const int s = kb & 1;
        const uint32_t kH = KH(s), vH = VH(s);

        // ---- S = Q K^T over 128 key columns (2 chains: Qh*K + Ql*K) ----
        float sc[16][4];
        #pragma unroll
        for (int j = 0; j < 16; j++)
            #pragma unroll
            for (int e = 0; e < 4; e++) sc[j][e] = 0.0f;

        #pragma unroll
        for (int ks = 0; ks < 4; ks++) {
            const int c = ks * 2 + khalf;
            #pragma unroll
            for (int nb = 0; nb < 8; nb++) {
                int r = nb * 16 + lrow;
                uint32_t off = (uint32_t)(r * 128 + ((c ^ (r & 7)) << 4));
                uint32_t kh[4];
                ldsm4(kh, kH + off);
                mma16816h(sc[2 * nb],     qh[ks], kh[0], kh[2]);
                mma16816h(sc[2 * nb],     ql[ks], kh[0], kh[2]);
                mma16816h(sc[2 * nb + 1], qh[ks], kh[1], kh[3]);
                mma16816h(sc[2 * nb + 1], ql[ks], kh[1], kh[3]);
            }
        }

        // ---- causal mask (diagonal tile only) ----
        if (kb == qb) {
            #pragma unroll
            for (int j = 0; j < 16; j++) {
                const int c0 = kb * 128 + 8 * j + (lane & 3) * 2;
                const int c1 = c0 + 1;
                if (c0 > gr0) sc[j][0] = -INFINITY;
                if (c1 > gr0) sc[j][1] = -INFINITY;
                if (c0 > gr1) sc[j][2] = -INFINITY;
                if (c1 > gr1) sc[j][3] = -INFINITY;
            }
        }

        // ---- fixed-base softmax: P = exp2(S), partial row sums ----
        #pragma unroll
        for (int j = 0; j < 16; j++) {
            sc[j][0] = ex2(sc[j][0]);
            sc[j][1] = ex2(sc[j][1]);
            sc[j][2] = ex2(sc[j][2]);
            sc[j][3] = ex2(sc[j][3]);
            l0 += sc[j][0] + sc[j][1];
            l1 += sc[j][2] + sc[j][3];
        }

        // ---- P fragments as fp16 ----
        uint32_t pa[8][4];
        #pragma unroll
        for (int kk = 0; kk < 8; kk++) {
            pa[kk][0] = pack_h2(sc[2 * kk][0],     sc[2 * kk][1]);
            pa[kk][1] = pack_h2(sc[2 * kk][2],     sc[2 * kk][3]);
            pa[kk][2] = pack_h2(sc[2 * kk + 1][0], sc[2 * kk + 1][1]);
            pa[kk][3] = pack_h2(sc[2 * kk + 1][2], sc[2 * kk + 1][3]);
        }

        // ---- O += P V (fp16 single chain), V via ldmatrix.trans ----
        #pragma unroll
        for (int kk = 0; kk < 8; kk++) {
            const int vr = kk * 16 + vrow_base;
            #pragma unroll
            for (int ng = 0; ng < 4; ng++) {
                const int vc = ng * 2 + vkh;
                uint32_t off = (uint32_t)(vr * 128 + ((vc ^ (vr & 7)) << 4));
                uint32_t vh[4];
                ldsm4t(vh, vH + off);
                mma16816h(oa[2 * ng],     pa[kk], vh[0], vh[1]);
                mma16816h(oa[2 * ng + 1], pa[kk], vh[2], vh[3]);
            }
        }
    }

    // ---- reduce l within quad, normalize, store fp16 hi/lo planes ----
    l0 += __shfl_xor_sync(0xffffffffu, l0, 1);
    l0 += __shfl_xor_sync(0xffffffffu, l0, 2);
    l1 += __shfl_xor_sync(0xffffffffu, l1, 1);
    l1 += __shfl_xor_sync(0xffffffffu, l1, 2);
    const float inv0 = 1.0f / l0, inv1 = 1.0f / l1;
    const int t0 = qb * 128 + wid * 16 + (lane >> 2);
    const size_t row0 = (size_t)b * SEQ + t0;
    const size_t row1 = row0 + 8;
    #pragma unroll
    for (int j = 0; j < 8; j++) {
        const int cidx = h * 32 + j * 4 + (lane & 3);
        uint32_t hi, lo;
        splitH2(make_float2(oa[j][0] * inv0, oa[j][1] * inv0), hi, lo);
        g_ahi[row0 * 512 + cidx] = hi;
        g_alo[row0 * 512 + cidx] = lo;
        splitH2(make_float2(oa[j][2] * inv1, oa[j][3] * inv1), hi, lo);
        g_ahi[row1 * 512 + cidx] = hi;
        g_alo[row1 * 512 + cidx] = lo;
    }
}

// ================= launch =================
extern "C" void kernel_launch(void* const* d_in, const int* in_sizes, int n_in,
                              void* d_out, int out_size) {
    const float* x    = (const float*)d_in[0];
    const float* qkvo = (const float*)d_in[1];
    const float* qw   = (const float*)d_in[2];
    const float* kw   = (const float*)d_in[3];
    float* out = (float*)d_out;

    void *p_qkv, *p_xhi, *p_xlo, *p_wh, *p_ahi, *p_alo;
    cudaGetSymbolAddress(&p_qkv, g_qkv);
    cudaGetSymbolAddress(&p_xhi, g_xhi); cudaGetSymbolAddress(&p_xlo, g_xlo);
    cudaGetSymbolAddress(&p_wh, g_wh);
    cudaGetSymbolAddress(&p_ahi, g_ahi); cudaGetSymbolAddress(&p_alo, g_alo);

    const int GEMM_SMEM = 3 * 49152;   // 144 KB
    const int ATTN_SMEM = 2 * 32768;   // 64 KB
    cudaFuncSetAttribute(gemm_f16x2, cudaFuncAttributeMaxDynamicSharedMemorySize, GEMM_SMEM);
    cudaFuncSetAttribute(attn_mma, cudaFuncAttributeMaxDynamicSharedMemorySize, ATTN_SMEM);

    // 0) split x (hi/lo) and pack weights (single fp16)
    {
        int np = ROWS * GK / 2;
        split_f16<<<np / 256, 256>>>(x, (uint32_t*)p_xhi, (uint32_t*)p_xlo, np);
        int nw = 2560 * GK / 2;
        pack_f16<<<nw / 256, 256>>>(qkvo, (uint32_t*)p_wh, nw);
    }

    // 1) QKV projection
    gemm_f16x2<<<dim3(QKVN / 128, ROWS / 128), 256, GEMM_SMEM>>>(
        (const __half*)p_xhi, (const __half*)p_xlo,
        (const __half*)p_wh, (float*)p_qkv, QKVN);

    // 2) RMSNorm + RoPE -> Q fp16 hi/lo, K/V fp16 single
    normrope<<<dim3(ROWS, 6), dim3(32, 4)>>>(qw, kw);

    // 3) tensor-core causal flash attention -> g_ahi/g_alo
    attn_mma<<<dim3(SEQ / 128, NH, BATCH), 256, ATTN_SMEM>>>();

    // 4) O projection
    gemm_f16x2<<<dim3(DM / 128, ROWS / 128), 256, GEMM_SMEM>>>(
        (const __half*)p_ahi, (const __half*)p_alo,
        (const __half*)p_wh + (size_t)QKVN * GK, out, DM);
}

// round 9
// speedup vs baseline: 6.0212x; 1.0280x over previous
#include <cuda_runtime.h>
#include <cuda_fp16.h>
#include <math.h>
#include <stdint.h>

#define BATCH 2
#define SEQ   2048
#define DM    1024
#define NH    16
#define NKV   4
#define DK    64
#define QKVN  1536
#define ROWS  (BATCH*SEQ)
#define GROUPS (NH/NKV)
#define GK    1024

// ---------------- scratch (fp16 packed pairs in uint32) ----------------
__device__ uint32_t g_xhi[ROWS * GK / 2],  g_xlo[ROWS * GK / 2];    // x hi/lo fp16
__device__ uint32_t g_wh [2560 * GK / 2];                            // weights single fp16
__device__ uint32_t g_ahi[ROWS * DM / 2],  g_alo[ROWS * DM / 2];    // attn out hi/lo fp16
__device__ uint32_t g_qhi[BATCH * NH  * SEQ * DK / 2], g_qlo[BATCH * NH  * SEQ * DK / 2];
__device__ uint32_t g_kh [BATCH * NKV * SEQ * DK / 2];               // K single fp16
__device__ uint32_t g_vh [BATCH * NKV * SEQ * DK / 2];               // V single fp16

// ================= helpers =================
__device__ __forceinline__ uint32_t smem_to_u32(const void* p) {
    uint32_t a;
    asm("{ .reg .u64 t; cvta.to.shared.u64 t, %1; cvt.u32.u64 %0, t; }" : "=r"(a) : "l"(p));
    return a;
}
__device__ __forceinline__ float ex2(float x) {
    float r; asm("ex2.approx.f32 %0, %1;" : "=f"(r) : "f"(x)); return r;
}
__device__ __forceinline__ uint32_t pack_h2(float lo, float hi) {
    uint32_t r;
    asm("cvt.rn.f16x2.f32 %0, %1, %2;" : "=r"(r) : "f"(hi), "f"(lo));
    return r;
}
__device__ __forceinline__ void splitH2(float2 v, uint32_t& hi, uint32_t& lo) {
    __half h0 = __float2half_rn(v.x);
    __half h1 = __float2half_rn(v.y);
    float r0 = v.x - __half2float(h0);
    float r1 = v.y - __half2float(h1);
    hi = (uint32_t)__half_as_ushort(h0) | ((uint32_t)__half_as_ushort(h1) << 16);
    lo = pack_h2(r0, r1);
}
__device__ __forceinline__ void cp16(uint32_t saddr, const void* gaddr) {
    asm volatile("cp.async.cg.shared.global [%0], [%1], 16;" :: "r"(saddr), "l"(gaddr));
}
#define CP_COMMIT() asm volatile("cp.async.commit_group;")
#define CP_WAIT(N)  asm volatile("cp.async.wait_group %0;" :: "n"(N))

__device__ __forceinline__ void ldsm4(uint32_t* r, uint32_t addr) {
    asm volatile("ldmatrix.sync.aligned.m8n8.x4.shared.b16 {%0,%1,%2,%3}, [%4];"
        : "=r"(r[0]), "=r"(r[1]), "=r"(r[2]), "=r"(r[3]) : "r"(addr));
}
__device__ __forceinline__ void ldsm4t(uint32_t* r, uint32_t addr) {
    asm volatile("ldmatrix.sync.aligned.m8n8.x4.trans.shared.b16 {%0,%1,%2,%3}, [%4];"
        : "=r"(r[0]), "=r"(r[1]), "=r"(r[2]), "=r"(r[3]) : "r"(addr));
}
__device__ __forceinline__ void mma16816h(float* c, const uint32_t* a, uint32_t b0, uint32_t b1) {
    asm volatile("mma.sync.aligned.m16n8k16.row.col.f32.f16.f16.f32 "
        "{%0,%1,%2,%3}, {%4,%5,%6,%7}, {%8,%9}, {%0,%1,%2,%3};"
        : "+f"(c[0]), "+f"(c[1]), "+f"(c[2]), "+f"(c[3])
        : "r"(a[0]), "r"(a[1]), "r"(a[2]), "r"(a[3]), "r"(b0), "r"(b1));
}

// ================= split / pack kernels =================
__global__ void split_f16(const float* __restrict__ src, uint32_t* __restrict__ hi,
                          uint32_t* __restrict__ lo, int npairs) {
    int i = blockIdx.x * blockDim.x + threadIdx.x;
    if (i < npairs) {
        float2 v = ((const float2*)src)[i];
        uint32_t h, l;
        splitH2(v, h, l);
        hi[i] = h;
        lo[i] = l;
    }
}
__global__ void pack_f16(const float* __restrict__ src, uint32_t* __restrict__ dst, int npairs) {
    int i = blockIdx.x * blockDim.x + threadIdx.x;
    if (i < npairs) {
        float2 v = ((const float2*)src)[i];
        dst[i] = pack_h2(v.x, v.y);
    }
}

// ================= fp16x2 GEMM, 4-stage pipeline =================
// FUSE_QKV: epilogue applies RMSNorm+RoPE and writes Q(hi/lo)/K/V fp16 planes.
// Otherwise plain fp32 store to C.
template<bool FUSE_QKV>
__global__ __launch_bounds__(256, 1) void gemm_f16x2(
        const __half* __restrict__ Ahi, const __half* __restrict__ Alo,
        const __half* __restrict__ Bh, float* __restrict__ C, int N,
        const float* __restrict__ qw, const float* __restrict__ kw) {
    extern __shared__ char smc[];
    const uint32_t sb = smem_to_u32(smc);
    const int tid = threadIdx.x;
    const int wid = tid >> 5, lane = tid & 31;
    const int wm = wid & 3, wn = wid >> 2;
    const int row0 = blockIdx.y * 128, col0 = blockIdx.x * 128;

    auto stA_hi = [&](int s) { return sb + s * 49152u; };
    auto stA_lo = [&](int s) { return sb + s * 49152u + 16384u; };
    auto stB    = [&](int s) { return sb + s * 49152u + 32768u; };

    auto load_stage = [&](int s, int kt) {
        const int k0 = kt * 64;
        #pragma unroll
        for (int i = 0; i < 4; i++) {
            int idx = tid + i * 256;
            int r = idx >> 3, c = idx & 7;
            uint32_t soff = (uint32_t)(r * 128 + ((c ^ (r & 7)) << 4));
            size_t gbyteA = ((size_t)(row0 + r) * GK + k0) * 2 + c * 16;
            size_t gbyteB = ((size_t)(col0 + r) * GK + k0) * 2 + c * 16;
            cp16(stA_hi(s) + soff, (const char*)Ahi + gbyteA);
            cp16(stA_lo(s) + soff, (const char*)Alo + gbyteA);
            cp16(stB(s)    + soff, (const char*)Bh  + gbyteB);
        }
    };

    float acc[2][8][4];
    #pragma unroll
    for (int i = 0; i < 2; i++)
        #pragma unroll
        for (int j = 0; j < 8; j++)
            #pragma unroll
            for (int e = 0; e < 4; e++) acc[i][j][e] = 0.0f;

    load_stage(0, 0); CP_COMMIT();
    load_stage(1, 1); CP_COMMIT();
    load_stage(2, 2); CP_COMMIT();

    const int lrow = lane & 15, khalf = lane >> 4;

    for (int kt = 0; kt < 16; kt++) {
        if (kt <= 13) CP_WAIT(2);
        else if (kt == 14) CP_WAIT(1);
        else CP_WAIT(0);
        __syncthreads();
        if (kt + 3 < 16) { load_stage((kt + 3) & 3, kt + 3); CP_COMMIT(); }

        const int s = kt & 3;
        const uint32_t aHi = stA_hi(s), aLo = stA_lo(s), bH = stB(s);

        #pragma unroll
        for (int ks = 0; ks < 4; ks++) {
            const int c = ks * 2 + khalf;
            uint32_t ah[2][4], al[2][4];
            #pragma unroll
            for (int ma = 0; ma < 2; ma++) {
                int r = wm * 32 + ma * 16 + lrow;
                uint32_t off = (uint32_t)(r * 128 + ((c ^ (r & 7)) << 4));
                ldsm4(ah[ma], aHi + off);
                ldsm4(al[ma], aLo + off);
            }
            uint32_t bh[4][4];
            #pragma unroll
            for (int nb = 0; nb < 4; nb++) {
                int r = wn * 64 + nb * 16 + lrow;
                uint32_t off = (uint32_t)(r * 128 + ((c ^ (r & 7)) << 4));
                ldsm4(bh[nb], bH + off);
            }
            #pragma unroll
            for (int ma = 0; ma < 2; ma++) {
                #pragma unroll
                for (int nb = 0; nb < 4; nb++) {
                    mma16816h(acc[ma][nb * 2],     ah[ma], bh[nb][0], bh[nb][2]);
                    mma16816h(acc[ma][nb * 2],     al[ma], bh[nb][0], bh[nb][2]);
                    mma16816h(acc[ma][nb * 2 + 1], ah[ma], bh[nb][1], bh[nb][3]);
                    mma16816h(acc[ma][nb * 2 + 1], al[ma], bh[nb][1], bh[nb][3]);
                }
            }
        }
    }

    const int crow = lane >> 2, ccl = lane & 3;

    if (!FUSE_QKV) {
        const int ccol = ccl * 2;
        #pragma unroll
        for (int ma = 0; ma < 2; ma++) {
            #pragma unroll
            for (int na = 0; na < 8; na++) {
                int r = row0 + wm * 32 + ma * 16 + crow;
                int cc = col0 + wn * 64 + na * 8 + ccol;
                *(float2*)&C[(size_t)r * N + cc]       = make_float2(acc[ma][na][0], acc[ma][na][1]);
                *(float2*)&C[(size_t)(r + 8) * N + cc] = make_float2(acc[ma][na][2], acc[ma][na][3]);
            }
        }
        return;
    }

    // ---------- fused RMSNorm + RoPE + fp16 pack epilogue ----------
    // warp owns 32 rows x 64 cols = one head slot: 0..15 Q, 16..19 K, 20..23 V
    const int slot = (col0 + wn * 64) >> 6;

    if (slot >= NH + NKV) {            // V: plain fp16 pack
        const int hv = slot - NH - NKV;
        #pragma unroll
        for (int ma = 0; ma < 2; ma++) {
            #pragma unroll
            for (int rr = 0; rr < 2; rr++) {
                const int row = row0 + wm * 32 + ma * 16 + rr * 8 + crow;
                const int b = row >> 11, t = row & (SEQ - 1);
                const size_t base = (((size_t)b * NKV + hv) * SEQ + t) * 32;
                #pragma unroll
                for (int na = 0; na < 8; na++) {
                    const int i = na * 4 + ccl;
                    g_vh[base + i] = pack_h2(acc[ma][na][rr * 2], acc[ma][na][rr * 2 + 1]);
                }
            }
        }
        return;
    }

    // Q or K: RMSNorm + RoPE
    const bool isQ = (slot < NH);
    const float* w = isQ ? qw : kw;
    float w0[8], w1[8], invf[8];
    #pragma unroll
    for (int na = 0; na < 8; na++) {
        const int i = na * 4 + ccl;
        w0[na] = w[2 * i];
        w1[na] = w[2 * i + 1];
        invf[na] = __powf(10000.0f, -(float)(2 * i) / (float)DK);
    }
    const float qs = 0.125f * 1.4426950408889634f;

    #pragma unroll
    for (int ma = 0; ma < 2; ma++) {
        #pragma unroll
        for (int rr = 0; rr < 2; rr++) {
            const int row = row0 + wm * 32 + ma * 16 + rr * 8 + crow;
            const int b = row >> 11, t = row & (SEQ - 1);

            float ss = 0.0f;
            #pragma unroll
            for (int na = 0; na < 8; na++) {
                float v0 = acc[ma][na][rr * 2], v1 = acc[ma][na][rr * 2 + 1];
                ss += v0 * v0 + v1 * v1;
            }
            ss += __shfl_xor_sync(0xffffffffu, ss, 1);
            ss += __shfl_xor_sync(0xffffffffu, ss, 2);
            const float rnorm = rsqrtf(ss * (1.0f / DK) + 1.1920929e-07f);

            const size_t base = isQ
                ? (((size_t)b * NH + slot) * SEQ + t) * 32
                : (((size_t)b * NKV + (slot - NH)) * SEQ + t) * 32;

            #pragma unroll
            for (int na = 0; na < 8; na++) {
                const int i = na * 4 + ccl;
                float y0 = acc[ma][na][rr * 2]     * rnorm * w0[na];
                float y1 = acc[ma][na][rr * 2 + 1] * rnorm * w1[na];
                float sv, cv;
                sincosf((float)t * invf[na], &sv, &cv);
                float o0 = y0 * cv - y1 * sv;
                float o1 = y0 * sv + y1 * cv;
                if (isQ) {
                    uint32_t hi, lo;
                    splitH2(make_float2(o0 * qs, o1 * qs), hi, lo);
                    g_qhi[base + i] = hi;
                    g_qlo[base + i] = lo;
                } else {
                    g_kh[base + i] = pack_h2(o0, o1);
                }
            }
        }
    }
}

// ================= tensor-core causal flash attention =================
// QK: Q fp16 hi/lo x K fp16 single (2 chains). PV: fp16 single (1 chain).
// Fixed-base exp2 softmax (RMSNorm bounds |log2 scores| <= 11.6).
__global__ __launch_bounds__(256, 1) void attn_mma() {
    extern __shared__ char sma[];
    const uint32_t sb = smem_to_u32(sma);
    const int tid = threadIdx.x;
    const int wid = tid >> 5, lane = tid & 31;
    const int qb = (int)gridDim.x - 1 - (int)blockIdx.x;   // heavy blocks first
    const int h  = blockIdx.y, b = blockIdx.z;
    const int kvh = h / GROUPS;

    auto KH = [&](int s) { return sb + s * 32768u; };
    auto VH = [&](int s) { return sb + s * 32768u + 16384u; };

    const char* qhiB = (const char*)g_qhi + (((size_t)b * NH + h) * SEQ + (size_t)qb * 128) * 128;
    const char* qloB = (const char*)g_qlo + (((size_t)b * NH + h) * SEQ + (size_t)qb * 128) * 128;
    const char* khB  = (const char*)g_kh  + ((size_t)b * NKV + kvh) * SEQ * 128;
    const char* vhB  = (const char*)g_vh  + ((size_t)b * NKV + kvh) * SEQ * 128;

    // ---- stage Q (hi+lo, 32KB), load fragments ----
    {
        const uint32_t QH = sb, QL = sb + 16384u;
        #pragma unroll
        for (int i = 0; i < 4; i++) {
            int idx = tid + i * 256;
            int r = idx >> 3, c = idx & 7;
            uint32_t soff = (uint32_t)(r * 128 + ((c ^ (r & 7)) << 4));
            cp16(QH + soff, qhiB + (size_t)r * 128 + c * 16);
            cp16(QL + soff, qloB + (size_t)r * 128 + c * 16);
        }
        CP_COMMIT(); CP_WAIT(0);
        __syncthreads();
    }
    uint32_t qh[4][4], ql[4][4];
    {
        const int lrow = lane & 15, khalf = lane >> 4;
        const int r = wid * 16 + lrow;
        #pragma unroll
        for (int ks = 0; ks < 4; ks++) {
            const int c = ks * 2 + khalf;
            uint32_t off = (uint32_t)(r * 128 + ((c ^ (r & 7)) << 4));
            ldsm4(qh[ks], sb + off);
            ldsm4(ql[ks], sb + 16384u + off);
        }
    }
    __syncthreads();

    auto load_kv = [&](int s, int kb) {
        #pragma unroll
        for (int i = 0; i < 4; i++) {
            int idx = tid + i * 256;
            int r = idx >> 3, c = idx & 7;
            uint32_t soff = (uint32_t)(r * 128 + ((c ^ (r & 7)) << 4));
            size_t gb = ((size_t)kb * 128 + r) * 128 + c * 16;
            cp16(KH(s) + soff, khB + gb);
            cp16(VH(s) + soff, vhB + gb);
        }
    };

    const int nkb = qb + 1;
    float oa[8][4];
    #pragma unroll
    for (int j = 0; j < 8; j++)
        #pragma unroll
        for (int e = 0; e < 4; e++) oa[j][e] = 0.0f;
    float l0 = 0.0f, l1 = 0.0f;

    const int gr0 = qb * 128 + wid * 16 + (lane >> 2);
    const int gr1 = gr0 + 8;
    const int lrow = lane & 15, khalf = lane >> 4;
    const int vrow_base = ((lane >> 3) & 1) * 8 + (lane & 7);
    const int vkh = lane >> 4;

    load_kv(0, 0);
    CP_COMMIT();

    for (int kb = 0; kb < nkb; kb++) {
        CP_WAIT(0);
        __syncthreads();
        if (kb + 1 < nkb) { load_kv((kb + 1) & 1, kb + 1); CP_COMMIT(); }

        const int s = kb & 1;
        const uint32_t kH = KH(s), vH = VH(s);

        // ---- S = Q K^T (2 chains) ----
        float sc[16][4];
        #pragma unroll
        for (int j = 0; j < 16; j++)
            #pragma unroll
            for (int e = 0; e < 4; e++) sc[j][e] = 0.0f;

        #pragma unroll
        for (int ks = 0; ks < 4; ks++) {
            const int c = ks * 2 + khalf;
            #pragma unroll
            for (int nb = 0; nb < 8; nb++) {
                int r = nb * 16 + lrow;
                uint32_t off = (uint32_t)(r * 128 + ((c ^ (r & 7)) << 4));
                uint32_t kh[4];
                ldsm4(kh, kH + off);
                mma16816h(sc[2 * nb],     qh[ks], kh[0], kh[2]);
                mma16816h(sc[2 * nb],     ql[ks], kh[0], kh[2]);
                mma16816h(sc[2 * nb + 1], qh[ks], kh[1], kh[3]);
                mma16816h(sc[2 * nb + 1], ql[ks], kh[1], kh[3]);
            }
        }

        // ---- causal mask (diagonal tile only) ----
        if (kb == qb) {
            #pragma unroll
            for (int j = 0; j < 16; j++) {
                const int c0 = kb * 128 + 8 * j + (lane & 3) * 2;
                const int c1 = c0 + 1;
                if (c0 > gr0) sc[j][0] = -INFINITY;
                if (c1 > gr0) sc[j][1] = -INFINITY;
                if (c0 > gr1) sc[j][2] = -INFINITY;
                if (c1 > gr1) sc[j][3] = -INFINITY;
            }
        }

        // ---- fixed-base softmax: P = exp2(S), partial row sums ----
        #pragma unroll
        for (int j = 0; j < 16; j++) {
            sc[j][0] = ex2(sc[j][0]);
            sc[j][1] = ex2(sc[j][1]);
            sc[j][2] = ex2(sc[j][2]);
            sc[j][3] = ex2(sc[j][3]);
            l0 += sc[j][0] + sc[j][1];
            l1 += sc[j][2] + sc[j][3];
        }

        // ---- P fragments as fp16 ----
        uint32_t pa[8][4];
        #pragma unroll
        for (int kk = 0; kk < 8; kk++) {
            pa[kk][0] = pack_h2(sc[2 * kk][0],     sc[2 * kk][1]);
            pa[kk][1] = pack_h2(sc[2 * kk][2],     sc[2 * kk][3]);
            pa[kk][2] = pack_h2(sc[2 * kk + 1][0], sc[2 * kk + 1][1]);
            pa[kk][3] = pack_h2(sc[2 * kk + 1][2], sc[2 * kk + 1][3]);
        }

        // ---- O += P V (fp16 single chain) ----
        #pragma unroll
        for (int kk = 0; kk < 8; kk++) {
            const int vr = kk * 16 + vrow_base;
            #pragma unroll
            for (int ng = 0; ng < 4; ng++) {
                const int vc = ng * 2 + vkh;
                uint32_t off = (uint32_t)(vr * 128 + ((vc ^ (vr & 7)) << 4));
                uint32_t vh[4];
                ldsm4t(vh, vH + off);
                mma16816h(oa[2 * ng],     pa[kk], vh[0], vh[1]);
                mma16816h(oa[2 * ng + 1], pa[kk], vh[2], vh[3]);
            }
        }
    }

    // ---- reduce l within quad, normalize, store fp16 hi/lo planes ----
    l0 += __shfl_xor_sync(0xffffffffu, l0, 1);
    l0 += __shfl_xor_sync(0xffffffffu, l0, 2);
    l1 += __shfl_xor_sync(0xffffffffu, l1, 1);
    l1 += __shfl_xor_sync(0xffffffffu, l1, 2);
    const float inv0 = 1.0f / l0, inv1 = 1.0f / l1;
    const int t0 = qb * 128 + wid * 16 + (lane >> 2);
    const size_t row0 = (size_t)b * SEQ + t0;
    const size_t row1 = row0 + 8;
    #pragma unroll
    for (int j = 0; j < 8; j++) {
        const int cidx = h * 32 + j * 4 + (lane & 3);
        uint32_t hi, lo;
        splitH2(make_float2(oa[j][0] * inv0, oa[j][1] * inv0), hi, lo);
        g_ahi[row0 * 512 + cidx] = hi;
        g_alo[row0 * 512 + cidx] = lo;
        splitH2(make_float2(oa[j][2] * inv1, oa[j][3] * inv1), hi, lo);
        g_ahi[row1 * 512 + cidx] = hi;
        g_alo[row1 * 512 + cidx] = lo;
    }
}

// ================= launch =================
extern "C" void kernel_launch(void* const* d_in, const int* in_sizes, int n_in,
                              void* d_out, int out_size) {
    const float* x    = (const float*)d_in[0];
    const float* qkvo = (const float*)d_in[1];
    const float* qw   = (const float*)d_in[2];
    const float* kw   = (const float*)d_in[3];
    float* out = (float*)d_out;

    void *p_xhi, *p_xlo, *p_wh, *p_ahi, *p_alo;
    cudaGetSymbolAddress(&p_xhi, g_xhi); cudaGetSymbolAddress(&p_xlo, g_xlo);
    cudaGetSymbolAddress(&p_wh, g_wh);
    cudaGetSymbolAddress(&p_ahi, g_ahi); cudaGetSymbolAddress(&p_alo, g_alo);

    const int GEMM_SMEM = 4 * 49152;   // 192 KB
    const int ATTN_SMEM = 2 * 32768;   // 64 KB
    cudaFuncSetAttribute(gemm_f16x2<true>,  cudaFuncAttributeMaxDynamicSharedMemorySize, GEMM_SMEM);
    cudaFuncSetAttribute(gemm_f16x2<false>, cudaFuncAttributeMaxDynamicSharedMemorySize, GEMM_SMEM);
    cudaFuncSetAttribute(attn_mma, cudaFuncAttributeMaxDynamicSharedMemorySize, ATTN_SMEM);

    // 0) split x (hi/lo) and pack weights (single fp16)
    {
        int np = ROWS * GK / 2;
        split_f16<<<np / 256, 256>>>(x, (uint32_t*)p_xhi, (uint32_t*)p_xlo, np);
        int nw = 2560 * GK / 2;
        pack_f16<<<nw / 256, 256>>>(qkvo, (uint32_t*)p_wh, nw);
    }

    // 1) QKV projection + fused RMSNorm/RoPE -> Q hi/lo, K, V fp16 planes
    gemm_f16x2<true><<<dim3(QKVN / 128, ROWS / 128), 256, GEMM_SMEM>>>(
        (const __half*)p_xhi, (const __half*)p_xlo,
        (const __half*)p_wh, nullptr, QKVN, qw, kw);

    // 2) tensor-core causal flash attention -> g_ahi/g_alo
    attn_mma<<<dim3(SEQ / 128, NH, BATCH), 256, ATTN_SMEM>>>();

    // 3) O projection
    gemm_f16x2<false><<<dim3(DM / 128, ROWS / 128), 256, GEMM_SMEM>>>(
        (const __half*)p_ahi, (const __half*)p_alo,
        (const __half*)p_wh + (size_t)QKVN * GK, out, DM, nullptr, nullptr);
}

// round 10
// speedup vs baseline: 6.0830x; 1.0103x over previous
#include <cuda_runtime.h>
#include <cuda_fp16.h>
#include <math.h>
#include <stdint.h>

#define BATCH 2
#define SEQ   2048
#define DM    1024
#define NH    16
#define NKV   4
#define DK    64
#define QKVN  1536
#define ROWS  (BATCH*SEQ)
#define GROUPS (NH/NKV)
#define GK    1024

// ---------------- scratch (fp16 packed pairs in uint32) ----------------
__device__ uint32_t g_xhi[ROWS * GK / 2],  g_xlo[ROWS * GK / 2];
__device__ uint32_t g_wh [2560 * GK / 2];
__device__ uint32_t g_ahi[ROWS * DM / 2],  g_alo[ROWS * DM / 2];
__device__ uint32_t g_qhi[BATCH * NH  * SEQ * DK / 2], g_qlo[BATCH * NH  * SEQ * DK / 2];
__device__ uint32_t g_kh [BATCH * NKV * SEQ * DK / 2];
__device__ uint32_t g_vh [BATCH * NKV * SEQ * DK / 2];

// ================= helpers =================
__device__ __forceinline__ uint32_t smem_to_u32(const void* p) {
    uint32_t a;
    asm("{ .reg .u64 t; cvta.to.shared.u64 t, %1; cvt.u32.u64 %0, t; }" : "=r"(a) : "l"(p));
    return a;
}
__device__ __forceinline__ float ex2(float x) {
    float r; asm("ex2.approx.f32 %0, %1;" : "=f"(r) : "f"(x)); return r;
}
__device__ __forceinline__ uint32_t pack_h2(float lo, float hi) {
    uint32_t r;
    asm("cvt.rn.f16x2.f32 %0, %1, %2;" : "=r"(r) : "f"(hi), "f"(lo));
    return r;
}
__device__ __forceinline__ void splitH2(float2 v, uint32_t& hi, uint32_t& lo) {
    __half h0 = __float2half_rn(v.x);
    __half h1 = __float2half_rn(v.y);
    float r0 = v.x - __half2float(h0);
    float r1 = v.y - __half2float(h1);
    hi = (uint32_t)__half_as_ushort(h0) | ((uint32_t)__half_as_ushort(h1) << 16);
    lo = pack_h2(r0, r1);
}
__device__ __forceinline__ void cp16(uint32_t saddr, const void* gaddr) {
    asm volatile("cp.async.cg.shared.global [%0], [%1], 16;" :: "r"(saddr), "l"(gaddr));
}
#define CP_COMMIT() asm volatile("cp.async.commit_group;")
#define CP_WAIT(N)  asm volatile("cp.async.wait_group %0;" :: "n"(N))

__device__ __forceinline__ void ldsm4(uint32_t* r, uint32_t addr) {
    asm volatile("ldmatrix.sync.aligned.m8n8.x4.shared.b16 {%0,%1,%2,%3}, [%4];"
        : "=r"(r[0]), "=r"(r[1]), "=r"(r[2]), "=r"(r[3]) : "r"(addr));
}
__device__ __forceinline__ void ldsm4t(uint32_t* r, uint32_t addr) {
    asm volatile("ldmatrix.sync.aligned.m8n8.x4.trans.shared.b16 {%0,%1,%2,%3}, [%4];"
        : "=r"(r[0]), "=r"(r[1]), "=r"(r[2]), "=r"(r[3]) : "r"(addr));
}
__device__ __forceinline__ void mma16816h(float* c, const uint32_t* a, uint32_t b0, uint32_t b1) {
    asm volatile("mma.sync.aligned.m16n8k16.row.col.f32.f16.f16.f32 "
        "{%0,%1,%2,%3}, {%4,%5,%6,%7}, {%8,%9}, {%0,%1,%2,%3};"
        : "+f"(c[0]), "+f"(c[1]), "+f"(c[2]), "+f"(c[3])
        : "r"(a[0]), "r"(a[1]), "r"(a[2]), "r"(a[3]), "r"(b0), "r"(b1));
}

// ================= split / pack kernels =================
__global__ void split_f16(const float* __restrict__ src, uint32_t* __restrict__ hi,
                          uint32_t* __restrict__ lo, int npairs) {
    int i = blockIdx.x * blockDim.x + threadIdx.x;
    if (i < npairs) {
        float2 v = ((const float2*)src)[i];
        uint32_t h, l;
        splitH2(v, h, l);
        hi[i] = h;
        lo[i] = l;
    }
}
__global__ void pack_f16(const float* __restrict__ src, uint32_t* __restrict__ dst, int npairs) {
    int i = blockIdx.x * blockDim.x + threadIdx.x;
    if (i < npairs) {
        float2 v = ((const float2*)src)[i];
        dst[i] = pack_h2(v.x, v.y);
    }
}

// ================= fp16x2 GEMM, 512 threads (16 warps), 4-stage pipeline =================
// warp tile 16m x 64n (warp grid 8x2). FUSE_QKV epilogue = RMSNorm+RoPE+fp16 planes.
template<bool FUSE_QKV>
__global__ __launch_bounds__(512, 1) void gemm_f16x2(
        const __half* __restrict__ Ahi, const __half* __restrict__ Alo,
        const __half* __restrict__ Bh, float* __restrict__ C, int N,
        const float* __restrict__ qw, const float* __restrict__ kw) {
    extern __shared__ char smc[];
    const uint32_t sb = smem_to_u32(smc);
    const int tid = threadIdx.x;
    const int wid = tid >> 5, lane = tid & 31;
    const int wm = wid >> 1, wn = wid & 1;        // 8 m-groups x 2 n-halves
    const int row0 = blockIdx.y * 128, col0 = blockIdx.x * 128;

    auto stA_hi = [&](int s) { return sb + s * 49152u; };
    auto stA_lo = [&](int s) { return sb + s * 49152u + 16384u; };
    auto stB    = [&](int s) { return sb + s * 49152u + 32768u; };

    auto load_stage = [&](int s, int kt) {
        const int k0 = kt * 64;
        #pragma unroll
        for (int i = 0; i < 2; i++) {
            int idx = tid + i * 512;
            int r = idx >> 3, c = idx & 7;
            uint32_t soff = (uint32_t)(r * 128 + ((c ^ (r & 7)) << 4));
            size_t gbyteA = ((size_t)(row0 + r) * GK + k0) * 2 + c * 16;
            size_t gbyteB = ((size_t)(col0 + r) * GK + k0) * 2 + c * 16;
            cp16(stA_hi(s) + soff, (const char*)Ahi + gbyteA);
            cp16(stA_lo(s) + soff, (const char*)Alo + gbyteA);
            cp16(stB(s)    + soff, (const char*)Bh  + gbyteB);
        }
    };

    float acc[8][4];
    #pragma unroll
    for (int j = 0; j < 8; j++)
        #pragma unroll
        for (int e = 0; e < 4; e++) acc[j][e] = 0.0f;

    load_stage(0, 0); CP_COMMIT();
    load_stage(1, 1); CP_COMMIT();
    load_stage(2, 2); CP_COMMIT();

    const int lrow = lane & 15, khalf = lane >> 4;

    for (int kt = 0; kt < 16; kt++) {
        if (kt <= 13) CP_WAIT(2);
        else if (kt == 14) CP_WAIT(1);
        else CP_WAIT(0);
        __syncthreads();
        if (kt + 3 < 16) { load_stage((kt + 3) & 3, kt + 3); CP_COMMIT(); }

        const int s = kt & 3;
        const uint32_t aHi = stA_hi(s), aLo = stA_lo(s), bH = stB(s);

        #pragma unroll
        for (int ks = 0; ks < 4; ks++) {
            const int c = ks * 2 + khalf;
            uint32_t ah[4], al[4];
            {
                int r = wm * 16 + lrow;
                uint32_t off = (uint32_t)(r * 128 + ((c ^ (r & 7)) << 4));
                ldsm4(ah, aHi + off);
                ldsm4(al, aLo + off);
            }
            #pragma unroll
            for (int nb = 0; nb < 4; nb++) {
                int r = wn * 64 + nb * 16 + lrow;
                uint32_t off = (uint32_t)(r * 128 + ((c ^ (r & 7)) << 4));
                uint32_t bh[4];
                ldsm4(bh, bH + off);
                mma16816h(acc[nb * 2],     ah, bh[0], bh[2]);
                mma16816h(acc[nb * 2],     al, bh[0], bh[2]);
                mma16816h(acc[nb * 2 + 1], ah, bh[1], bh[3]);
                mma16816h(acc[nb * 2 + 1], al, bh[1], bh[3]);
            }
        }
    }

    const int crow = lane >> 2, ccl = lane & 3;

    if (!FUSE_QKV) {
        const int ccol = ccl * 2;
        #pragma unroll
        for (int na = 0; na < 8; na++) {
            int r = row0 + wm * 16 + crow;
            int cc = col0 + wn * 64 + na * 8 + ccol;
            *(float2*)&C[(size_t)r * N + cc]       = make_float2(acc[na][0], acc[na][1]);
            *(float2*)&C[(size_t)(r + 8) * N + cc] = make_float2(acc[na][2], acc[na][3]);
        }
        return;
    }

    // ---------- fused RMSNorm + RoPE + fp16 pack epilogue ----------
    const int slot = (col0 + wn * 64) >> 6;   // one full head per warp

    if (slot >= NH + NKV) {            // V: plain fp16 pack
        const int hv = slot - NH - NKV;
        #pragma unroll
        for (int rr = 0; rr < 2; rr++) {
            const int row = row0 + wm * 16 + rr * 8 + crow;
            const int b = row >> 11, t = row & (SEQ - 1);
            const size_t base = (((size_t)b * NKV + hv) * SEQ + t) * 32;
            #pragma unroll
            for (int na = 0; na < 8; na++) {
                const int i = na * 4 + ccl;
                g_vh[base + i] = pack_h2(acc[na][rr * 2], acc[na][rr * 2 + 1]);
            }
        }
        return;
    }

    const bool isQ = (slot < NH);
    const float* w = isQ ? qw : kw;
    float w0[8], w1[8], invf[8];
    #pragma unroll
    for (int na = 0; na < 8; na++) {
        const int i = na * 4 + ccl;
        w0[na] = w[2 * i];
        w1[na] = w[2 * i + 1];
        invf[na] = __powf(10000.0f, -(float)(2 * i) / (float)DK);
    }
    const float qs = 0.125f * 1.4426950408889634f;

    #pragma unroll
    for (int rr = 0; rr < 2; rr++) {
        const int row = row0 + wm * 16 + rr * 8 + crow;
        const int b = row >> 11, t = row & (SEQ - 1);

        float ss = 0.0f;
        #pragma unroll
        for (int na = 0; na < 8; na++) {
            float v0 = acc[na][rr * 2], v1 = acc[na][rr * 2 + 1];
            ss += v0 * v0 + v1 * v1;
        }
        ss += __shfl_xor_sync(0xffffffffu, ss, 1);
        ss += __shfl_xor_sync(0xffffffffu, ss, 2);
        const float rnorm = rsqrtf(ss * (1.0f / DK) + 1.1920929e-07f);

        const size_t base = isQ
            ? (((size_t)b * NH + slot) * SEQ + t) * 32
            : (((size_t)b * NKV + (slot - NH)) * SEQ + t) * 32;

        #pragma unroll
        for (int na = 0; na < 8; na++) {
            const int i = na * 4 + ccl;
            float y0 = acc[na][rr * 2]     * rnorm * w0[na];
            float y1 = acc[na][rr * 2 + 1] * rnorm * w1[na];
            float sv, cv;
            sincosf((float)t * invf[na], &sv, &cv);
            float o0 = y0 * cv - y1 * sv;
            float o1 = y0 * sv + y1 * cv;
            if (isQ) {
                uint32_t hi, lo;
                splitH2(make_float2(o0 * qs, o1 * qs), hi, lo);
                g_qhi[base + i] = hi;
                g_qlo[base + i] = lo;
            } else {
                g_kh[base + i] = pack_h2(o0, o1);
            }
        }
    }
}

// ================= tensor-core causal flash attention, 512 threads =================
// warp grid 8(q-groups) x 2(kv-halves); warp = 16 q-rows x 64 kv-cols.
// Partial O / l per kv-half (legal: fixed-base softmax), combined via smem at end.
__global__ __launch_bounds__(512, 1) void attn_mma() {
    extern __shared__ char sma[];
    const uint32_t sb = smem_to_u32(sma);
    const int tid = threadIdx.x;
    const int wid = tid >> 5, lane = tid & 31;
    const int wq = wid >> 1, wk = wid & 1;
    const int qb = (int)gridDim.x - 1 - (int)blockIdx.x;   // heavy blocks first
    const int h  = blockIdx.y, b = blockIdx.z;
    const int kvh = h / GROUPS;

    auto KH = [&](int s) { return sb + s * 32768u; };
    auto VH = [&](int s) { return sb + s * 32768u + 16384u; };

    const char* qhiB = (const char*)g_qhi + (((size_t)b * NH + h) * SEQ + (size_t)qb * 128) * 128;
    const char* qloB = (const char*)g_qlo + (((size_t)b * NH + h) * SEQ + (size_t)qb * 128) * 128;
    const char* khB  = (const char*)g_kh  + ((size_t)b * NKV + kvh) * SEQ * 128;
    const char* vhB  = (const char*)g_vh  + ((size_t)b * NKV + kvh) * SEQ * 128;

    // ---- stage Q (hi+lo, 32KB), load fragments ----
    {
        const uint32_t QH = sb, QL = sb + 16384u;
        #pragma unroll
        for (int i = 0; i < 2; i++) {
            int idx = tid + i * 512;
            int r = idx >> 3, c = idx & 7;
            uint32_t soff = (uint32_t)(r * 128 + ((c ^ (r & 7)) << 4));
            cp16(QH + soff, qhiB + (size_t)r * 128 + c * 16);
            cp16(QL + soff, qloB + (size_t)r * 128 + c * 16);
        }
        CP_COMMIT(); CP_WAIT(0);
        __syncthreads();
    }
    const int lrow = lane & 15, khalf = lane >> 4;
    uint32_t qh[4][4], ql[4][4];
    {
        const int r = wq * 16 + lrow;
        #pragma unroll
        for (int ks = 0; ks < 4; ks++) {
            const int c = ks * 2 + khalf;
            uint32_t off = (uint32_t)(r * 128 + ((c ^ (r & 7)) << 4));
            ldsm4(qh[ks], sb + off);
            ldsm4(ql[ks], sb + 16384u + off);
        }
    }
    __syncthreads();

    auto load_kv = [&](int s, int kb) {
        #pragma unroll
        for (int i = 0; i < 2; i++) {
            int idx = tid + i * 512;
            int r = idx >> 3, c = idx & 7;
            uint32_t soff = (uint32_t)(r * 128 + ((c ^ (r & 7)) << 4));
            size_t gb = ((size_t)kb * 128 + r) * 128 + c * 16;
            cp16(KH(s) + soff, khB + gb);
            cp16(VH(s) + soff, vhB + gb);
        }
    };

    const int nkb = qb + 1;
    float oa[8][4];
    #pragma unroll
    for (int j = 0; j < 8; j++)
        #pragma unroll
        for (int e = 0; e < 4; e++) oa[j][e] = 0.0f;
    float l0 = 0.0f, l1 = 0.0f;

    const int gr0 = qb * 128 + wq * 16 + (lane >> 2);
    const int gr1 = gr0 + 8;
    const int vrow_base = ((lane >> 3) & 1) * 8 + (lane & 7);
    const int vkh = lane >> 4;

    load_kv(0, 0);
    CP_COMMIT();

    for (int kb = 0; kb < nkb; kb++) {
        CP_WAIT(0);
        __syncthreads();
        if (kb + 1 < nkb) { load_kv((kb + 1) & 1, kb + 1); CP_COMMIT(); }

        const int s = kb & 1;
        const uint32_t kH = KH(s), vH = VH(s);

        // ---- S = Q K^T over this warp's 64 kv columns (2 chains) ----
        float sc[8][4];
        #pragma unroll
        for (int j = 0; j < 8; j++)
            #pragma unroll
            for (int e = 0; e < 4; e++) sc[j][e] = 0.0f;

        #pragma unroll
        for (int ks = 0; ks < 4; ks++) {
            const int c = ks * 2 + khalf;
            #pragma unroll
            for (int nb = 0; nb < 4; nb++) {
                int r = wk * 64 + nb * 16 + lrow;
                uint32_t off = (uint32_t)(r * 128 + ((c ^ (r & 7)) << 4));
                uint32_t kh[4];
                ldsm4(kh, kH + off);
                mma16816h(sc[2 * nb],     qh[ks], kh[0], kh[2]);
                mma16816h(sc[2 * nb],     ql[ks], kh[0], kh[2]);
                mma16816h(sc[2 * nb + 1], qh[ks], kh[1], kh[3]);
                mma16816h(sc[2 * nb + 1], ql[ks], kh[1], kh[3]);
            }
        }

        // ---- causal mask (diagonal tile only) ----
        if (kb == qb) {
            #pragma unroll
            for (int j = 0; j < 8; j++) {
                const int c0 = kb * 128 + wk * 64 + 8 * j + (lane & 3) * 2;
                const int c1 = c0 + 1;
                if (c0 > gr0) sc[j][0] = -INFINITY;
                if (c1 > gr0) sc[j][1] = -INFINITY;
                if (c0 > gr1) sc[j][2] = -INFINITY;
                if (c1 > gr1) sc[j][3] = -INFINITY;
            }
        }

        // ---- fixed-base softmax: P = exp2(S), partial row sums ----
        #pragma unroll
        for (int j = 0; j < 8; j++) {
            sc[j][0] = ex2(sc[j][0]);
            sc[j][1] = ex2(sc[j][1]);
            sc[j][2] = ex2(sc[j][2]);
            sc[j][3] = ex2(sc[j][3]);
            l0 += sc[j][0] + sc[j][1];
            l1 += sc[j][2] + sc[j][3];
        }

        // ---- P fragments as fp16 ----
        uint32_t pa[4][4];
        #pragma unroll
        for (int kk = 0; kk < 4; kk++) {
            pa[kk][0] = pack_h2(sc[2 * kk][0],     sc[2 * kk][1]);
            pa[kk][1] = pack_h2(sc[2 * kk][2],     sc[2 * kk][3]);
            pa[kk][2] = pack_h2(sc[2 * kk + 1][0], sc[2 * kk + 1][1]);
            pa[kk][3] = pack_h2(sc[2 * kk + 1][2], sc[2 * kk + 1][3]);
        }

        // ---- O += P V over this warp's 64 kv rows (fp16 single chain) ----
        #pragma unroll
        for (int kk = 0; kk < 4; kk++) {
            const int vr = wk * 64 + kk * 16 + vrow_base;
            #pragma unroll
            for (int ng = 0; ng < 4; ng++) {
                const int vc = ng * 2 + vkh;
                uint32_t off = (uint32_t)(vr * 128 + ((vc ^ (vr & 7)) << 4));
                uint32_t vh[4];
                ldsm4t(vh, vH + off);
                mma16816h(oa[2 * ng],     pa[kk], vh[0], vh[1]);
                mma16816h(oa[2 * ng + 1], pa[kk], vh[2], vh[3]);
            }
        }
    }

    // ---- quad-reduce partial l, then combine kv-half partials via smem ----
    l0 += __shfl_xor_sync(0xffffffffu, l0, 1);
    l0 += __shfl_xor_sync(0xffffffffu, l0, 2);
    l1 += __shfl_xor_sync(0xffffffffu, l1, 1);
    l1 += __shfl_xor_sync(0xffffffffu, l1, 2);

    float* xch = (float*)sma;                       // 8 pairs x 32 lanes x 34 floats
    __syncthreads();                                 // all compute done; KV smem reusable
    if (wk == 1) {
        float* dst = xch + (wq * 32 + lane) * 34;
        #pragma unroll
        for (int j = 0; j < 8; j++) {
            dst[j * 4 + 0] = oa[j][0]; dst[j * 4 + 1] = oa[j][1];
            dst[j * 4 + 2] = oa[j][2]; dst[j * 4 + 3] = oa[j][3];
        }
        dst[32] = l0; dst[33] = l1;
    }
    __syncthreads();
    if (wk == 1) return;

    {
        const float* src = xch + (wq * 32 + lane) * 34;
        #pragma unroll
        for (int j = 0; j < 8; j++) {
            oa[j][0] += src[j * 4 + 0]; oa[j][1] += src[j * 4 + 1];
            oa[j][2] += src[j * 4 + 2]; oa[j][3] += src[j * 4 + 3];
        }
        l0 += src[32]; l1 += src[33];
    }

    const float inv0 = 1.0f / l0, inv1 = 1.0f / l1;
    const int t0 = qb * 128 + wq * 16 + (lane >> 2);
    const size_t row0 = (size_t)b * SEQ + t0;
    const size_t row1 = row0 + 8;
    #pragma unroll
    for (int j = 0; j < 8; j++) {
        const int cidx = h * 32 + j * 4 + (lane & 3);
        uint32_t hi, lo;
        splitH2(make_float2(oa[j][0] * inv0, oa[j][1] * inv0), hi, lo);
        g_ahi[row0 * 512 + cidx] = hi;
        g_alo[row0 * 512 + cidx] = lo;
        splitH2(make_float2(oa[j][2] * inv1, oa[j][3] * inv1), hi, lo);
        g_ahi[row1 * 512 + cidx] = hi;
        g_alo[row1 * 512 + cidx] = lo;
    }
}

// ================= launch =================
extern "C" void kernel_launch(void* const* d_in, const int* in_sizes, int n_in,
                              void* d_out, int out_size) {
    const float* x    = (const float*)d_in[0];
    const float* qkvo = (const float*)d_in[1];
    const float* qw   = (const float*)d_in[2];
    const float* kw   = (const float*)d_in[3];
    float* out = (float*)d_out;

    void *p_xhi, *p_xlo, *p_wh, *p_ahi, *p_alo;
    cudaGetSymbolAddress(&p_xhi, g_xhi); cudaGetSymbolAddress(&p_xlo, g_xlo);
    cudaGetSymbolAddress(&p_wh, g_wh);
    cudaGetSymbolAddress(&p_ahi, g_ahi); cudaGetSymbolAddress(&p_alo, g_alo);

    const int GEMM_SMEM = 4 * 49152;   // 192 KB
    const int ATTN_SMEM = 2 * 32768;   // 64 KB
    cudaFuncSetAttribute(gemm_f16x2<true>,  cudaFuncAttributeMaxDynamicSharedMemorySize, GEMM_SMEM);
    cudaFuncSetAttribute(gemm_f16x2<false>, cudaFuncAttributeMaxDynamicSharedMemorySize, GEMM_SMEM);
    cudaFuncSetAttribute(attn_mma, cudaFuncAttributeMaxDynamicSharedMemorySize, ATTN_SMEM);

    // 0) split x (hi/lo) and pack weights (single fp16)
    {
        int np = ROWS * GK / 2;
        split_f16<<<np / 256, 256>>>(x, (uint32_t*)p_xhi, (uint32_t*)p_xlo, np);
        int nw = 2560 * GK / 2;
        pack_f16<<<nw / 256, 256>>>(qkvo, (uint32_t*)p_wh, nw);
    }

    // 1) QKV projection + fused RMSNorm/RoPE -> Q hi/lo, K, V fp16 planes
    gemm_f16x2<true><<<dim3(QKVN / 128, ROWS / 128), 512, GEMM_SMEM>>>(
        (const __half*)p_xhi, (const __half*)p_xlo,
        (const __half*)p_wh, nullptr, QKVN, qw, kw);

    // 2) tensor-core causal flash attention -> g_ahi/g_alo
    attn_mma<<<dim3(SEQ / 128, NH, BATCH), 512, ATTN_SMEM>>>();

    // 3) O projection
    gemm_f16x2<false><<<dim3(DM / 128, ROWS / 128), 512, GEMM_SMEM>>>(
        (const __half*)p_ahi, (const __half*)p_alo,
        (const __half*)p_wh + (size_t)QKVN * GK, out, DM, nullptr, nullptr);
}

// round 11
// speedup vs baseline: 6.9198x; 1.1376x over previous
#include <cuda_runtime.h>
#include <cuda_fp16.h>
#include <math.h>
#include <stdint.h>

#define BATCH 2
#define SEQ   2048
#define DM    1024
#define NH    16
#define NKV   4
#define DK    64
#define QKVN  1536
#define ROWS  (BATCH*SEQ)
#define GROUPS (NH/NKV)
#define GK    1024

// ---------------- scratch (fp16 packed pairs in uint32) ----------------
__device__ uint32_t g_xhi[ROWS * GK / 2],  g_xlo[ROWS * GK / 2];
__device__ uint32_t g_wh [2560 * GK / 2];
__device__ uint32_t g_ahi[ROWS * DM / 2],  g_alo[ROWS * DM / 2];
__device__ uint32_t g_qh [BATCH * NH  * SEQ * DK / 2];   // Q single fp16 (scaled)
__device__ uint32_t g_kh [BATCH * NKV * SEQ * DK / 2];
__device__ uint32_t g_vh [BATCH * NKV * SEQ * DK / 2];

// ================= helpers =================
__device__ __forceinline__ uint32_t smem_to_u32(const void* p) {
    uint32_t a;
    asm("{ .reg .u64 t; cvta.to.shared.u64 t, %1; cvt.u32.u64 %0, t; }" : "=r"(a) : "l"(p));
    return a;
}
__device__ __forceinline__ float ex2(float x) {
    float r; asm("ex2.approx.f32 %0, %1;" : "=f"(r) : "f"(x)); return r;
}
__device__ __forceinline__ uint32_t pack_h2(float lo, float hi) {
    uint32_t r;
    asm("cvt.rn.f16x2.f32 %0, %1, %2;" : "=r"(r) : "f"(hi), "f"(lo));
    return r;
}
__device__ __forceinline__ void splitH2(float2 v, uint32_t& hi, uint32_t& lo) {
    __half h0 = __float2half_rn(v.x);
    __half h1 = __float2half_rn(v.y);
    float r0 = v.x - __half2float(h0);
    float r1 = v.y - __half2float(h1);
    hi = (uint32_t)__half_as_ushort(h0) | ((uint32_t)__half_as_ushort(h1) << 16);
    lo = pack_h2(r0, r1);
}
__device__ __forceinline__ void cp16(uint32_t saddr, const void* gaddr) {
    asm volatile("cp.async.cg.shared.global [%0], [%1], 16;" :: "r"(saddr), "l"(gaddr));
}
#define CP_COMMIT() asm volatile("cp.async.commit_group;")
#define CP_WAIT(N)  asm volatile("cp.async.wait_group %0;" :: "n"(N))

__device__ __forceinline__ void ldsm4(uint32_t* r, uint32_t addr) {
    asm volatile("ldmatrix.sync.aligned.m8n8.x4.shared.b16 {%0,%1,%2,%3}, [%4];"
        : "=r"(r[0]), "=r"(r[1]), "=r"(r[2]), "=r"(r[3]) : "r"(addr));
}
__device__ __forceinline__ void ldsm4t(uint32_t* r, uint32_t addr) {
    asm volatile("ldmatrix.sync.aligned.m8n8.x4.trans.shared.b16 {%0,%1,%2,%3}, [%4];"
        : "=r"(r[0]), "=r"(r[1]), "=r"(r[2]), "=r"(r[3]) : "r"(addr));
}
__device__ __forceinline__ void mma16816h(float* c, const uint32_t* a, uint32_t b0, uint32_t b1) {
    asm volatile("mma.sync.aligned.m16n8k16.row.col.f32.f16.f16.f32 "
        "{%0,%1,%2,%3}, {%4,%5,%6,%7}, {%8,%9}, {%0,%1,%2,%3};"
        : "+f"(c[0]), "+f"(c[1]), "+f"(c[2]), "+f"(c[3])
        : "r"(a[0]), "r"(a[1]), "r"(a[2]), "r"(a[3]), "r"(b0), "r"(b1));
}

// ================= split / pack kernels =================
__global__ void split_f16(const float* __restrict__ src, uint32_t* __restrict__ hi,
                          uint32_t* __restrict__ lo, int npairs) {
    int i = blockIdx.x * blockDim.x + threadIdx.x;
    if (i < npairs) {
        float2 v = ((const float2*)src)[i];
        uint32_t h, l;
        splitH2(v, h, l);
        hi[i] = h;
        lo[i] = l;
    }
}
__global__ void pack_f16(const float* __restrict__ src, uint32_t* __restrict__ dst, int npairs) {
    int i = blockIdx.x * blockDim.x + threadIdx.x;
    if (i < npairs) {
        float2 v = ((const float2*)src)[i];
        dst[i] = pack_h2(v.x, v.y);
    }
}

// ================= fp16x2 GEMM, 512 threads, 4-stage pipeline =================
template<bool FUSE_QKV>
__global__ __launch_bounds__(512, 1) void gemm_f16x2(
        const __half* __restrict__ Ahi, const __half* __restrict__ Alo,
        const __half* __restrict__ Bh, float* __restrict__ C, int N,
        const float* __restrict__ qw, const float* __restrict__ kw) {
    extern __shared__ char smc[];
    const uint32_t sb = smem_to_u32(smc);
    const int tid = threadIdx.x;
    const int wid = tid >> 5, lane = tid & 31;
    const int wm = wid >> 1, wn = wid & 1;
    const int row0 = blockIdx.y * 128, col0 = blockIdx.x * 128;

    auto stA_hi = [&](int s) { return sb + s * 49152u; };
    auto stA_lo = [&](int s) { return sb + s * 49152u + 16384u; };
    auto stB    = [&](int s) { return sb + s * 49152u + 32768u; };

    auto load_stage = [&](int s, int kt) {
        const int k0 = kt * 64;
        #pragma unroll
        for (int i = 0; i < 2; i++) {
            int idx = tid + i * 512;
            int r = idx >> 3, c = idx & 7;
            uint32_t soff = (uint32_t)(r * 128 + ((c ^ (r & 7)) << 4));
            size_t gbyteA = ((size_t)(row0 + r) * GK + k0) * 2 + c * 16;
            size_t gbyteB = ((size_t)(col0 + r) * GK + k0) * 2 + c * 16;
            cp16(stA_hi(s) + soff, (const char*)Ahi + gbyteA);
            cp16(stA_lo(s) + soff, (const char*)Alo + gbyteA);
            cp16(stB(s)    + soff, (const char*)Bh  + gbyteB);
        }
    };

    float acc[8][4];
    #pragma unroll
    for (int j = 0; j < 8; j++)
        #pragma unroll
        for (int e = 0; e < 4; e++) acc[j][e] = 0.0f;

    load_stage(0, 0); CP_COMMIT();
    load_stage(1, 1); CP_COMMIT();
    load_stage(2, 2); CP_COMMIT();

    const int lrow = lane & 15, khalf = lane >> 4;

    for (int kt = 0; kt < 16; kt++) {
        if (kt <= 13) CP_WAIT(2);
        else if (kt == 14) CP_WAIT(1);
        else CP_WAIT(0);
        __syncthreads();
        if (kt + 3 < 16) { load_stage((kt + 3) & 3, kt + 3); CP_COMMIT(); }

        const int s = kt & 3;
        const uint32_t aHi = stA_hi(s), aLo = stA_lo(s), bH = stB(s);

        #pragma unroll
        for (int ks = 0; ks < 4; ks++) {
            const int c = ks * 2 + khalf;
            uint32_t ah[4], al[4];
            {
                int r = wm * 16 + lrow;
                uint32_t off = (uint32_t)(r * 128 + ((c ^ (r & 7)) << 4));
                ldsm4(ah, aHi + off);
                ldsm4(al, aLo + off);
            }
            #pragma unroll
            for (int nb = 0; nb < 4; nb++) {
                int r = wn * 64 + nb * 16 + lrow;
                uint32_t off = (uint32_t)(r * 128 + ((c ^ (r & 7)) << 4));
                uint32_t bh[4];
                ldsm4(bh, bH + off);
                mma16816h(acc[nb * 2],     ah, bh[0], bh[2]);
                mma16816h(acc[nb * 2],     al, bh[0], bh[2]);
                mma16816h(acc[nb * 2 + 1], ah, bh[1], bh[3]);
                mma16816h(acc[nb * 2 + 1], al, bh[1], bh[3]);
            }
        }
    }

    const int crow = lane >> 2, ccl = lane & 3;

    if (!FUSE_QKV) {
        const int ccol = ccl * 2;
        #pragma unroll
        for (int na = 0; na < 8; na++) {
            int r = row0 + wm * 16 + crow;
            int cc = col0 + wn * 64 + na * 8 + ccol;
            *(float2*)&C[(size_t)r * N + cc]       = make_float2(acc[na][0], acc[na][1]);
            *(float2*)&C[(size_t)(r + 8) * N + cc] = make_float2(acc[na][2], acc[na][3]);
        }
        return;
    }

    // ---------- fused RMSNorm + RoPE + fp16 pack epilogue ----------
    const int slot = (col0 + wn * 64) >> 6;

    if (slot >= NH + NKV) {            // V
        const int hv = slot - NH - NKV;
        #pragma unroll
        for (int rr = 0; rr < 2; rr++) {
            const int row = row0 + wm * 16 + rr * 8 + crow;
            const int b = row >> 11, t = row & (SEQ - 1);
            const size_t base = (((size_t)b * NKV + hv) * SEQ + t) * 32;
            #pragma unroll
            for (int na = 0; na < 8; na++) {
                const int i = na * 4 + ccl;
                g_vh[base + i] = pack_h2(acc[na][rr * 2], acc[na][rr * 2 + 1]);
            }
        }
        return;
    }

    const bool isQ = (slot < NH);
    const float* w = isQ ? qw : kw;
    float w0[8], w1[8], invf[8];
    #pragma unroll
    for (int na = 0; na < 8; na++) {
        const int i = na * 4 + ccl;
        w0[na] = w[2 * i];
        w1[na] = w[2 * i + 1];
        invf[na] = __powf(10000.0f, -(float)(2 * i) / (float)DK);
    }
    const float qs = 0.125f * 1.4426950408889634f;

    #pragma unroll
    for (int rr = 0; rr < 2; rr++) {
        const int row = row0 + wm * 16 + rr * 8 + crow;
        const int b = row >> 11, t = row & (SEQ - 1);

        float ss = 0.0f;
        #pragma unroll
        for (int na = 0; na < 8; na++) {
            float v0 = acc[na][rr * 2], v1 = acc[na][rr * 2 + 1];
            ss += v0 * v0 + v1 * v1;
        }
        ss += __shfl_xor_sync(0xffffffffu, ss, 1);
        ss += __shfl_xor_sync(0xffffffffu, ss, 2);
        const float rnorm = rsqrtf(ss * (1.0f / DK) + 1.1920929e-07f);

        const size_t base = isQ
            ? (((size_t)b * NH + slot) * SEQ + t) * 32
            : (((size_t)b * NKV + (slot - NH)) * SEQ + t) * 32;

        #pragma unroll
        for (int na = 0; na < 8; na++) {
            const int i = na * 4 + ccl;
            float y0 = acc[na][rr * 2]     * rnorm * w0[na];
            float y1 = acc[na][rr * 2 + 1] * rnorm * w1[na];
            float sv, cv;
            sincosf((float)t * invf[na], &sv, &cv);
            float o0 = y0 * cv - y1 * sv;
            float o1 = y0 * sv + y1 * cv;
            if (isQ) {
                g_qh[base + i] = pack_h2(o0 * qs, o1 * qs);
            } else {
                g_kh[base + i] = pack_h2(o0, o1);
            }
        }
    }
}

// ================= tensor-core causal flash attention =================
// 256 threads (8 warps), warp grid 4(q)x2(kv): warp = 32 q-rows x 64 kv-cols.
// Q/K/V single fp16 (1 QK chain, 1 PV chain). Fixed-base exp2 softmax.
// kv-half partials combined via smem at the end.
__global__ __launch_bounds__(256, 1) void attn_mma() {
    extern __shared__ char sma[];
    const uint32_t sb = smem_to_u32(sma);
    const int tid = threadIdx.x;
    const int wid = tid >> 5, lane = tid & 31;
    const int wq = wid >> 1, wk = wid & 1;
    const int qb = (int)gridDim.x - 1 - (int)blockIdx.x;
    const int h  = blockIdx.y, b = blockIdx.z;
    const int kvh = h / GROUPS;

    auto KH = [&](int s) { return sb + s * 32768u; };
    auto VH = [&](int s) { return sb + s * 32768u + 16384u; };

    const char* qhB = (const char*)g_qh + (((size_t)b * NH + h) * SEQ + (size_t)qb * 128) * 128;
    const char* khB = (const char*)g_kh + ((size_t)b * NKV + kvh) * SEQ * 128;
    const char* vhB = (const char*)g_vh + ((size_t)b * NKV + kvh) * SEQ * 128;

    // ---- stage Q (16KB, single plane), load fragments for 32 rows ----
    {
        #pragma unroll
        for (int i = 0; i < 4; i++) {
            int idx = tid + i * 256;
            int r = idx >> 3, c = idx & 7;
            uint32_t soff = (uint32_t)(r * 128 + ((c ^ (r & 7)) << 4));
            cp16(sb + soff, qhB + (size_t)r * 128 + c * 16);
        }
        CP_COMMIT(); CP_WAIT(0);
        __syncthreads();
    }
    const int lrow = lane & 15, khalf = lane >> 4;
    uint32_t qh[2][4][4];
    #pragma unroll
    for (int rb = 0; rb < 2; rb++) {
        const int r = wq * 32 + rb * 16 + lrow;
        #pragma unroll
        for (int ks = 0; ks < 4; ks++) {
            const int c = ks * 2 + khalf;
            uint32_t off = (uint32_t)(r * 128 + ((c ^ (r & 7)) << 4));
            ldsm4(qh[rb][ks], sb + off);
        }
    }
    __syncthreads();

    auto load_kv = [&](int s, int kb) {
        #pragma unroll
        for (int i = 0; i < 4; i++) {
            int idx = tid + i * 256;
            int r = idx >> 3, c = idx & 7;
            uint32_t soff = (uint32_t)(r * 128 + ((c ^ (r & 7)) << 4));
            size_t gb = ((size_t)kb * 128 + r) * 128 + c * 16;
            cp16(KH(s) + soff, khB + gb);
            cp16(VH(s) + soff, vhB + gb);
        }
    };

    const int nkb = qb + 1;
    float oa[2][8][4];
    #pragma unroll
    for (int rb = 0; rb < 2; rb++)
        #pragma unroll
        for (int j = 0; j < 8; j++)
            #pragma unroll
            for (int e = 0; e < 4; e++) oa[rb][j][e] = 0.0f;
    float lsum[2][2] = {{0.0f, 0.0f}, {0.0f, 0.0f}};

    const int vrow_base = ((lane >> 3) & 1) * 8 + (lane & 7);
    const int vkh = lane >> 4;

    load_kv(0, 0);
    CP_COMMIT();

    for (int kb = 0; kb < nkb; kb++) {
        CP_WAIT(0);
        __syncthreads();
        if (kb + 1 < nkb) { load_kv((kb + 1) & 1, kb + 1); CP_COMMIT(); }

        const int s = kb & 1;
        const uint32_t kH = KH(s), vH = VH(s);

        // ---- S = Q K^T (single chain), K ldsm shared across 2 row-blocks ----
        float sc[2][8][4];
        #pragma unroll
        for (int rb = 0; rb < 2; rb++)
            #pragma unroll
            for (int j = 0; j < 8; j++)
                #pragma unroll
                for (int e = 0; e < 4; e++) sc[rb][j][e] = 0.0f;

        #pragma unroll
        for (int ks = 0; ks < 4; ks++) {
            const int c = ks * 2 + khalf;
            #pragma unroll
            for (int nb = 0; nb < 4; nb++) {
                int r = wk * 64 + nb * 16 + lrow;
                uint32_t off = (uint32_t)(r * 128 + ((c ^ (r & 7)) << 4));
                uint32_t kh[4];
                ldsm4(kh, kH + off);
                #pragma unroll
                for (int rb = 0; rb < 2; rb++) {
                    mma16816h(sc[rb][2 * nb],     qh[rb][ks], kh[0], kh[2]);
                    mma16816h(sc[rb][2 * nb + 1], qh[rb][ks], kh[1], kh[3]);
                }
            }
        }

        // ---- causal mask (diagonal tile only) ----
        if (kb == qb) {
            #pragma unroll
            for (int rb = 0; rb < 2; rb++) {
                const int g0 = qb * 128 + wq * 32 + rb * 16 + (lane >> 2);
                const int g1 = g0 + 8;
                #pragma unroll
                for (int j = 0; j < 8; j++) {
                    const int c0 = kb * 128 + wk * 64 + 8 * j + (lane & 3) * 2;
                    const int c1 = c0 + 1;
                    if (c0 > g0) sc[rb][j][0] = -INFINITY;
                    if (c1 > g0) sc[rb][j][1] = -INFINITY;
                    if (c0 > g1) sc[rb][j][2] = -INFINITY;
                    if (c1 > g1) sc[rb][j][3] = -INFINITY;
                }
            }
        }

        // ---- fixed-base softmax + PV (per row-block) ----
        #pragma unroll
        for (int rb = 0; rb < 2; rb++) {
            #pragma unroll
            for (int j = 0; j < 8; j++) {
                sc[rb][j][0] = ex2(sc[rb][j][0]);
                sc[rb][j][1] = ex2(sc[rb][j][1]);
                sc[rb][j][2] = ex2(sc[rb][j][2]);
                sc[rb][j][3] = ex2(sc[rb][j][3]);
                lsum[rb][0] += sc[rb][j][0] + sc[rb][j][1];
                lsum[rb][1] += sc[rb][j][2] + sc[rb][j][3];
            }
        }

        uint32_t pa[2][4][4];
        #pragma unroll
        for (int rb = 0; rb < 2; rb++)
            #pragma unroll
            for (int kk = 0; kk < 4; kk++) {
                pa[rb][kk][0] = pack_h2(sc[rb][2 * kk][0],     sc[rb][2 * kk][1]);
                pa[rb][kk][1] = pack_h2(sc[rb][2 * kk][2],     sc[rb][2 * kk][3]);
                pa[rb][kk][2] = pack_h2(sc[rb][2 * kk + 1][0], sc[rb][2 * kk + 1][1]);
                pa[rb][kk][3] = pack_h2(sc[rb][2 * kk + 1][2], sc[rb][2 * kk + 1][3]);
            }

        #pragma unroll
        for (int kk = 0; kk < 4; kk++) {
            const int vr = wk * 64 + kk * 16 + vrow_base;
            #pragma unroll
            for (int ng = 0; ng < 4; ng++) {
                const int vc = ng * 2 + vkh;
                uint32_t off = (uint32_t)(vr * 128 + ((vc ^ (vr & 7)) << 4));
                uint32_t vh[4];
                ldsm4t(vh, vH + off);
                #pragma unroll
                for (int rb = 0; rb < 2; rb++) {
                    mma16816h(oa[rb][2 * ng],     pa[rb][kk], vh[0], vh[1]);
                    mma16816h(oa[rb][2 * ng + 1], pa[rb][kk], vh[2], vh[3]);
                }
            }
        }
    }

    // ---- quad-reduce l, combine kv-half partials via smem ----
    #pragma unroll
    for (int rb = 0; rb < 2; rb++) {
        lsum[rb][0] += __shfl_xor_sync(0xffffffffu, lsum[rb][0], 1);
        lsum[rb][0] += __shfl_xor_sync(0xffffffffu, lsum[rb][0], 2);
        lsum[rb][1] += __shfl_xor_sync(0xffffffffu, lsum[rb][1], 1);
        lsum[rb][1] += __shfl_xor_sync(0xffffffffu, lsum[rb][1], 2);
    }

    float* xch = (float*)sma;                 // 4 wq x 32 lanes x 68 floats = 34.8KB
    __syncthreads();
    if (wk == 1) {
        float* dst = xch + (wq * 32 + lane) * 68;
        #pragma unroll
        for (int rb = 0; rb < 2; rb++)
            #pragma unroll
            for (int j = 0; j < 8; j++) {
                dst[rb * 32 + j * 4 + 0] = oa[rb][j][0];
                dst[rb * 32 + j * 4 + 1] = oa[rb][j][1];
                dst[rb * 32 + j * 4 + 2] = oa[rb][j][2];
                dst[rb * 32 + j * 4 + 3] = oa[rb][j][3];
            }
        dst[64] = lsum[0][0]; dst[65] = lsum[0][1];
        dst[66] = lsum[1][0]; dst[67] = lsum[1][1];
    }
    __syncthreads();
    if (wk == 1) return;

    {
        const float* src = xch + (wq * 32 + lane) * 68;
        #pragma unroll
        for (int rb = 0; rb < 2; rb++)
            #pragma unroll
            for (int j = 0; j < 8; j++) {
                oa[rb][j][0] += src[rb * 32 + j * 4 + 0];
                oa[rb][j][1] += src[rb * 32 + j * 4 + 1];
                oa[rb][j][2] += src[rb * 32 + j * 4 + 2];
                oa[rb][j][3] += src[rb * 32 + j * 4 + 3];
            }
        lsum[0][0] += src[64]; lsum[0][1] += src[65];
        lsum[1][0] += src[66]; lsum[1][1] += src[67];
    }

    #pragma unroll
    for (int rb = 0; rb < 2; rb++) {
        const float inv0 = 1.0f / lsum[rb][0], inv1 = 1.0f / lsum[rb][1];
        const int t0 = qb * 128 + wq * 32 + rb * 16 + (lane >> 2);
        const size_t row0 = (size_t)b * SEQ + t0;
        const size_t row1 = row0 + 8;
        #pragma unroll
        for (int j = 0; j < 8; j++) {
            const int cidx = h * 32 + j * 4 + (lane & 3);
            uint32_t hi, lo;
            splitH2(make_float2(oa[rb][j][0] * inv0, oa[rb][j][1] * inv0), hi, lo);
            g_ahi[row0 * 512 + cidx] = hi;
            g_alo[row0 * 512 + cidx] = lo;
            splitH2(make_float2(oa[rb][j][2] * inv1, oa[rb][j][3] * inv1), hi, lo);
            g_ahi[row1 * 512 + cidx] = hi;
            g_alo[row1 * 512 + cidx] = lo;
        }
    }
}

// ================= launch =================
extern "C" void kernel_launch(void* const* d_in, const int* in_sizes, int n_in,
                              void* d_out, int out_size) {
    const float* x    = (const float*)d_in[0];
    const float* qkvo = (const float*)d_in[1];
    const float* qw   = (const float*)d_in[2];
    const float* kw   = (const float*)d_in[3];
    float* out = (float*)d_out;

    void *p_xhi, *p_xlo, *p_wh, *p_ahi, *p_alo;
    cudaGetSymbolAddress(&p_xhi, g_xhi); cudaGetSymbolAddress(&p_xlo, g_xlo);
    cudaGetSymbolAddress(&p_wh, g_wh);
    cudaGetSymbolAddress(&p_ahi, g_ahi); cudaGetSymbolAddress(&p_alo, g_alo);

    const int GEMM_SMEM = 4 * 49152;   // 192 KB
    const int ATTN_SMEM = 2 * 32768;   // 64 KB
    cudaFuncSetAttribute(gemm_f16x2<true>,  cudaFuncAttributeMaxDynamicSharedMemorySize, GEMM_SMEM);
    cudaFuncSetAttribute(gemm_f16x2<false>, cudaFuncAttributeMaxDynamicSharedMemorySize, GEMM_SMEM);
    cudaFuncSetAttribute(attn_mma, cudaFuncAttributeMaxDynamicSharedMemorySize, ATTN_SMEM);

    // 0) split x (hi/lo) and pack weights (single fp16)
    {
        int np = ROWS * GK / 2;
        split_f16<<<np / 256, 256>>>(x, (uint32_t*)p_xhi, (uint32_t*)p_xlo, np);
        int nw = 2560 * GK / 2;
        pack_f16<<<nw / 256, 256>>>(qkvo, (uint32_t*)p_wh, nw);
    }

    // 1) QKV projection + fused RMSNorm/RoPE -> Q/K/V fp16 planes
    gemm_f16x2<true><<<dim3(QKVN / 128, ROWS / 128), 512, GEMM_SMEM>>>(
        (const __half*)p_xhi, (const __half*)p_xlo,
        (const __half*)p_wh, nullptr, QKVN, qw, kw);

    // 2) tensor-core causal flash attention -> g_ahi/g_alo
    attn_mma<<<dim3(SEQ / 128, NH, BATCH), 256, ATTN_SMEM>>>();

    // 3) O projection
    gemm_f16x2<false><<<dim3(DM / 128, ROWS / 128), 512, GEMM_SMEM>>>(
        (const __half*)p_ahi, (const __half*)p_alo,
        (const __half*)p_wh + (size_t)QKVN * GK, out, DM, nullptr, nullptr);
}